// round 1
// baseline (speedup 1.0000x reference)
#include <cuda_runtime.h>
#include <cuda_bf16.h>
#include <math.h>

// Problem constants
#define BATCH 4
#define SEQ   2048
#define DMODEL 512
#define NHEADS 4
#define HDIM  128
#define DFF   2048
#define MROWS (BATCH*SEQ)   // 8192

// ---------------------------------------------------------------------------
// Static scratch (no allocation allowed)
// ---------------------------------------------------------------------------
__device__ float g_ln1 [MROWS * DMODEL];
__device__ float g_qkv [MROWS * 3 * DMODEL];
__device__ float g_attn[MROWS * DMODEL];
__device__ float g_x1  [MROWS * DMODEL];
__device__ float g_ln2 [MROWS * DMODEL];
__device__ float g_ff1 [MROWS * DFF];

// ---------------------------------------------------------------------------
// LayerNorm: one warp per row (D=512), 8 warps per block
// ---------------------------------------------------------------------------
__global__ void ln_kernel(const float* __restrict__ x,
                          const float* __restrict__ g,
                          const float* __restrict__ b,
                          float* __restrict__ out, int rows)
{
    int row  = blockIdx.x * 8 + threadIdx.y;
    int lane = threadIdx.x;
    if (row >= rows) return;

    const float4* xr = (const float4*)(x + (size_t)row * DMODEL);
    float4 v[4];
    float s = 0.f, s2 = 0.f;
    #pragma unroll
    for (int i = 0; i < 4; i++) {
        v[i] = xr[lane + i * 32];
        s  += v[i].x + v[i].y + v[i].z + v[i].w;
        s2 += v[i].x*v[i].x + v[i].y*v[i].y + v[i].z*v[i].z + v[i].w*v[i].w;
    }
    #pragma unroll
    for (int o = 16; o > 0; o >>= 1) {
        s  += __shfl_xor_sync(0xffffffffu, s,  o);
        s2 += __shfl_xor_sync(0xffffffffu, s2, o);
    }
    float mu  = s * (1.f / DMODEL);
    float var = s2 * (1.f / DMODEL) - mu * mu;
    float inv = rsqrtf(var + 1e-5f);

    float4* orow = (float4*)(out + (size_t)row * DMODEL);
    const float4* g4 = (const float4*)g;
    const float4* b4 = (const float4*)b;
    #pragma unroll
    for (int i = 0; i < 4; i++) {
        float4 gg = g4[lane + i * 32];
        float4 bb = b4[lane + i * 32];
        float4 r;
        r.x = (v[i].x - mu) * inv * gg.x + bb.x;
        r.y = (v[i].y - mu) * inv * gg.y + bb.y;
        r.z = (v[i].z - mu) * inv * gg.z + bb.z;
        r.w = (v[i].w - mu) * inv * gg.w + bb.w;
        orow[lane + i * 32] = r;
    }
}

// ---------------------------------------------------------------------------
// Tiled SGEMM: C[M,N] = A[M,K] @ B[K,N]  (+epilogue)
// BM=BN=128, BK=16, 256 threads, 8x8 per thread.
// EPI: 0 = none, 1 = exact GELU, 2 = add residual
// All dims assumed multiples of tile sizes (true for this problem).
// ---------------------------------------------------------------------------
template <int EPI>
__global__ void __launch_bounds__(256)
gemm_kernel(const float* __restrict__ A, const float* __restrict__ Bm,
            const float* __restrict__ res, float* __restrict__ C,
            int M, int N, int K)
{
    __shared__ float As[16][132];
    __shared__ float Bs[16][128];

    const int tid = threadIdx.x;
    const int tx = tid & 15;        // 0..15  -> 8 cols each
    const int ty = tid >> 4;        // 0..15  -> 8 rows each
    const int bx = blockIdx.x;      // N tile
    const int by = blockIdx.y;      // M tile

    const float* Ab = A + (size_t)(by * 128) * K;
    const float* Bb = Bm + (size_t)(bx * 128);

    float acc[8][8];
    #pragma unroll
    for (int i = 0; i < 8; i++)
        #pragma unroll
        for (int j = 0; j < 8; j++) acc[i][j] = 0.f;

    for (int k0 = 0; k0 < K; k0 += 16) {
        // Load A tile [128,16] transposed -> As[k][m]
        #pragma unroll
        for (int t = 0; t < 2; t++) {
            int id = tid + t * 256;           // 0..511
            int r  = id >> 2;                 // 0..127
            int c4 = id & 3;                  // 0..3 (float4 within 16)
            float4 a = *(const float4*)(Ab + (size_t)r * K + k0 + c4 * 4);
            As[c4*4+0][r] = a.x;
            As[c4*4+1][r] = a.y;
            As[c4*4+2][r] = a.z;
            As[c4*4+3][r] = a.w;
        }
        // Load B tile [16,128]
        #pragma unroll
        for (int t = 0; t < 2; t++) {
            int id = tid + t * 256;           // 0..511
            int r  = id >> 5;                 // 0..15
            int c4 = id & 31;                 // 0..31
            *(float4*)(&Bs[r][c4 * 4]) =
                *(const float4*)(Bb + (size_t)(k0 + r) * N + c4 * 4);
        }
        __syncthreads();

        #pragma unroll
        for (int kk = 0; kk < 16; kk++) {
            float a[8], b[8];
            #pragma unroll
            for (int i = 0; i < 8; i++) a[i] = As[kk][ty * 8 + i];
            #pragma unroll
            for (int j = 0; j < 8; j++) b[j] = Bs[kk][tx * 8 + j];
            #pragma unroll
            for (int i = 0; i < 8; i++)
                #pragma unroll
                for (int j = 0; j < 8; j++)
                    acc[i][j] += a[i] * b[j];
        }
        __syncthreads();
    }

    const int row0 = by * 128 + ty * 8;
    const int col0 = bx * 128 + tx * 8;
    #pragma unroll
    for (int i = 0; i < 8; i++) {
        size_t rowoff = (size_t)(row0 + i) * N + col0;
        #pragma unroll
        for (int j4 = 0; j4 < 2; j4++) {
            float4 v;
            v.x = acc[i][j4*4+0];
            v.y = acc[i][j4*4+1];
            v.z = acc[i][j4*4+2];
            v.w = acc[i][j4*4+3];
            if (EPI == 1) {
                v.x = 0.5f * v.x * (1.f + erff(v.x * 0.70710678118654752f));
                v.y = 0.5f * v.y * (1.f + erff(v.y * 0.70710678118654752f));
                v.z = 0.5f * v.z * (1.f + erff(v.z * 0.70710678118654752f));
                v.w = 0.5f * v.w * (1.f + erff(v.w * 0.70710678118654752f));
            }
            if (EPI == 2) {
                float4 r = *(const float4*)(res + rowoff + j4 * 4);
                v.x += r.x; v.y += r.y; v.z += r.z; v.w += r.w;
            }
            *(float4*)(C + rowoff + j4 * 4) = v;
        }
    }
}

// ---------------------------------------------------------------------------
// Flash attention, fp32, causal.
// Block: 128 threads handles 32 q-rows for one (b,h).
// Each q-row owned by 4 threads (p=0..3), each covering 32 of 128 head dims.
// K/V tiles of 32 keys live in smem; online softmax; causal tile skipping.
// ---------------------------------------------------------------------------
__global__ void __launch_bounds__(128)
attn_kernel(const float* __restrict__ qkv, float* __restrict__ out)
{
    const int qt = blockIdx.x;        // q tile (32 rows)
    const int h  = blockIdx.y;
    const int b  = blockIdx.z;
    const int tid = threadIdx.x;
    const int r = tid >> 2;           // local q row 0..31
    const int p = tid & 3;            // dim slice 0..3
    const int qi = qt * 32 + r;       // global q index within sequence

    const float* base = qkv + (size_t)b * SEQ * (3 * DMODEL);
    const float scale = 0.08838834764831845f;   // 1/sqrt(128)

    // q slice: 32 floats (pre-scaled)
    float4 q[8];
    {
        const float4* qrow = (const float4*)(base + (size_t)qi * (3*DMODEL) + h * HDIM + p * 32);
        #pragma unroll
        for (int i = 0; i < 8; i++) {
            float4 t = qrow[i];
            t.x *= scale; t.y *= scale; t.z *= scale; t.w *= scale;
            q[i] = t;
        }
    }

    float o[32];
    #pragma unroll
    for (int c = 0; c < 32; c++) o[c] = 0.f;
    float m = -1e30f, l = 0.f;

    __shared__ float4 ks[32][33];
    __shared__ float4 vs[32][33];

    const int ntiles = qt + 1;        // causal: skip tiles past the diagonal
    for (int kt = 0; kt < ntiles; kt++) {
        // cooperative K/V tile load (32 rows x 128 floats each)
        #pragma unroll
        for (int i = 0; i < 8; i++) {
            int idx = tid + i * 128;         // 0..1023
            int kr = idx >> 5;
            int kc = idx & 31;
            const float* krow = base + (size_t)(kt*32 + kr) * (3*DMODEL) + h * HDIM + kc * 4;
            ks[kr][kc] = *(const float4*)(krow + DMODEL);       // K at offset 512
            vs[kr][kc] = *(const float4*)(krow + 2 * DMODEL);   // V at offset 1024
        }
        __syncthreads();

        float pbuf[32];
        float mt = m;
        const bool full = (kt < qt);   // fully unmasked tile
        #pragma unroll
        for (int j = 0; j < 32; j++) {
            float s = 0.f;
            #pragma unroll
            for (int i = 0; i < 8; i++) {
                int ii = (i + p * 2) & 7;          // bank-rotation
                float4 kk = ks[j][p * 8 + ii];
                s += q[ii].x * kk.x + q[ii].y * kk.y + q[ii].z * kk.z + q[ii].w * kk.w;
            }
            s += __shfl_xor_sync(0xffffffffu, s, 1);
            s += __shfl_xor_sync(0xffffffffu, s, 2);
            if (!full && (kt * 32 + j) > qi) s = -1e30f;
            pbuf[j] = s;
            mt = fmaxf(mt, s);
        }

        float corr = __expf(m - mt);
        m = mt;
        l *= corr;
        #pragma unroll
        for (int c = 0; c < 32; c++) o[c] *= corr;

        #pragma unroll
        for (int j = 0; j < 32; j++) {
            float pj = __expf(pbuf[j] - m);
            l += pj;
            #pragma unroll
            for (int i = 0; i < 8; i++) {
                int ii = (i + p * 2) & 7;
                float4 vv = vs[j][p * 8 + ii];
                o[ii*4+0] += pj * vv.x;
                o[ii*4+1] += pj * vv.y;
                o[ii*4+2] += pj * vv.z;
                o[ii*4+3] += pj * vv.w;
            }
        }
        __syncthreads();
    }

    float inv = 1.f / l;
    float4* orow = (float4*)(out + ((size_t)b * SEQ + qi) * DMODEL + h * HDIM + p * 32);
    #pragma unroll
    for (int i = 0; i < 8; i++) {
        float4 t;
        t.x = o[i*4+0] * inv;
        t.y = o[i*4+1] * inv;
        t.z = o[i*4+2] * inv;
        t.w = o[i*4+3] * inv;
        orow[i] = t;
    }
}

// ---------------------------------------------------------------------------
// Launch
// ---------------------------------------------------------------------------
extern "C" void kernel_launch(void* const* d_in, const int* in_sizes, int n_in,
                              void* d_out, int out_size)
{
    const float* x      = (const float*)d_in[0];
    const float* ln1_g  = (const float*)d_in[1];
    const float* ln1_b  = (const float*)d_in[2];
    const float* w_qkv  = (const float*)d_in[3];
    const float* w_proj = (const float*)d_in[4];
    const float* ln2_g  = (const float*)d_in[5];
    const float* ln2_b  = (const float*)d_in[6];
    const float* w_ff1  = (const float*)d_in[7];
    const float* w_ff2  = (const float*)d_in[8];
    float* out = (float*)d_out;

    float *ln1, *qkv, *attn, *x1, *ln2, *ff1;
    cudaGetSymbolAddress((void**)&ln1,  g_ln1);
    cudaGetSymbolAddress((void**)&qkv,  g_qkv);
    cudaGetSymbolAddress((void**)&attn, g_attn);
    cudaGetSymbolAddress((void**)&x1,   g_x1);
    cudaGetSymbolAddress((void**)&ln2,  g_ln2);
    cudaGetSymbolAddress((void**)&ff1,  g_ff1);

    dim3 lnBlk(32, 8);

    // 1. ln1 = LN(x)
    ln_kernel<<<MROWS / 8, lnBlk>>>(x, ln1_g, ln1_b, ln1, MROWS);
    // 2. qkv = ln1 @ w_qkv           [8192,1536]
    gemm_kernel<0><<<dim3(1536/128, MROWS/128), 256>>>(ln1, w_qkv, nullptr, qkv,
                                                       MROWS, 3*DMODEL, DMODEL);
    // 3. attn = causal_flash(qkv)    [8192,512]
    attn_kernel<<<dim3(SEQ/32, NHEADS, BATCH), 128>>>(qkv, attn);
    // 4. x1 = x + attn @ w_proj
    gemm_kernel<2><<<dim3(512/128, MROWS/128), 256>>>(attn, w_proj, x, x1,
                                                      MROWS, DMODEL, DMODEL);
    // 5. ln2 = LN(x1)
    ln_kernel<<<MROWS / 8, lnBlk>>>(x1, ln2_g, ln2_b, ln2, MROWS);
    // 6. ff1 = gelu(ln2 @ w_ff1)     [8192,2048]
    gemm_kernel<1><<<dim3(DFF/128, MROWS/128), 256>>>(ln2, w_ff1, nullptr, ff1,
                                                      MROWS, DFF, DMODEL);
    // 7. out = x1 + ff1 @ w_ff2
    gemm_kernel<2><<<dim3(512/128, MROWS/128), 256>>>(ff1, w_ff2, x1, out,
                                                      MROWS, DMODEL, DFF);
}

// round 2
// speedup vs baseline: 5.9394x; 5.9394x over previous
#include <cuda_runtime.h>
#include <cuda_bf16.h>
#include <math.h>

// Problem constants
#define BATCH 4
#define SEQ   2048
#define DMODEL 512
#define NHEADS 4
#define HDIM  128
#define DFF   2048
#define MROWS (BATCH*SEQ)   // 8192

// ---------------------------------------------------------------------------
// Static scratch (no allocation allowed)
// ---------------------------------------------------------------------------
__device__ float g_ln1 [MROWS * DMODEL];
__device__ float g_qkv [MROWS * 3 * DMODEL];
__device__ float g_attn[MROWS * DMODEL];
__device__ float g_x1  [MROWS * DMODEL];
__device__ float g_ln2 [MROWS * DMODEL];
__device__ float g_ff1 [MROWS * DFF];

// ---------------------------------------------------------------------------
// LayerNorm: one warp per row (D=512), 8 warps per block
// ---------------------------------------------------------------------------
__global__ void ln_kernel(const float* __restrict__ x,
                          const float* __restrict__ g,
                          const float* __restrict__ b,
                          float* __restrict__ out, int rows)
{
    int row  = blockIdx.x * 8 + threadIdx.y;
    int lane = threadIdx.x;
    if (row >= rows) return;

    const float4* xr = (const float4*)(x + (size_t)row * DMODEL);
    float4 v[4];
    float s = 0.f, s2 = 0.f;
    #pragma unroll
    for (int i = 0; i < 4; i++) {
        v[i] = xr[lane + i * 32];
        s  += v[i].x + v[i].y + v[i].z + v[i].w;
        s2 += v[i].x*v[i].x + v[i].y*v[i].y + v[i].z*v[i].z + v[i].w*v[i].w;
    }
    #pragma unroll
    for (int o = 16; o > 0; o >>= 1) {
        s  += __shfl_xor_sync(0xffffffffu, s,  o);
        s2 += __shfl_xor_sync(0xffffffffu, s2, o);
    }
    float mu  = s * (1.f / DMODEL);
    float var = s2 * (1.f / DMODEL) - mu * mu;
    float inv = rsqrtf(var + 1e-5f);

    float4* orow = (float4*)(out + (size_t)row * DMODEL);
    const float4* g4 = (const float4*)g;
    const float4* b4 = (const float4*)b;
    #pragma unroll
    for (int i = 0; i < 4; i++) {
        float4 gg = g4[lane + i * 32];
        float4 bb = b4[lane + i * 32];
        float4 r;
        r.x = (v[i].x - mu) * inv * gg.x + bb.x;
        r.y = (v[i].y - mu) * inv * gg.y + bb.y;
        r.z = (v[i].z - mu) * inv * gg.z + bb.z;
        r.w = (v[i].w - mu) * inv * gg.w + bb.w;
        orow[lane + i * 32] = r;
    }
}

// ---------------------------------------------------------------------------
// Tiled SGEMM: C[M,N] = A[M,K] @ B[K,N]  (+epilogue)
// BM=BN=128, BK=16, 256 threads, 8x8 per thread.
// EPI: 0 = none, 1 = exact GELU, 2 = add residual
// ---------------------------------------------------------------------------
template <int EPI>
__global__ void __launch_bounds__(256)
gemm_kernel(const float* __restrict__ A, const float* __restrict__ Bm,
            const float* __restrict__ res, float* __restrict__ C,
            int M, int N, int K)
{
    __shared__ float As[16][132];
    __shared__ float Bs[16][128];

    const int tid = threadIdx.x;
    const int tx = tid & 15;
    const int ty = tid >> 4;
    const int bx = blockIdx.x;
    const int by = blockIdx.y;

    const float* Ab = A + (size_t)(by * 128) * K;
    const float* Bb = Bm + (size_t)(bx * 128);

    float acc[8][8];
    #pragma unroll
    for (int i = 0; i < 8; i++)
        #pragma unroll
        for (int j = 0; j < 8; j++) acc[i][j] = 0.f;

    for (int k0 = 0; k0 < K; k0 += 16) {
        #pragma unroll
        for (int t = 0; t < 2; t++) {
            int id = tid + t * 256;
            int r  = id >> 2;
            int c4 = id & 3;
            float4 a = *(const float4*)(Ab + (size_t)r * K + k0 + c4 * 4);
            As[c4*4+0][r] = a.x;
            As[c4*4+1][r] = a.y;
            As[c4*4+2][r] = a.z;
            As[c4*4+3][r] = a.w;
        }
        #pragma unroll
        for (int t = 0; t < 2; t++) {
            int id = tid + t * 256;
            int r  = id >> 5;
            int c4 = id & 31;
            *(float4*)(&Bs[r][c4 * 4]) =
                *(const float4*)(Bb + (size_t)(k0 + r) * N + c4 * 4);
        }
        __syncthreads();

        #pragma unroll
        for (int kk = 0; kk < 16; kk++) {
            float a[8], b[8];
            #pragma unroll
            for (int i = 0; i < 8; i++) a[i] = As[kk][ty * 8 + i];
            #pragma unroll
            for (int j = 0; j < 8; j++) b[j] = Bs[kk][tx * 8 + j];
            #pragma unroll
            for (int i = 0; i < 8; i++)
                #pragma unroll
                for (int j = 0; j < 8; j++)
                    acc[i][j] += a[i] * b[j];
        }
        __syncthreads();
    }

    const int row0 = by * 128 + ty * 8;
    const int col0 = bx * 128 + tx * 8;
    #pragma unroll
    for (int i = 0; i < 8; i++) {
        size_t rowoff = (size_t)(row0 + i) * N + col0;
        #pragma unroll
        for (int j4 = 0; j4 < 2; j4++) {
            float4 v;
            v.x = acc[i][j4*4+0];
            v.y = acc[i][j4*4+1];
            v.z = acc[i][j4*4+2];
            v.w = acc[i][j4*4+3];
            if (EPI == 1) {
                v.x = 0.5f * v.x * (1.f + erff(v.x * 0.70710678118654752f));
                v.y = 0.5f * v.y * (1.f + erff(v.y * 0.70710678118654752f));
                v.z = 0.5f * v.z * (1.f + erff(v.z * 0.70710678118654752f));
                v.w = 0.5f * v.w * (1.f + erff(v.w * 0.70710678118654752f));
            }
            if (EPI == 2) {
                float4 r = *(const float4*)(res + rowoff + j4 * 4);
                v.x += r.x; v.y += r.y; v.z += r.z; v.w += r.w;
            }
            *(float4*)(C + rowoff + j4 * 4) = v;
        }
    }
}

// ---------------------------------------------------------------------------
// Flash attention v2 (GEMM-structured), fp32, causal.
// Block: 256 threads (16x16) handles BQ=64 q rows for one (b,h).
// K-tiles of BK=64. S = Q@K^T as smem GEMM (4x4/thread), online softmax with
// 16-lane shuffle row reductions, P staged to smem, O += P@V as smem GEMM
// (4 rows x 8 dims per thread).
// Dynamic smem: Qst[128][68] + Kst[128][68] + Vs[64][128] + Ps[64][68]
// ---------------------------------------------------------------------------
#define BQ 64
#define BK 64
#define QK_STRIDE 68
#define ATTN_SMEM ((128*QK_STRIDE + 128*QK_STRIDE + 64*128 + 64*QK_STRIDE) * 4)

__global__ void __launch_bounds__(256)
attn_kernel2(const float* __restrict__ qkv, float* __restrict__ out)
{
    extern __shared__ float sm[];
    float* Qst = sm;                            // [128][68]  d-major
    float* Kst = Qst + 128 * QK_STRIDE;         // [128][68]  d-major
    float* Vs  = Kst + 128 * QK_STRIDE;         // [64][128]  key-major
    float* Ps  = Vs  + 64 * 128;                // [64][68]   row-major

    const int qblk = (SEQ / BQ - 1) - blockIdx.x;   // heavy blocks first
    const int h  = blockIdx.y;
    const int b  = blockIdx.z;
    const int tid = threadIdx.x;
    const int tx = tid & 15;
    const int ty = tid >> 4;

    const float scale = 0.08838834764831845f;   // 1/sqrt(128)
    const size_t rowstride = 3 * DMODEL;        // 1536

    // ---- load Q tile, transposed + scaled: Qst[d][row] ----
    {
        const float* qbase = qkv + ((size_t)b * SEQ + qblk * BQ) * rowstride + h * HDIM;
        #pragma unroll
        for (int t = 0; t < 8; t++) {
            int idx = tid + t * 256;     // 0..2047
            int row = idx >> 5;          // 0..63
            int d4  = idx & 31;          // 0..31
            float4 v = *(const float4*)(qbase + (size_t)row * rowstride + d4 * 4);
            Qst[(d4*4+0)*QK_STRIDE + row] = v.x * scale;
            Qst[(d4*4+1)*QK_STRIDE + row] = v.y * scale;
            Qst[(d4*4+2)*QK_STRIDE + row] = v.z * scale;
            Qst[(d4*4+3)*QK_STRIDE + row] = v.w * scale;
        }
    }

    float o[4][8];
    float m[4], l[4];
    #pragma unroll
    for (int i = 0; i < 4; i++) {
        m[i] = -1e30f; l[i] = 0.f;
        #pragma unroll
        for (int j = 0; j < 8; j++) o[i][j] = 0.f;
    }

    const int ntiles = qblk + 1;
    for (int kt = 0; kt < ntiles; kt++) {
        // ---- load K (transposed) and V tiles ----
        const float* kbase = qkv + ((size_t)b * SEQ + kt * BK) * rowstride + h * HDIM + DMODEL;
        const float* vbase = kbase + DMODEL;
        __syncthreads();   // protect Kst/Vs from previous iteration readers
        #pragma unroll
        for (int t = 0; t < 8; t++) {
            int idx = tid + t * 256;
            int row = idx >> 5;
            int d4  = idx & 31;
            float4 kv = *(const float4*)(kbase + (size_t)row * rowstride + d4 * 4);
            Kst[(d4*4+0)*QK_STRIDE + row] = kv.x;
            Kst[(d4*4+1)*QK_STRIDE + row] = kv.y;
            Kst[(d4*4+2)*QK_STRIDE + row] = kv.z;
            Kst[(d4*4+3)*QK_STRIDE + row] = kv.w;
            float4 vv = *(const float4*)(vbase + (size_t)row * rowstride + d4 * 4);
            *(float4*)(&Vs[row * 128 + d4 * 4]) = vv;
        }
        __syncthreads();

        // ---- S = Q @ K^T  (4x4 per thread) ----
        float s[4][4];
        #pragma unroll
        for (int i = 0; i < 4; i++)
            #pragma unroll
            for (int j = 0; j < 4; j++) s[i][j] = 0.f;

        #pragma unroll 4
        for (int kk = 0; kk < 128; kk++) {
            float4 a = *(const float4*)(&Qst[kk * QK_STRIDE + ty * 4]);
            float4 bq = *(const float4*)(&Kst[kk * QK_STRIDE + tx * 4]);
            float av[4] = {a.x, a.y, a.z, a.w};
            float bv[4] = {bq.x, bq.y, bq.z, bq.w};
            #pragma unroll
            for (int i = 0; i < 4; i++)
                #pragma unroll
                for (int j = 0; j < 4; j++)
                    s[i][j] += av[i] * bv[j];
        }

        // ---- causal mask (diagonal tile only) ----
        if (kt == qblk) {
            #pragma unroll
            for (int i = 0; i < 4; i++)
                #pragma unroll
                for (int j = 0; j < 4; j++)
                    if (tx * 4 + j > ty * 4 + i) s[i][j] = -1e30f;
        }

        // ---- online softmax (row reductions over 16 tx lanes) ----
        #pragma unroll
        for (int i = 0; i < 4; i++) {
            float rm = fmaxf(fmaxf(s[i][0], s[i][1]), fmaxf(s[i][2], s[i][3]));
            #pragma unroll
            for (int off = 8; off > 0; off >>= 1)
                rm = fmaxf(rm, __shfl_xor_sync(0xffffffffu, rm, off));
            float mnew = fmaxf(m[i], rm);
            float rs = 0.f;
            #pragma unroll
            for (int j = 0; j < 4; j++) {
                float p = __expf(s[i][j] - mnew);
                s[i][j] = p;
                rs += p;
            }
            #pragma unroll
            for (int off = 8; off > 0; off >>= 1)
                rs += __shfl_xor_sync(0xffffffffu, rs, off);
            float corr = __expf(m[i] - mnew);
            l[i] = l[i] * corr + rs;
            m[i] = mnew;
            #pragma unroll
            for (int j = 0; j < 8; j++) o[i][j] *= corr;
            *(float4*)(&Ps[(ty * 4 + i) * QK_STRIDE + tx * 4]) =
                make_float4(s[i][0], s[i][1], s[i][2], s[i][3]);
        }
        __syncthreads();

        // ---- O += P @ V  (4 rows x 8 dims per thread) ----
        #pragma unroll 4
        for (int kk = 0; kk < BK; kk++) {
            float a[4];
            #pragma unroll
            for (int i = 0; i < 4; i++) a[i] = Ps[(ty * 4 + i) * QK_STRIDE + kk];
            float4 b0 = *(const float4*)(&Vs[kk * 128 + tx * 8]);
            float4 b1 = *(const float4*)(&Vs[kk * 128 + tx * 8 + 4]);
            #pragma unroll
            for (int i = 0; i < 4; i++) {
                o[i][0] += a[i] * b0.x;
                o[i][1] += a[i] * b0.y;
                o[i][2] += a[i] * b0.z;
                o[i][3] += a[i] * b0.w;
                o[i][4] += a[i] * b1.x;
                o[i][5] += a[i] * b1.y;
                o[i][6] += a[i] * b1.z;
                o[i][7] += a[i] * b1.w;
            }
        }
    }

    // ---- write O ----
    #pragma unroll
    for (int i = 0; i < 4; i++) {
        float inv = 1.f / l[i];
        int row = qblk * BQ + ty * 4 + i;
        float* orow = out + ((size_t)b * SEQ + row) * DMODEL + h * HDIM + tx * 8;
        float4 v0, v1;
        v0.x = o[i][0]*inv; v0.y = o[i][1]*inv; v0.z = o[i][2]*inv; v0.w = o[i][3]*inv;
        v1.x = o[i][4]*inv; v1.y = o[i][5]*inv; v1.z = o[i][6]*inv; v1.w = o[i][7]*inv;
        *(float4*)(orow)     = v0;
        *(float4*)(orow + 4) = v1;
    }
}

// ---------------------------------------------------------------------------
// Launch
// ---------------------------------------------------------------------------
extern "C" void kernel_launch(void* const* d_in, const int* in_sizes, int n_in,
                              void* d_out, int out_size)
{
    const float* x      = (const float*)d_in[0];
    const float* ln1_g  = (const float*)d_in[1];
    const float* ln1_b  = (const float*)d_in[2];
    const float* w_qkv  = (const float*)d_in[3];
    const float* w_proj = (const float*)d_in[4];
    const float* ln2_g  = (const float*)d_in[5];
    const float* ln2_b  = (const float*)d_in[6];
    const float* w_ff1  = (const float*)d_in[7];
    const float* w_ff2  = (const float*)d_in[8];
    float* out = (float*)d_out;

    float *ln1, *qkv, *attn, *x1, *ln2, *ff1;
    cudaGetSymbolAddress((void**)&ln1,  g_ln1);
    cudaGetSymbolAddress((void**)&qkv,  g_qkv);
    cudaGetSymbolAddress((void**)&attn, g_attn);
    cudaGetSymbolAddress((void**)&x1,   g_x1);
    cudaGetSymbolAddress((void**)&ln2,  g_ln2);
    cudaGetSymbolAddress((void**)&ff1,  g_ff1);

    static bool attr_done = false;
    // (idempotent attribute set; safe under graph capture — not a stream op)
    cudaFuncSetAttribute(attn_kernel2,
                         cudaFuncAttributeMaxDynamicSharedMemorySize, ATTN_SMEM);

    dim3 lnBlk(32, 8);

    // 1. ln1 = LN(x)
    ln_kernel<<<MROWS / 8, lnBlk>>>(x, ln1_g, ln1_b, ln1, MROWS);
    // 2. qkv = ln1 @ w_qkv           [8192,1536]
    gemm_kernel<0><<<dim3(1536/128, MROWS/128), 256>>>(ln1, w_qkv, nullptr, qkv,
                                                       MROWS, 3*DMODEL, DMODEL);
    // 3. attn = causal_flash(qkv)    [8192,512]
    attn_kernel2<<<dim3(SEQ/BQ, NHEADS, BATCH), 256, ATTN_SMEM>>>(qkv, attn);
    // 4. x1 = x + attn @ w_proj
    gemm_kernel<2><<<dim3(512/128, MROWS/128), 256>>>(attn, w_proj, x, x1,
                                                      MROWS, DMODEL, DMODEL);
    // 5. ln2 = LN(x1)
    ln_kernel<<<MROWS / 8, lnBlk>>>(x1, ln2_g, ln2_b, ln2, MROWS);
    // 6. ff1 = gelu(ln2 @ w_ff1)     [8192,2048]
    gemm_kernel<1><<<dim3(DFF/128, MROWS/128), 256>>>(ln2, w_ff1, nullptr, ff1,
                                                      MROWS, DFF, DMODEL);
    // 7. out = x1 + ff1 @ w_ff2
    gemm_kernel<2><<<dim3(512/128, MROWS/128), 256>>>(ff1, w_ff2, x1, out,
                                                      MROWS, DMODEL, DFF);
}

// round 3
// speedup vs baseline: 9.4530x; 1.5916x over previous
#include <cuda_runtime.h>
#include <cuda_bf16.h>
#include <math.h>
#include <stdint.h>

// Problem constants
#define BATCH 4
#define SEQ   2048
#define DMODEL 512
#define NHEADS 4
#define HDIM  128
#define DFF   2048
#define MROWS (BATCH*SEQ)   // 8192

// ---------------------------------------------------------------------------
// Static scratch (no allocation allowed)
// ---------------------------------------------------------------------------
__device__ float g_ln1 [MROWS * DMODEL];
__device__ float g_qkv [MROWS * 3 * DMODEL];
__device__ float g_attn[MROWS * DMODEL];
__device__ float g_x1  [MROWS * DMODEL];
__device__ float g_ln2 [MROWS * DMODEL];
__device__ float g_ff1 [MROWS * DFF];

// ---------------------------------------------------------------------------
// LayerNorm: one warp per row (D=512), 8 warps per block
// ---------------------------------------------------------------------------
__global__ void ln_kernel(const float* __restrict__ x,
                          const float* __restrict__ g,
                          const float* __restrict__ b,
                          float* __restrict__ out, int rows)
{
    int row  = blockIdx.x * 8 + threadIdx.y;
    int lane = threadIdx.x;
    if (row >= rows) return;

    const float4* xr = (const float4*)(x + (size_t)row * DMODEL);
    float4 v[4];
    float s = 0.f, s2 = 0.f;
    #pragma unroll
    for (int i = 0; i < 4; i++) {
        v[i] = xr[lane + i * 32];
        s  += v[i].x + v[i].y + v[i].z + v[i].w;
        s2 += v[i].x*v[i].x + v[i].y*v[i].y + v[i].z*v[i].z + v[i].w*v[i].w;
    }
    #pragma unroll
    for (int o = 16; o > 0; o >>= 1) {
        s  += __shfl_xor_sync(0xffffffffu, s,  o);
        s2 += __shfl_xor_sync(0xffffffffu, s2, o);
    }
    float mu  = s * (1.f / DMODEL);
    float var = s2 * (1.f / DMODEL) - mu * mu;
    float inv = rsqrtf(var + 1e-5f);

    float4* orow = (float4*)(out + (size_t)row * DMODEL);
    const float4* g4 = (const float4*)g;
    const float4* b4 = (const float4*)b;
    #pragma unroll
    for (int i = 0; i < 4; i++) {
        float4 gg = g4[lane + i * 32];
        float4 bb = b4[lane + i * 32];
        float4 r;
        r.x = (v[i].x - mu) * inv * gg.x + bb.x;
        r.y = (v[i].y - mu) * inv * gg.y + bb.y;
        r.z = (v[i].z - mu) * inv * gg.z + bb.z;
        r.w = (v[i].w - mu) * inv * gg.w + bb.w;
        orow[lane + i * 32] = r;
    }
}

// ---------------------------------------------------------------------------
// tf32 tensor-core GEMM: C[M,N] = A[M,K] @ B[K,N]  (+epilogue)
// BM=BN=128, BK=32, 256 threads = 8 warps (4m x 2n), warp tile 32x64.
// mma.sync.m16n8k8 tf32, fp32 accumulate. Register-prefetch double buffer.
// EPI: 0 = none, 1 = exact GELU, 2 = add residual
// ---------------------------------------------------------------------------
__device__ __forceinline__ uint32_t f2tf32(float f) {
    uint32_t u;
    asm("cvt.rna.tf32.f32 %0, %1;" : "=r"(u) : "f"(f));
    return u;
}

__device__ __forceinline__ void mma_tf32(float c[4], const uint32_t a[4], const uint32_t b[2]) {
    asm volatile(
        "mma.sync.aligned.m16n8k8.row.col.f32.tf32.tf32.f32 "
        "{%0,%1,%2,%3}, {%4,%5,%6,%7}, {%8,%9}, {%0,%1,%2,%3};"
        : "+f"(c[0]), "+f"(c[1]), "+f"(c[2]), "+f"(c[3])
        : "r"(a[0]), "r"(a[1]), "r"(a[2]), "r"(a[3]), "r"(b[0]), "r"(b[1]));
}

#define AS_STRIDE 36
#define BS_STRIDE 136

template <int EPI>
__global__ void __launch_bounds__(256)
gemm_tc(const float* __restrict__ A, const float* __restrict__ Bm,
        const float* __restrict__ res, float* __restrict__ C,
        int M, int N, int K)
{
    __shared__ float As[128 * AS_STRIDE];   // [m][k]  (k-tile of 32)
    __shared__ float Bs[32 * BS_STRIDE];    // [k][n]

    const int tid  = threadIdx.x;
    const int lane = tid & 31;
    const int wid  = tid >> 5;
    const int wm   = wid >> 1;     // 0..3  (m)
    const int wn   = wid & 1;      // 0..1  (n)
    const int g    = lane >> 2;    // group 0..7
    const int tig  = lane & 3;     // thread-in-group

    const int bx = blockIdx.x;
    const int by = blockIdx.y;

    const float* Ab = A + (size_t)(by * 128) * K;
    const float* Bb = Bm + (size_t)(bx * 128);

    float acc[2][8][4];
    #pragma unroll
    for (int mf = 0; mf < 2; mf++)
        #pragma unroll
        for (int nf = 0; nf < 8; nf++)
            #pragma unroll
            for (int r = 0; r < 4; r++) acc[mf][nf][r] = 0.f;

    // Per-thread load coordinates (4 float4 each for A and B per k-tile)
    int arow[4], ac4[4], brow[4], bc4;
    #pragma unroll
    for (int i = 0; i < 4; i++) {
        int idx = tid + i * 256;
        arow[i] = idx >> 3;   // 0..127
        ac4[i]  = idx & 7;    // 0..7
        brow[i] = idx >> 5;   // 0..31
    }
    bc4 = tid & 31;           // 0..31

    float4 pa[4], pb[4];

    // prologue: load k-tile 0
    #pragma unroll
    for (int i = 0; i < 4; i++) {
        pa[i] = *(const float4*)(Ab + (size_t)arow[i] * K + ac4[i] * 4);
        pb[i] = *(const float4*)(Bb + (size_t)brow[i] * N + bc4 * 4);
    }
    #pragma unroll
    for (int i = 0; i < 4; i++) {
        uint4 ta, tb;
        ta.x = f2tf32(pa[i].x); ta.y = f2tf32(pa[i].y);
        ta.z = f2tf32(pa[i].z); ta.w = f2tf32(pa[i].w);
        tb.x = f2tf32(pb[i].x); tb.y = f2tf32(pb[i].y);
        tb.z = f2tf32(pb[i].z); tb.w = f2tf32(pb[i].w);
        *(uint4*)(&As[arow[i] * AS_STRIDE + ac4[i] * 4]) = ta;
        *(uint4*)(&Bs[brow[i] * BS_STRIDE + bc4 * 4])    = tb;
    }
    __syncthreads();

    const int ntiles = K >> 5;
    for (int kt = 0; kt < ntiles; kt++) {
        // prefetch next k-tile into registers
        if (kt + 1 < ntiles) {
            int k0 = (kt + 1) * 32;
            #pragma unroll
            for (int i = 0; i < 4; i++) {
                pa[i] = *(const float4*)(Ab + (size_t)arow[i] * K + k0 + ac4[i] * 4);
                pb[i] = *(const float4*)(Bb + (size_t)(k0 + brow[i]) * N + bc4 * 4);
            }
        }

        // compute 4 k-steps of 8 from smem
        #pragma unroll
        for (int ks = 0; ks < 4; ks++) {
            uint32_t af[2][4], bf[8][2];
            const int kc = ks * 8 + tig;
            #pragma unroll
            for (int mf = 0; mf < 2; mf++) {
                int r = wm * 32 + mf * 16 + g;
                af[mf][0] = __float_as_uint(As[r       * AS_STRIDE + kc]);
                af[mf][1] = __float_as_uint(As[(r + 8) * AS_STRIDE + kc]);
                af[mf][2] = __float_as_uint(As[r       * AS_STRIDE + kc + 4]);
                af[mf][3] = __float_as_uint(As[(r + 8) * AS_STRIDE + kc + 4]);
            }
            #pragma unroll
            for (int nf = 0; nf < 8; nf++) {
                int nc = wn * 64 + nf * 8 + g;
                bf[nf][0] = __float_as_uint(Bs[(ks * 8 + tig)     * BS_STRIDE + nc]);
                bf[nf][1] = __float_as_uint(Bs[(ks * 8 + tig + 4) * BS_STRIDE + nc]);
            }
            #pragma unroll
            for (int mf = 0; mf < 2; mf++)
                #pragma unroll
                for (int nf = 0; nf < 8; nf++)
                    mma_tf32(acc[mf][nf], af[mf], bf[nf]);
        }

        if (kt + 1 < ntiles) {
            __syncthreads();
            #pragma unroll
            for (int i = 0; i < 4; i++) {
                uint4 ta, tb;
                ta.x = f2tf32(pa[i].x); ta.y = f2tf32(pa[i].y);
                ta.z = f2tf32(pa[i].z); ta.w = f2tf32(pa[i].w);
                tb.x = f2tf32(pb[i].x); tb.y = f2tf32(pb[i].y);
                tb.z = f2tf32(pb[i].z); tb.w = f2tf32(pb[i].w);
                *(uint4*)(&As[arow[i] * AS_STRIDE + ac4[i] * 4]) = ta;
                *(uint4*)(&Bs[brow[i] * BS_STRIDE + bc4 * 4])    = tb;
            }
            __syncthreads();
        }
    }

    // epilogue
    #pragma unroll
    for (int mf = 0; mf < 2; mf++) {
        #pragma unroll
        for (int i2 = 0; i2 < 2; i2++) {
            int row = by * 128 + wm * 32 + mf * 16 + g + i2 * 8;
            #pragma unroll
            for (int nf = 0; nf < 8; nf++) {
                int col = bx * 128 + wn * 64 + nf * 8 + tig * 2;
                float v0 = acc[mf][nf][i2 * 2 + 0];
                float v1 = acc[mf][nf][i2 * 2 + 1];
                size_t off = (size_t)row * N + col;
                if (EPI == 1) {
                    v0 = 0.5f * v0 * (1.f + erff(v0 * 0.70710678118654752f));
                    v1 = 0.5f * v1 * (1.f + erff(v1 * 0.70710678118654752f));
                }
                if (EPI == 2) {
                    float2 r = *(const float2*)(res + off);
                    v0 += r.x; v1 += r.y;
                }
                *(float2*)(C + off) = make_float2(v0, v1);
            }
        }
    }
}

// ---------------------------------------------------------------------------
// Flash attention v2 (GEMM-structured), fp32, causal. (unchanged from R1)
// ---------------------------------------------------------------------------
#define BQ 64
#define BK 64
#define QK_STRIDE 68
#define ATTN_SMEM ((128*QK_STRIDE + 128*QK_STRIDE + 64*128 + 64*QK_STRIDE) * 4)

__global__ void __launch_bounds__(256)
attn_kernel2(const float* __restrict__ qkv, float* __restrict__ out)
{
    extern __shared__ float sm[];
    float* Qst = sm;                            // [128][68]  d-major
    float* Kst = Qst + 128 * QK_STRIDE;         // [128][68]  d-major
    float* Vs  = Kst + 128 * QK_STRIDE;         // [64][128]  key-major
    float* Ps  = Vs  + 64 * 128;                // [64][68]   row-major

    const int qblk = (SEQ / BQ - 1) - blockIdx.x;   // heavy blocks first
    const int h  = blockIdx.y;
    const int b  = blockIdx.z;
    const int tid = threadIdx.x;
    const int tx = tid & 15;
    const int ty = tid >> 4;

    const float scale = 0.08838834764831845f;   // 1/sqrt(128)
    const size_t rowstride = 3 * DMODEL;        // 1536

    {
        const float* qbase = qkv + ((size_t)b * SEQ + qblk * BQ) * rowstride + h * HDIM;
        #pragma unroll
        for (int t = 0; t < 8; t++) {
            int idx = tid + t * 256;
            int row = idx >> 5;
            int d4  = idx & 31;
            float4 v = *(const float4*)(qbase + (size_t)row * rowstride + d4 * 4);
            Qst[(d4*4+0)*QK_STRIDE + row] = v.x * scale;
            Qst[(d4*4+1)*QK_STRIDE + row] = v.y * scale;
            Qst[(d4*4+2)*QK_STRIDE + row] = v.z * scale;
            Qst[(d4*4+3)*QK_STRIDE + row] = v.w * scale;
        }
    }

    float o[4][8];
    float m[4], l[4];
    #pragma unroll
    for (int i = 0; i < 4; i++) {
        m[i] = -1e30f; l[i] = 0.f;
        #pragma unroll
        for (int j = 0; j < 8; j++) o[i][j] = 0.f;
    }

    const int ntiles = qblk + 1;
    for (int kt = 0; kt < ntiles; kt++) {
        const float* kbase = qkv + ((size_t)b * SEQ + kt * BK) * rowstride + h * HDIM + DMODEL;
        const float* vbase = kbase + DMODEL;
        __syncthreads();
        #pragma unroll
        for (int t = 0; t < 8; t++) {
            int idx = tid + t * 256;
            int row = idx >> 5;
            int d4  = idx & 31;
            float4 kv = *(const float4*)(kbase + (size_t)row * rowstride + d4 * 4);
            Kst[(d4*4+0)*QK_STRIDE + row] = kv.x;
            Kst[(d4*4+1)*QK_STRIDE + row] = kv.y;
            Kst[(d4*4+2)*QK_STRIDE + row] = kv.z;
            Kst[(d4*4+3)*QK_STRIDE + row] = kv.w;
            float4 vv = *(const float4*)(vbase + (size_t)row * rowstride + d4 * 4);
            *(float4*)(&Vs[row * 128 + d4 * 4]) = vv;
        }
        __syncthreads();

        float s[4][4];
        #pragma unroll
        for (int i = 0; i < 4; i++)
            #pragma unroll
            for (int j = 0; j < 4; j++) s[i][j] = 0.f;

        #pragma unroll 4
        for (int kk = 0; kk < 128; kk++) {
            float4 a = *(const float4*)(&Qst[kk * QK_STRIDE + ty * 4]);
            float4 bq = *(const float4*)(&Kst[kk * QK_STRIDE + tx * 4]);
            float av[4] = {a.x, a.y, a.z, a.w};
            float bv[4] = {bq.x, bq.y, bq.z, bq.w};
            #pragma unroll
            for (int i = 0; i < 4; i++)
                #pragma unroll
                for (int j = 0; j < 4; j++)
                    s[i][j] += av[i] * bv[j];
        }

        if (kt == qblk) {
            #pragma unroll
            for (int i = 0; i < 4; i++)
                #pragma unroll
                for (int j = 0; j < 4; j++)
                    if (tx * 4 + j > ty * 4 + i) s[i][j] = -1e30f;
        }

        #pragma unroll
        for (int i = 0; i < 4; i++) {
            float rm = fmaxf(fmaxf(s[i][0], s[i][1]), fmaxf(s[i][2], s[i][3]));
            #pragma unroll
            for (int off = 8; off > 0; off >>= 1)
                rm = fmaxf(rm, __shfl_xor_sync(0xffffffffu, rm, off));
            float mnew = fmaxf(m[i], rm);
            float rs = 0.f;
            #pragma unroll
            for (int j = 0; j < 4; j++) {
                float p = __expf(s[i][j] - mnew);
                s[i][j] = p;
                rs += p;
            }
            #pragma unroll
            for (int off = 8; off > 0; off >>= 1)
                rs += __shfl_xor_sync(0xffffffffu, rs, off);
            float corr = __expf(m[i] - mnew);
            l[i] = l[i] * corr + rs;
            m[i] = mnew;
            #pragma unroll
            for (int j = 0; j < 8; j++) o[i][j] *= corr;
            *(float4*)(&Ps[(ty * 4 + i) * QK_STRIDE + tx * 4]) =
                make_float4(s[i][0], s[i][1], s[i][2], s[i][3]);
        }
        __syncthreads();

        #pragma unroll 4
        for (int kk = 0; kk < BK; kk++) {
            float a[4];
            #pragma unroll
            for (int i = 0; i < 4; i++) a[i] = Ps[(ty * 4 + i) * QK_STRIDE + kk];
            float4 b0 = *(const float4*)(&Vs[kk * 128 + tx * 8]);
            float4 b1 = *(const float4*)(&Vs[kk * 128 + tx * 8 + 4]);
            #pragma unroll
            for (int i = 0; i < 4; i++) {
                o[i][0] += a[i] * b0.x;
                o[i][1] += a[i] * b0.y;
                o[i][2] += a[i] * b0.z;
                o[i][3] += a[i] * b0.w;
                o[i][4] += a[i] * b1.x;
                o[i][5] += a[i] * b1.y;
                o[i][6] += a[i] * b1.z;
                o[i][7] += a[i] * b1.w;
            }
        }
    }

    #pragma unroll
    for (int i = 0; i < 4; i++) {
        float inv = 1.f / l[i];
        int row = qblk * BQ + ty * 4 + i;
        float* orow = out + ((size_t)b * SEQ + row) * DMODEL + h * HDIM + tx * 8;
        float4 v0, v1;
        v0.x = o[i][0]*inv; v0.y = o[i][1]*inv; v0.z = o[i][2]*inv; v0.w = o[i][3]*inv;
        v1.x = o[i][4]*inv; v1.y = o[i][5]*inv; v1.z = o[i][6]*inv; v1.w = o[i][7]*inv;
        *(float4*)(orow)     = v0;
        *(float4*)(orow + 4) = v1;
    }
}

// ---------------------------------------------------------------------------
// Launch
// ---------------------------------------------------------------------------
extern "C" void kernel_launch(void* const* d_in, const int* in_sizes, int n_in,
                              void* d_out, int out_size)
{
    const float* x      = (const float*)d_in[0];
    const float* ln1_g  = (const float*)d_in[1];
    const float* ln1_b  = (const float*)d_in[2];
    const float* w_qkv  = (const float*)d_in[3];
    const float* w_proj = (const float*)d_in[4];
    const float* ln2_g  = (const float*)d_in[5];
    const float* ln2_b  = (const float*)d_in[6];
    const float* w_ff1  = (const float*)d_in[7];
    const float* w_ff2  = (const float*)d_in[8];
    float* out = (float*)d_out;

    float *ln1, *qkv, *attn, *x1, *ln2, *ff1;
    cudaGetSymbolAddress((void**)&ln1,  g_ln1);
    cudaGetSymbolAddress((void**)&qkv,  g_qkv);
    cudaGetSymbolAddress((void**)&attn, g_attn);
    cudaGetSymbolAddress((void**)&x1,   g_x1);
    cudaGetSymbolAddress((void**)&ln2,  g_ln2);
    cudaGetSymbolAddress((void**)&ff1,  g_ff1);

    cudaFuncSetAttribute(attn_kernel2,
                         cudaFuncAttributeMaxDynamicSharedMemorySize, ATTN_SMEM);

    dim3 lnBlk(32, 8);

    // 1. ln1 = LN(x)
    ln_kernel<<<MROWS / 8, lnBlk>>>(x, ln1_g, ln1_b, ln1, MROWS);
    // 2. qkv = ln1 @ w_qkv           [8192,1536]
    gemm_tc<0><<<dim3(1536/128, MROWS/128), 256>>>(ln1, w_qkv, nullptr, qkv,
                                                   MROWS, 3*DMODEL, DMODEL);
    // 3. attn = causal_flash(qkv)    [8192,512]
    attn_kernel2<<<dim3(SEQ/BQ, NHEADS, BATCH), 256, ATTN_SMEM>>>(qkv, attn);
    // 4. x1 = x + attn @ w_proj
    gemm_tc<2><<<dim3(512/128, MROWS/128), 256>>>(attn, w_proj, x, x1,
                                                  MROWS, DMODEL, DMODEL);
    // 5. ln2 = LN(x1)
    ln_kernel<<<MROWS / 8, lnBlk>>>(x1, ln2_g, ln2_b, ln2, MROWS);
    // 6. ff1 = gelu(ln2 @ w_ff1)     [8192,2048]
    gemm_tc<1><<<dim3(DFF/128, MROWS/128), 256>>>(ln2, w_ff1, nullptr, ff1,
                                                  MROWS, DFF, DMODEL);
    // 7. out = x1 + ff1 @ w_ff2
    gemm_tc<2><<<dim3(512/128, MROWS/128), 256>>>(ff1, w_ff2, x1, out,
                                                  MROWS, DMODEL, DFF);
}

// round 4
// speedup vs baseline: 23.7112x; 2.5083x over previous
#include <cuda_runtime.h>
#include <cuda_bf16.h>
#include <math.h>
#include <stdint.h>

// Problem constants
#define BATCH 4
#define SEQ   2048
#define DMODEL 512
#define NHEADS 4
#define HDIM  128
#define DFF   2048
#define MROWS (BATCH*SEQ)   // 8192

// ---------------------------------------------------------------------------
// Static scratch (no allocation allowed)
// ---------------------------------------------------------------------------
__device__ float g_ln1 [MROWS * DMODEL];
__device__ float g_qkv [MROWS * 3 * DMODEL];
__device__ float g_attn[MROWS * DMODEL];
__device__ float g_x1  [MROWS * DMODEL];
__device__ float g_ln2 [MROWS * DMODEL];
__device__ float g_ff1 [MROWS * DFF];

// ---------------------------------------------------------------------------
// Common PTX helpers
// ---------------------------------------------------------------------------
__device__ __forceinline__ void mma_tf32(float c[4], const uint32_t a[4], const uint32_t b[2]) {
    asm volatile(
        "mma.sync.aligned.m16n8k8.row.col.f32.tf32.tf32.f32 "
        "{%0,%1,%2,%3}, {%4,%5,%6,%7}, {%8,%9}, {%0,%1,%2,%3};"
        : "+f"(c[0]), "+f"(c[1]), "+f"(c[2]), "+f"(c[3])
        : "r"(a[0]), "r"(a[1]), "r"(a[2]), "r"(a[3]), "r"(b[0]), "r"(b[1]));
}

__device__ __forceinline__ void cp16(const void* smem, const void* gmem) {
    uint32_t s = (uint32_t)__cvta_generic_to_shared(smem);
    asm volatile("cp.async.cg.shared.global [%0], [%1], 16;" :: "r"(s), "l"(gmem));
}
__device__ __forceinline__ void cp_commit() {
    asm volatile("cp.async.commit_group;");
}
template <int N>
__device__ __forceinline__ void cp_wait() {
    asm volatile("cp.async.wait_group %0;" :: "n"(N));
}

// ---------------------------------------------------------------------------
// LayerNorm: one warp per row (D=512), 8 warps per block
// ---------------------------------------------------------------------------
__global__ void ln_kernel(const float* __restrict__ x,
                          const float* __restrict__ g,
                          const float* __restrict__ b,
                          float* __restrict__ out, int rows)
{
    int row  = blockIdx.x * 8 + threadIdx.y;
    int lane = threadIdx.x;
    if (row >= rows) return;

    const float4* xr = (const float4*)(x + (size_t)row * DMODEL);
    float4 v[4];
    float s = 0.f, s2 = 0.f;
    #pragma unroll
    for (int i = 0; i < 4; i++) {
        v[i] = xr[lane + i * 32];
        s  += v[i].x + v[i].y + v[i].z + v[i].w;
        s2 += v[i].x*v[i].x + v[i].y*v[i].y + v[i].z*v[i].z + v[i].w*v[i].w;
    }
    #pragma unroll
    for (int o = 16; o > 0; o >>= 1) {
        s  += __shfl_xor_sync(0xffffffffu, s,  o);
        s2 += __shfl_xor_sync(0xffffffffu, s2, o);
    }
    float mu  = s * (1.f / DMODEL);
    float var = s2 * (1.f / DMODEL) - mu * mu;
    float inv = rsqrtf(var + 1e-5f);

    float4* orow = (float4*)(out + (size_t)row * DMODEL);
    const float4* g4 = (const float4*)g;
    const float4* b4 = (const float4*)b;
    #pragma unroll
    for (int i = 0; i < 4; i++) {
        float4 gg = g4[lane + i * 32];
        float4 bb = b4[lane + i * 32];
        float4 r;
        r.x = (v[i].x - mu) * inv * gg.x + bb.x;
        r.y = (v[i].y - mu) * inv * gg.y + bb.y;
        r.z = (v[i].z - mu) * inv * gg.z + bb.z;
        r.w = (v[i].w - mu) * inv * gg.w + bb.w;
        orow[lane + i * 32] = r;
    }
}

// ---------------------------------------------------------------------------
// tf32 tensor-core GEMM with cp.async double-buffered pipeline.
// BM=BN=128, BK=32, 256 threads = 8 warps (4m x 2n), warp tile 32x64.
// Raw fp32 bits fed to tf32 MMA (HW truncation; no cvt).
// EPI: 0 = none, 1 = exact GELU, 2 = add residual
// ---------------------------------------------------------------------------
#define AS_STRIDE 36
#define BS_STRIDE 136
#define AS_ELEMS (128 * AS_STRIDE)   // 4608
#define BS_ELEMS (32 * BS_STRIDE)    // 4352
#define GEMM_SMEM ((AS_ELEMS + BS_ELEMS) * 2 * 4)   // 71680 B

__device__ __forceinline__ void gemm_load_stage(
    float* As, float* Bs, const float* Ab, const float* Bb,
    int k0, int K, int N, int tid)
{
    #pragma unroll
    for (int t = 0; t < 4; t++) {
        int idx = tid + t * 256;
        int ar = idx >> 3, ac = idx & 7;
        cp16(As + ar * AS_STRIDE + ac * 4, Ab + (size_t)ar * K + k0 + ac * 4);
        int br = idx >> 5, bc = idx & 31;
        cp16(Bs + br * BS_STRIDE + bc * 4, Bb + (size_t)(k0 + br) * N + bc * 4);
    }
}

template <int EPI>
__global__ void __launch_bounds__(256, 2)
gemm_tc(const float* __restrict__ A, const float* __restrict__ Bm,
        const float* __restrict__ res, float* __restrict__ C,
        int M, int N, int K)
{
    extern __shared__ float smg[];
    float* As0 = smg;
    float* As1 = As0 + AS_ELEMS;
    float* Bs0 = As1 + AS_ELEMS;
    float* Bs1 = Bs0 + BS_ELEMS;

    const int tid  = threadIdx.x;
    const int lane = tid & 31;
    const int wid  = tid >> 5;
    const int wm   = wid >> 1;     // 0..3  (m)
    const int wn   = wid & 1;      // 0..1  (n)
    const int g    = lane >> 2;    // 0..7
    const int tig  = lane & 3;     // 0..3

    const int bx = blockIdx.x;
    const int by = blockIdx.y;

    const float* Ab = A + (size_t)(by * 128) * K;
    const float* Bb = Bm + (size_t)(bx * 128);

    float acc[2][8][4];
    #pragma unroll
    for (int mf = 0; mf < 2; mf++)
        #pragma unroll
        for (int nf = 0; nf < 8; nf++)
            #pragma unroll
            for (int r = 0; r < 4; r++) acc[mf][nf][r] = 0.f;

    const int nt = K >> 5;
    gemm_load_stage(As0, Bs0, Ab, Bb, 0, K, N, tid);
    cp_commit();

    for (int kt = 0; kt < nt; kt++) {
        const float* Asc = (kt & 1) ? As1 : As0;
        const float* Bsc = (kt & 1) ? Bs1 : Bs0;
        if (kt + 1 < nt) {
            float* Asn = (kt & 1) ? As0 : As1;
            float* Bsn = (kt & 1) ? Bs0 : Bs1;
            gemm_load_stage(Asn, Bsn, Ab, Bb, (kt + 1) * 32, K, N, tid);
            cp_commit();
            cp_wait<1>();
        } else {
            cp_wait<0>();
        }
        __syncthreads();

        #pragma unroll
        for (int ks = 0; ks < 4; ks++) {
            uint32_t af[2][4], bf[8][2];
            const int kc = ks * 8 + tig;
            #pragma unroll
            for (int mf = 0; mf < 2; mf++) {
                int r = wm * 32 + mf * 16 + g;
                af[mf][0] = __float_as_uint(Asc[r       * AS_STRIDE + kc]);
                af[mf][1] = __float_as_uint(Asc[(r + 8) * AS_STRIDE + kc]);
                af[mf][2] = __float_as_uint(Asc[r       * AS_STRIDE + kc + 4]);
                af[mf][3] = __float_as_uint(Asc[(r + 8) * AS_STRIDE + kc + 4]);
            }
            #pragma unroll
            for (int nf = 0; nf < 8; nf++) {
                int nc = wn * 64 + nf * 8 + g;
                bf[nf][0] = __float_as_uint(Bsc[(ks * 8 + tig)     * BS_STRIDE + nc]);
                bf[nf][1] = __float_as_uint(Bsc[(ks * 8 + tig + 4) * BS_STRIDE + nc]);
            }
            #pragma unroll
            for (int mf = 0; mf < 2; mf++)
                #pragma unroll
                for (int nf = 0; nf < 8; nf++)
                    mma_tf32(acc[mf][nf], af[mf], bf[nf]);
        }
        __syncthreads();
    }

    // epilogue
    #pragma unroll
    for (int mf = 0; mf < 2; mf++) {
        #pragma unroll
        for (int i2 = 0; i2 < 2; i2++) {
            int row = by * 128 + wm * 32 + mf * 16 + g + i2 * 8;
            #pragma unroll
            for (int nf = 0; nf < 8; nf++) {
                int col = bx * 128 + wn * 64 + nf * 8 + tig * 2;
                float v0 = acc[mf][nf][i2 * 2 + 0];
                float v1 = acc[mf][nf][i2 * 2 + 1];
                size_t off = (size_t)row * N + col;
                if (EPI == 1) {
                    v0 = 0.5f * v0 * (1.f + erff(v0 * 0.70710678118654752f));
                    v1 = 0.5f * v1 * (1.f + erff(v1 * 0.70710678118654752f));
                }
                if (EPI == 2) {
                    float2 r = *(const float2*)(res + off);
                    v0 += r.x; v1 += r.y;
                }
                *(float2*)(C + off) = make_float2(v0, v1);
            }
        }
    }
}

// ---------------------------------------------------------------------------
// Tensor-core flash attention, tf32 MMA, causal.
// 128 threads = 4... 8 warps? -> 128 threads = 4 warps is wrong; we use 8 warps
// NOTE: block = 256 threads? No: 8 warps x 16 rows = BQ 128 -> 256 threads.
// Each warp owns 16 q-rows completely (softmax = 4-lane shuffles).
// BQ=128 (8 warps x 16 rows), BK=64, HDIM=128.
// S = Q K^T via m16n8k8 tf32 (raw fp32 bits); P -> smem; O += P V via MMA.
// Scale folded into exp: softmax(c*s) tracked with unscaled running max.
// ---------------------------------------------------------------------------
#define BQA 128
#define BKA 64
#define QS_STR 132
#define KS_STR 132
#define VS_STR 136
#define PS_STR 68
#define ATTN_SMEM ((BQA*QS_STR + BKA*KS_STR + BKA*VS_STR + BQA*PS_STR) * 4)

__global__ void __launch_bounds__(256, 1)
attn_tc(const float* __restrict__ qkv, float* __restrict__ out)
{
    extern __shared__ float sma[];
    float* Qs = sma;                       // [128][132] row-major (q, d)
    float* Ks = Qs + BQA * QS_STR;         // [64][132]  row-major (j, d)
    float* Vs = Ks + BKA * KS_STR;         // [64][136]  row-major (j, d)
    float* Ps = Vs + BKA * VS_STR;         // [128][68]  row-major (q, j)

    const int qblk = (SEQ / BQA - 1) - blockIdx.x;   // heavy blocks first
    const int h  = blockIdx.y;
    const int b  = blockIdx.z;
    const int tid  = threadIdx.x;
    const int lane = tid & 31;
    const int wid  = tid >> 5;          // 0..7
    const int g    = lane >> 2;         // 0..7
    const int tig  = lane & 3;          // 0..3
    const int m0w  = wid * 16;          // warp's first q row (local)

    const size_t rstride = 3 * DMODEL;  // 1536
    const float scale = 0.08838834764831845f;   // 1/sqrt(128)

    // ---- load Q tile [128][128], straight copy ----
    {
        const float* qbase = qkv + ((size_t)b * SEQ + qblk * BQA) * rstride + h * HDIM;
        #pragma unroll
        for (int t = 0; t < 16; t++) {
            int idx = tid + t * 256;        // 0..4095
            int row = idx >> 5, d4 = idx & 31;
            *(float4*)(&Qs[row * QS_STR + d4 * 4]) =
                *(const float4*)(qbase + (size_t)row * rstride + d4 * 4);
        }
    }

    float o[16][4];
    #pragma unroll
    for (int nf = 0; nf < 16; nf++)
        #pragma unroll
        for (int r = 0; r < 4; r++) o[nf][r] = 0.f;
    float m0 = -1e30f, m1 = -1e30f, l0 = 0.f, l1 = 0.f;

    const int ntiles = 2 * qblk + 2;
    for (int kt = 0; kt < ntiles; kt++) {
        const float* kbase = qkv + ((size_t)b * SEQ + kt * BKA) * rstride + h * HDIM + DMODEL;
        const float* vbase = kbase + DMODEL;
        __syncthreads();    // previous tile's consumers done
        #pragma unroll
        for (int t = 0; t < 8; t++) {
            int idx = tid + t * 256;        // 0..2047
            int row = idx >> 5, d4 = idx & 31;
            *(float4*)(&Ks[row * KS_STR + d4 * 4]) =
                *(const float4*)(kbase + (size_t)row * rstride + d4 * 4);
            *(float4*)(&Vs[row * VS_STR + d4 * 4]) =
                *(const float4*)(vbase + (size_t)row * rstride + d4 * 4);
        }
        __syncthreads();

        // ---- S = Q K^T : rows [m0w, m0w+16), cols [0,64) ----
        float s[8][4];
        #pragma unroll
        for (int nf = 0; nf < 8; nf++)
            #pragma unroll
            for (int r = 0; r < 4; r++) s[nf][r] = 0.f;

        #pragma unroll
        for (int kk = 0; kk < 16; kk++) {
            uint32_t a[4];
            const float* q0 = &Qs[(m0w + g)     * QS_STR + kk * 8];
            const float* q1 = &Qs[(m0w + 8 + g) * QS_STR + kk * 8];
            a[0] = __float_as_uint(q0[tig]);
            a[1] = __float_as_uint(q1[tig]);
            a[2] = __float_as_uint(q0[tig + 4]);
            a[3] = __float_as_uint(q1[tig + 4]);
            #pragma unroll
            for (int nf = 0; nf < 8; nf++) {
                uint32_t bb[2];
                const float* kr = &Ks[(nf * 8 + g) * KS_STR + kk * 8];
                bb[0] = __float_as_uint(kr[tig]);
                bb[1] = __float_as_uint(kr[tig + 4]);
                mma_tf32(s[nf], a, bb);
            }
        }

        // ---- causal mask (only the last two tiles of this q block) ----
        if (kt >= 2 * qblk) {
            int qrow0 = qblk * BQA + m0w + g;
            int col0  = kt * BKA;
            #pragma unroll
            for (int nf = 0; nf < 8; nf++) {
                int c0 = col0 + nf * 8 + tig * 2;
                if (c0     > qrow0)     s[nf][0] = -1e30f;
                if (c0 + 1 > qrow0)     s[nf][1] = -1e30f;
                if (c0     > qrow0 + 8) s[nf][2] = -1e30f;
                if (c0 + 1 > qrow0 + 8) s[nf][3] = -1e30f;
            }
        }

        // ---- online softmax (rows g and g+8; reduce over 4 tig lanes) ----
        float rm0 = -1e30f, rm1 = -1e30f;
        #pragma unroll
        for (int nf = 0; nf < 8; nf++) {
            rm0 = fmaxf(rm0, fmaxf(s[nf][0], s[nf][1]));
            rm1 = fmaxf(rm1, fmaxf(s[nf][2], s[nf][3]));
        }
        rm0 = fmaxf(rm0, __shfl_xor_sync(0xffffffffu, rm0, 1));
        rm0 = fmaxf(rm0, __shfl_xor_sync(0xffffffffu, rm0, 2));
        rm1 = fmaxf(rm1, __shfl_xor_sync(0xffffffffu, rm1, 1));
        rm1 = fmaxf(rm1, __shfl_xor_sync(0xffffffffu, rm1, 2));
        float mn0 = fmaxf(m0, rm0);
        float mn1 = fmaxf(m1, rm1);

        float rs0 = 0.f, rs1 = 0.f;
        #pragma unroll
        for (int nf = 0; nf < 8; nf++) {
            float p00 = __expf((s[nf][0] - mn0) * scale);
            float p01 = __expf((s[nf][1] - mn0) * scale);
            float p10 = __expf((s[nf][2] - mn1) * scale);
            float p11 = __expf((s[nf][3] - mn1) * scale);
            rs0 += p00 + p01;
            rs1 += p10 + p11;
            *(float2*)(&Ps[(m0w + g)     * PS_STR + nf * 8 + tig * 2]) = make_float2(p00, p01);
            *(float2*)(&Ps[(m0w + 8 + g) * PS_STR + nf * 8 + tig * 2]) = make_float2(p10, p11);
        }
        rs0 += __shfl_xor_sync(0xffffffffu, rs0, 1);
        rs0 += __shfl_xor_sync(0xffffffffu, rs0, 2);
        rs1 += __shfl_xor_sync(0xffffffffu, rs1, 1);
        rs1 += __shfl_xor_sync(0xffffffffu, rs1, 2);

        float corr0 = __expf((m0 - mn0) * scale);
        float corr1 = __expf((m1 - mn1) * scale);
        l0 = l0 * corr0 + rs0;
        l1 = l1 * corr1 + rs1;
        m0 = mn0; m1 = mn1;
        #pragma unroll
        for (int nf = 0; nf < 16; nf++) {
            o[nf][0] *= corr0; o[nf][1] *= corr0;
            o[nf][2] *= corr1; o[nf][3] *= corr1;
        }
        __syncwarp();    // Ps write -> read (same warp's rows only)

        // ---- O += P V : rows [m0w,m0w+16), dims [0,128) ----
        #pragma unroll
        for (int kk = 0; kk < 8; kk++) {
            uint32_t a[4];
            const float* p0 = &Ps[(m0w + g)     * PS_STR + kk * 8];
            const float* p1 = &Ps[(m0w + 8 + g) * PS_STR + kk * 8];
            a[0] = __float_as_uint(p0[tig]);
            a[1] = __float_as_uint(p1[tig]);
            a[2] = __float_as_uint(p0[tig + 4]);
            a[3] = __float_as_uint(p1[tig + 4]);
            #pragma unroll
            for (int nf = 0; nf < 16; nf++) {
                uint32_t bb[2];
                const float* vr = &Vs[(kk * 8 + tig) * VS_STR + nf * 8 + g];
                bb[0] = __float_as_uint(vr[0]);
                bb[1] = __float_as_uint(Vs[(kk * 8 + tig + 4) * VS_STR + nf * 8 + g]);
                mma_tf32(o[nf], a, bb);
            }
        }
    }

    // ---- write O (divide by l) ----
    float inv0 = 1.f / l0, inv1 = 1.f / l1;
    int row0 = qblk * BQA + m0w + g;
    float* ob0 = out + ((size_t)b * SEQ + row0)     * DMODEL + h * HDIM;
    float* ob1 = out + ((size_t)b * SEQ + row0 + 8) * DMODEL + h * HDIM;
    #pragma unroll
    for (int nf = 0; nf < 16; nf++) {
        *(float2*)(ob0 + nf * 8 + tig * 2) = make_float2(o[nf][0] * inv0, o[nf][1] * inv0);
        *(float2*)(ob1 + nf * 8 + tig * 2) = make_float2(o[nf][2] * inv1, o[nf][3] * inv1);
    }
}

// ---------------------------------------------------------------------------
// Launch
// ---------------------------------------------------------------------------
extern "C" void kernel_launch(void* const* d_in, const int* in_sizes, int n_in,
                              void* d_out, int out_size)
{
    const float* x      = (const float*)d_in[0];
    const float* ln1_g  = (const float*)d_in[1];
    const float* ln1_b  = (const float*)d_in[2];
    const float* w_qkv  = (const float*)d_in[3];
    const float* w_proj = (const float*)d_in[4];
    const float* ln2_g  = (const float*)d_in[5];
    const float* ln2_b  = (const float*)d_in[6];
    const float* w_ff1  = (const float*)d_in[7];
    const float* w_ff2  = (const float*)d_in[8];
    float* out = (float*)d_out;

    float *ln1, *qkv, *attn, *x1, *ln2, *ff1;
    cudaGetSymbolAddress((void**)&ln1,  g_ln1);
    cudaGetSymbolAddress((void**)&qkv,  g_qkv);
    cudaGetSymbolAddress((void**)&attn, g_attn);
    cudaGetSymbolAddress((void**)&x1,   g_x1);
    cudaGetSymbolAddress((void**)&ln2,  g_ln2);
    cudaGetSymbolAddress((void**)&ff1,  g_ff1);

    cudaFuncSetAttribute(gemm_tc<0>, cudaFuncAttributeMaxDynamicSharedMemorySize, GEMM_SMEM);
    cudaFuncSetAttribute(gemm_tc<1>, cudaFuncAttributeMaxDynamicSharedMemorySize, GEMM_SMEM);
    cudaFuncSetAttribute(gemm_tc<2>, cudaFuncAttributeMaxDynamicSharedMemorySize, GEMM_SMEM);
    cudaFuncSetAttribute(attn_tc,    cudaFuncAttributeMaxDynamicSharedMemorySize, ATTN_SMEM);

    dim3 lnBlk(32, 8);

    // 1. ln1 = LN(x)
    ln_kernel<<<MROWS / 8, lnBlk>>>(x, ln1_g, ln1_b, ln1, MROWS);
    // 2. qkv = ln1 @ w_qkv           [8192,1536]
    gemm_tc<0><<<dim3(1536/128, MROWS/128), 256, GEMM_SMEM>>>(ln1, w_qkv, nullptr, qkv,
                                                              MROWS, 3*DMODEL, DMODEL);
    // 3. attn = causal_flash(qkv)    [8192,512]
    attn_tc<<<dim3(SEQ/BQA, NHEADS, BATCH), 256, ATTN_SMEM>>>(qkv, attn);
    // 4. x1 = x + attn @ w_proj
    gemm_tc<2><<<dim3(512/128, MROWS/128), 256, GEMM_SMEM>>>(attn, w_proj, x, x1,
                                                             MROWS, DMODEL, DMODEL);
    // 5. ln2 = LN(x1)
    ln_kernel<<<MROWS / 8, lnBlk>>>(x1, ln2_g, ln2_b, ln2, MROWS);
    // 6. ff1 = gelu(ln2 @ w_ff1)     [8192,2048]
    gemm_tc<1><<<dim3(DFF/128, MROWS/128), 256, GEMM_SMEM>>>(ln2, w_ff1, nullptr, ff1,
                                                             MROWS, DFF, DMODEL);
    // 7. out = x1 + ff1 @ w_ff2
    gemm_tc<2><<<dim3(512/128, MROWS/128), 256, GEMM_SMEM>>>(ff1, w_ff2, x1, out,
                                                             MROWS, DMODEL, DFF);
}

// round 5
// speedup vs baseline: 24.0349x; 1.0137x over previous
#include <cuda_runtime.h>
#include <cuda_bf16.h>
#include <math.h>
#include <stdint.h>

// Problem constants
#define BATCH 4
#define SEQ   2048
#define DMODEL 512
#define NHEADS 4
#define HDIM  128
#define DFF   2048
#define MROWS (BATCH*SEQ)   // 8192

// ---------------------------------------------------------------------------
// Static scratch (no allocation allowed)
// ---------------------------------------------------------------------------
__device__ float g_ln1 [MROWS * DMODEL];
__device__ float g_qkv [MROWS * 3 * DMODEL];
__device__ float g_attn[MROWS * DMODEL];
__device__ float g_x1  [MROWS * DMODEL];
__device__ float g_ln2 [MROWS * DMODEL];
__device__ float g_ff1 [MROWS * DFF];

// ---------------------------------------------------------------------------
// Common PTX helpers
// ---------------------------------------------------------------------------
__device__ __forceinline__ void mma_tf32(float c[4], const uint32_t a[4], const uint32_t b[2]) {
    asm volatile(
        "mma.sync.aligned.m16n8k8.row.col.f32.tf32.tf32.f32 "
        "{%0,%1,%2,%3}, {%4,%5,%6,%7}, {%8,%9}, {%0,%1,%2,%3};"
        : "+f"(c[0]), "+f"(c[1]), "+f"(c[2]), "+f"(c[3])
        : "r"(a[0]), "r"(a[1]), "r"(a[2]), "r"(a[3]), "r"(b[0]), "r"(b[1]));
}

__device__ __forceinline__ void cp16(const void* smem, const void* gmem) {
    uint32_t s = (uint32_t)__cvta_generic_to_shared(smem);
    asm volatile("cp.async.cg.shared.global [%0], [%1], 16;" :: "r"(s), "l"(gmem));
}
__device__ __forceinline__ void cp_commit() {
    asm volatile("cp.async.commit_group;");
}
template <int N>
__device__ __forceinline__ void cp_wait() {
    asm volatile("cp.async.wait_group %0;" :: "n"(N));
}

// ---------------------------------------------------------------------------
// LayerNorm: one warp per row (D=512), 8 warps per block
// ---------------------------------------------------------------------------
__global__ void ln_kernel(const float* __restrict__ x,
                          const float* __restrict__ g,
                          const float* __restrict__ b,
                          float* __restrict__ out, int rows)
{
    int row  = blockIdx.x * 8 + threadIdx.y;
    int lane = threadIdx.x;
    if (row >= rows) return;

    const float4* xr = (const float4*)(x + (size_t)row * DMODEL);
    float4 v[4];
    float s = 0.f, s2 = 0.f;
    #pragma unroll
    for (int i = 0; i < 4; i++) {
        v[i] = xr[lane + i * 32];
        s  += v[i].x + v[i].y + v[i].z + v[i].w;
        s2 += v[i].x*v[i].x + v[i].y*v[i].y + v[i].z*v[i].z + v[i].w*v[i].w;
    }
    #pragma unroll
    for (int o = 16; o > 0; o >>= 1) {
        s  += __shfl_xor_sync(0xffffffffu, s,  o);
        s2 += __shfl_xor_sync(0xffffffffu, s2, o);
    }
    float mu  = s * (1.f / DMODEL);
    float var = s2 * (1.f / DMODEL) - mu * mu;
    float inv = rsqrtf(var + 1e-5f);

    float4* orow = (float4*)(out + (size_t)row * DMODEL);
    const float4* g4 = (const float4*)g;
    const float4* b4 = (const float4*)b;
    #pragma unroll
    for (int i = 0; i < 4; i++) {
        float4 gg = g4[lane + i * 32];
        float4 bb = b4[lane + i * 32];
        float4 r;
        r.x = (v[i].x - mu) * inv * gg.x + bb.x;
        r.y = (v[i].y - mu) * inv * gg.y + bb.y;
        r.z = (v[i].z - mu) * inv * gg.z + bb.z;
        r.w = (v[i].w - mu) * inv * gg.w + bb.w;
        orow[lane + i * 32] = r;
    }
}

// ---------------------------------------------------------------------------
// tf32 tensor-core GEMM, cp.async double buffer, single sync per k-tile.
// Block 128x128x32, 128 threads = 4 warps (2m x 2n), warp tile 64x64.
// Per ks: 32 scalar LDS feed 32 MMAs (LDS:MMA = 1.0).
// EPI: 0 = none, 1 = exact GELU, 2 = add residual
// ---------------------------------------------------------------------------
#define AS_STRIDE 36
#define BS_STRIDE 136
#define AS_ELEMS (128 * AS_STRIDE)   // 4608
#define BS_ELEMS (32 * BS_STRIDE)    // 4352
#define STAGE_ELEMS (AS_ELEMS + BS_ELEMS)
#define GEMM_SMEM (STAGE_ELEMS * 2 * 4)   // 71680 B

__device__ __forceinline__ void gemm_load_stage(
    float* stage, const float* Ab, const float* Bb,
    int k0, int K, int N, int tid)
{
    float* As = stage;
    float* Bs = stage + AS_ELEMS;
    #pragma unroll
    for (int t = 0; t < 8; t++) {
        int idx = tid + t * 128;
        int ar = idx >> 3, ac = idx & 7;
        cp16(As + ar * AS_STRIDE + ac * 4, Ab + (size_t)ar * K + k0 + ac * 4);
    }
    #pragma unroll
    for (int t = 0; t < 8; t++) {
        int idx = tid + t * 128;
        int br = idx >> 5, bc = idx & 31;
        cp16(Bs + br * BS_STRIDE + bc * 4, Bb + (size_t)(k0 + br) * N + bc * 4);
    }
}

template <int EPI>
__global__ void __launch_bounds__(128, 2)
gemm_tc(const float* __restrict__ A, const float* __restrict__ Bm,
        const float* __restrict__ res, float* __restrict__ C,
        int M, int N, int K)
{
    extern __shared__ float smg[];
    float* stage0 = smg;
    float* stage1 = smg + STAGE_ELEMS;

    const int tid  = threadIdx.x;
    const int lane = tid & 31;
    const int wid  = tid >> 5;     // 0..3
    const int wm   = wid >> 1;     // 0..1  (m, x64)
    const int wn   = wid & 1;      // 0..1  (n, x64)
    const int g    = lane >> 2;    // 0..7
    const int tig  = lane & 3;     // 0..3

    const int bx = blockIdx.x;
    const int by = blockIdx.y;

    const float* Ab = A + (size_t)(by * 128) * K;
    const float* Bb = Bm + (size_t)(bx * 128);

    float acc[4][8][4];
    #pragma unroll
    for (int mf = 0; mf < 4; mf++)
        #pragma unroll
        for (int nf = 0; nf < 8; nf++)
            #pragma unroll
            for (int r = 0; r < 4; r++) acc[mf][nf][r] = 0.f;

    const int nt = K >> 5;
    gemm_load_stage(stage0, Ab, Bb, 0, K, N, tid);
    cp_commit();

    for (int kt = 0; kt < nt; kt++) {
        const float* cur = (kt & 1) ? stage1 : stage0;
        const float* Asc = cur;
        const float* Bsc = cur + AS_ELEMS;

        cp_wait<0>();          // my stage-kt copies done
        __syncthreads();       // everyone's stage-kt copies visible; compute kt-1 finished

        if (kt + 1 < nt) {     // issue next stage into the other buffer (safe post-sync)
            float* nxt = (kt & 1) ? stage0 : stage1;
            gemm_load_stage(nxt, Ab, Bb, (kt + 1) * 32, K, N, tid);
            cp_commit();
        }

        #pragma unroll
        for (int ks = 0; ks < 4; ks++) {
            uint32_t af[4][4], bf[8][2];
            const int kc = ks * 8 + tig;
            #pragma unroll
            for (int mf = 0; mf < 4; mf++) {
                int r = wm * 64 + mf * 16 + g;
                af[mf][0] = __float_as_uint(Asc[r       * AS_STRIDE + kc]);
                af[mf][1] = __float_as_uint(Asc[(r + 8) * AS_STRIDE + kc]);
                af[mf][2] = __float_as_uint(Asc[r       * AS_STRIDE + kc + 4]);
                af[mf][3] = __float_as_uint(Asc[(r + 8) * AS_STRIDE + kc + 4]);
            }
            #pragma unroll
            for (int nf = 0; nf < 8; nf++) {
                int nc = wn * 64 + nf * 8 + g;
                bf[nf][0] = __float_as_uint(Bsc[(ks * 8 + tig)     * BS_STRIDE + nc]);
                bf[nf][1] = __float_as_uint(Bsc[(ks * 8 + tig + 4) * BS_STRIDE + nc]);
            }
            #pragma unroll
            for (int mf = 0; mf < 4; mf++)
                #pragma unroll
                for (int nf = 0; nf < 8; nf++)
                    mma_tf32(acc[mf][nf], af[mf], bf[nf]);
        }
    }

    // epilogue
    #pragma unroll
    for (int mf = 0; mf < 4; mf++) {
        #pragma unroll
        for (int i2 = 0; i2 < 2; i2++) {
            int row = by * 128 + wm * 64 + mf * 16 + g + i2 * 8;
            #pragma unroll
            for (int nf = 0; nf < 8; nf++) {
                int col = bx * 128 + wn * 64 + nf * 8 + tig * 2;
                float v0 = acc[mf][nf][i2 * 2 + 0];
                float v1 = acc[mf][nf][i2 * 2 + 1];
                size_t off = (size_t)row * N + col;
                if (EPI == 1) {
                    v0 = 0.5f * v0 * (1.f + erff(v0 * 0.70710678118654752f));
                    v1 = 0.5f * v1 * (1.f + erff(v1 * 0.70710678118654752f));
                }
                if (EPI == 2) {
                    float2 r = *(const float2*)(res + off);
                    v0 += r.x; v1 += r.y;
                }
                *(float2*)(C + off) = make_float2(v0, v1);
            }
        }
    }
}

// ---------------------------------------------------------------------------
// Tensor-core flash attention, tf32 MMA, causal. (unchanged from R3 — passing)
// 256 threads = 8 warps, each warp owns 16 q-rows. BQ=128, BK=64.
// ---------------------------------------------------------------------------
#define BQA 128
#define BKA 64
#define QS_STR 132
#define KS_STR 132
#define VS_STR 136
#define PS_STR 68
#define ATTN_SMEM ((BQA*QS_STR + BKA*KS_STR + BKA*VS_STR + BQA*PS_STR) * 4)

__global__ void __launch_bounds__(256, 1)
attn_tc(const float* __restrict__ qkv, float* __restrict__ out)
{
    extern __shared__ float sma[];
    float* Qs = sma;                       // [128][132] row-major (q, d)
    float* Ks = Qs + BQA * QS_STR;         // [64][132]  row-major (j, d)
    float* Vs = Ks + BKA * KS_STR;         // [64][136]  row-major (j, d)
    float* Ps = Vs + BKA * VS_STR;         // [128][68]  row-major (q, j)

    const int qblk = (SEQ / BQA - 1) - blockIdx.x;   // heavy blocks first
    const int h  = blockIdx.y;
    const int b  = blockIdx.z;
    const int tid  = threadIdx.x;
    const int lane = tid & 31;
    const int wid  = tid >> 5;          // 0..7
    const int g    = lane >> 2;         // 0..7
    const int tig  = lane & 3;          // 0..3
    const int m0w  = wid * 16;          // warp's first q row (local)

    const size_t rstride = 3 * DMODEL;  // 1536
    const float scale = 0.08838834764831845f;   // 1/sqrt(128)

    // ---- load Q tile [128][128], straight copy ----
    {
        const float* qbase = qkv + ((size_t)b * SEQ + qblk * BQA) * rstride + h * HDIM;
        #pragma unroll
        for (int t = 0; t < 16; t++) {
            int idx = tid + t * 256;        // 0..4095
            int row = idx >> 5, d4 = idx & 31;
            *(float4*)(&Qs[row * QS_STR + d4 * 4]) =
                *(const float4*)(qbase + (size_t)row * rstride + d4 * 4);
        }
    }

    float o[16][4];
    #pragma unroll
    for (int nf = 0; nf < 16; nf++)
        #pragma unroll
        for (int r = 0; r < 4; r++) o[nf][r] = 0.f;
    float m0 = -1e30f, m1 = -1e30f, l0 = 0.f, l1 = 0.f;

    const int ntiles = 2 * qblk + 2;
    for (int kt = 0; kt < ntiles; kt++) {
        const float* kbase = qkv + ((size_t)b * SEQ + kt * BKA) * rstride + h * HDIM + DMODEL;
        const float* vbase = kbase + DMODEL;
        __syncthreads();    // previous tile's consumers done
        #pragma unroll
        for (int t = 0; t < 8; t++) {
            int idx = tid + t * 256;        // 0..2047
            int row = idx >> 5, d4 = idx & 31;
            *(float4*)(&Ks[row * KS_STR + d4 * 4]) =
                *(const float4*)(kbase + (size_t)row * rstride + d4 * 4);
            *(float4*)(&Vs[row * VS_STR + d4 * 4]) =
                *(const float4*)(vbase + (size_t)row * rstride + d4 * 4);
        }
        __syncthreads();

        // ---- S = Q K^T : rows [m0w, m0w+16), cols [0,64) ----
        float s[8][4];
        #pragma unroll
        for (int nf = 0; nf < 8; nf++)
            #pragma unroll
            for (int r = 0; r < 4; r++) s[nf][r] = 0.f;

        #pragma unroll
        for (int kk = 0; kk < 16; kk++) {
            uint32_t a[4];
            const float* q0 = &Qs[(m0w + g)     * QS_STR + kk * 8];
            const float* q1 = &Qs[(m0w + 8 + g) * QS_STR + kk * 8];
            a[0] = __float_as_uint(q0[tig]);
            a[1] = __float_as_uint(q1[tig]);
            a[2] = __float_as_uint(q0[tig + 4]);
            a[3] = __float_as_uint(q1[tig + 4]);
            #pragma unroll
            for (int nf = 0; nf < 8; nf++) {
                uint32_t bb[2];
                const float* kr = &Ks[(nf * 8 + g) * KS_STR + kk * 8];
                bb[0] = __float_as_uint(kr[tig]);
                bb[1] = __float_as_uint(kr[tig + 4]);
                mma_tf32(s[nf], a, bb);
            }
        }

        // ---- causal mask (only the last two tiles of this q block) ----
        if (kt >= 2 * qblk) {
            int qrow0 = qblk * BQA + m0w + g;
            int col0  = kt * BKA;
            #pragma unroll
            for (int nf = 0; nf < 8; nf++) {
                int c0 = col0 + nf * 8 + tig * 2;
                if (c0     > qrow0)     s[nf][0] = -1e30f;
                if (c0 + 1 > qrow0)     s[nf][1] = -1e30f;
                if (c0     > qrow0 + 8) s[nf][2] = -1e30f;
                if (c0 + 1 > qrow0 + 8) s[nf][3] = -1e30f;
            }
        }

        // ---- online softmax (rows g and g+8; reduce over 4 tig lanes) ----
        float rm0 = -1e30f, rm1 = -1e30f;
        #pragma unroll
        for (int nf = 0; nf < 8; nf++) {
            rm0 = fmaxf(rm0, fmaxf(s[nf][0], s[nf][1]));
            rm1 = fmaxf(rm1, fmaxf(s[nf][2], s[nf][3]));
        }
        rm0 = fmaxf(rm0, __shfl_xor_sync(0xffffffffu, rm0, 1));
        rm0 = fmaxf(rm0, __shfl_xor_sync(0xffffffffu, rm0, 2));
        rm1 = fmaxf(rm1, __shfl_xor_sync(0xffffffffu, rm1, 1));
        rm1 = fmaxf(rm1, __shfl_xor_sync(0xffffffffu, rm1, 2));
        float mn0 = fmaxf(m0, rm0);
        float mn1 = fmaxf(m1, rm1);

        float rs0 = 0.f, rs1 = 0.f;
        #pragma unroll
        for (int nf = 0; nf < 8; nf++) {
            float p00 = __expf((s[nf][0] - mn0) * scale);
            float p01 = __expf((s[nf][1] - mn0) * scale);
            float p10 = __expf((s[nf][2] - mn1) * scale);
            float p11 = __expf((s[nf][3] - mn1) * scale);
            rs0 += p00 + p01;
            rs1 += p10 + p11;
            *(float2*)(&Ps[(m0w + g)     * PS_STR + nf * 8 + tig * 2]) = make_float2(p00, p01);
            *(float2*)(&Ps[(m0w + 8 + g) * PS_STR + nf * 8 + tig * 2]) = make_float2(p10, p11);
        }
        rs0 += __shfl_xor_sync(0xffffffffu, rs0, 1);
        rs0 += __shfl_xor_sync(0xffffffffu, rs0, 2);
        rs1 += __shfl_xor_sync(0xffffffffu, rs1, 1);
        rs1 += __shfl_xor_sync(0xffffffffu, rs1, 2);

        float corr0 = __expf((m0 - mn0) * scale);
        float corr1 = __expf((m1 - mn1) * scale);
        l0 = l0 * corr0 + rs0;
        l1 = l1 * corr1 + rs1;
        m0 = mn0; m1 = mn1;
        #pragma unroll
        for (int nf = 0; nf < 16; nf++) {
            o[nf][0] *= corr0; o[nf][1] *= corr0;
            o[nf][2] *= corr1; o[nf][3] *= corr1;
        }
        __syncwarp();    // Ps write -> read (same warp's rows only)

        // ---- O += P V : rows [m0w,m0w+16), dims [0,128) ----
        #pragma unroll
        for (int kk = 0; kk < 8; kk++) {
            uint32_t a[4];
            const float* p0 = &Ps[(m0w + g)     * PS_STR + kk * 8];
            const float* p1 = &Ps[(m0w + 8 + g) * PS_STR + kk * 8];
            a[0] = __float_as_uint(p0[tig]);
            a[1] = __float_as_uint(p1[tig]);
            a[2] = __float_as_uint(p0[tig + 4]);
            a[3] = __float_as_uint(p1[tig + 4]);
            #pragma unroll
            for (int nf = 0; nf < 16; nf++) {
                uint32_t bb[2];
                const float* vr = &Vs[(kk * 8 + tig) * VS_STR + nf * 8 + g];
                bb[0] = __float_as_uint(vr[0]);
                bb[1] = __float_as_uint(Vs[(kk * 8 + tig + 4) * VS_STR + nf * 8 + g]);
                mma_tf32(o[nf], a, bb);
            }
        }
    }

    // ---- write O (divide by l) ----
    float inv0 = 1.f / l0, inv1 = 1.f / l1;
    int row0 = qblk * BQA + m0w + g;
    float* ob0 = out + ((size_t)b * SEQ + row0)     * DMODEL + h * HDIM;
    float* ob1 = out + ((size_t)b * SEQ + row0 + 8) * DMODEL + h * HDIM;
    #pragma unroll
    for (int nf = 0; nf < 16; nf++) {
        *(float2*)(ob0 + nf * 8 + tig * 2) = make_float2(o[nf][0] * inv0, o[nf][1] * inv0);
        *(float2*)(ob1 + nf * 8 + tig * 2) = make_float2(o[nf][2] * inv1, o[nf][3] * inv1);
    }
}

// ---------------------------------------------------------------------------
// Launch
// ---------------------------------------------------------------------------
extern "C" void kernel_launch(void* const* d_in, const int* in_sizes, int n_in,
                              void* d_out, int out_size)
{
    const float* x      = (const float*)d_in[0];
    const float* ln1_g  = (const float*)d_in[1];
    const float* ln1_b  = (const float*)d_in[2];
    const float* w_qkv  = (const float*)d_in[3];
    const float* w_proj = (const float*)d_in[4];
    const float* ln2_g  = (const float*)d_in[5];
    const float* ln2_b  = (const float*)d_in[6];
    const float* w_ff1  = (const float*)d_in[7];
    const float* w_ff2  = (const float*)d_in[8];
    float* out = (float*)d_out;

    float *ln1, *qkv, *attn, *x1, *ln2, *ff1;
    cudaGetSymbolAddress((void**)&ln1,  g_ln1);
    cudaGetSymbolAddress((void**)&qkv,  g_qkv);
    cudaGetSymbolAddress((void**)&attn, g_attn);
    cudaGetSymbolAddress((void**)&x1,   g_x1);
    cudaGetSymbolAddress((void**)&ln2,  g_ln2);
    cudaGetSymbolAddress((void**)&ff1,  g_ff1);

    cudaFuncSetAttribute(gemm_tc<0>, cudaFuncAttributeMaxDynamicSharedMemorySize, GEMM_SMEM);
    cudaFuncSetAttribute(gemm_tc<1>, cudaFuncAttributeMaxDynamicSharedMemorySize, GEMM_SMEM);
    cudaFuncSetAttribute(gemm_tc<2>, cudaFuncAttributeMaxDynamicSharedMemorySize, GEMM_SMEM);
    cudaFuncSetAttribute(attn_tc,    cudaFuncAttributeMaxDynamicSharedMemorySize, ATTN_SMEM);

    dim3 lnBlk(32, 8);

    // 1. ln1 = LN(x)
    ln_kernel<<<MROWS / 8, lnBlk>>>(x, ln1_g, ln1_b, ln1, MROWS);
    // 2. qkv = ln1 @ w_qkv           [8192,1536]
    gemm_tc<0><<<dim3(1536/128, MROWS/128), 128, GEMM_SMEM>>>(ln1, w_qkv, nullptr, qkv,
                                                              MROWS, 3*DMODEL, DMODEL);
    // 3. attn = causal_flash(qkv)    [8192,512]
    attn_tc<<<dim3(SEQ/BQA, NHEADS, BATCH), 256, ATTN_SMEM>>>(qkv, attn);
    // 4. x1 = x + attn @ w_proj
    gemm_tc<2><<<dim3(512/128, MROWS/128), 128, GEMM_SMEM>>>(attn, w_proj, x, x1,
                                                             MROWS, DMODEL, DMODEL);
    // 5. ln2 = LN(x1)
    ln_kernel<<<MROWS / 8, lnBlk>>>(x1, ln2_g, ln2_b, ln2, MROWS);
    // 6. ff1 = gelu(ln2 @ w_ff1)     [8192,2048]
    gemm_tc<1><<<dim3(DFF/128, MROWS/128), 128, GEMM_SMEM>>>(ln2, w_ff1, nullptr, ff1,
                                                             MROWS, DFF, DMODEL);
    // 7. out = x1 + ff1 @ w_ff2
    gemm_tc<2><<<dim3(512/128, MROWS/128), 128, GEMM_SMEM>>>(ff1, w_ff2, x1, out,
                                                             MROWS, DMODEL, DFF);
}

// round 7
// speedup vs baseline: 28.6234x; 1.1909x over previous
#include <cuda_runtime.h>
#include <cuda_fp16.h>
#include <math.h>
#include <stdint.h>

// Problem constants
#define BATCH 4
#define SEQ   2048
#define DMODEL 512
#define NHEADS 4
#define HDIM  128
#define DFF   2048
#define MROWS (BATCH*SEQ)   // 8192

// ---------------------------------------------------------------------------
// Static scratch (no allocation allowed)
// ---------------------------------------------------------------------------
__device__ float  g_qkv [MROWS * 3 * DMODEL];   // fp32 (attention input)
__device__ float  g_x1  [MROWS * DMODEL];       // fp32 residual
__device__ __half g_ln1h [MROWS * DMODEL];
__device__ __half g_attnh[MROWS * DMODEL];
__device__ __half g_ln2h [MROWS * DMODEL];
__device__ __half g_ff1h [MROWS * DFF];
// transposed half weights [N,K]
__device__ __half g_wqkvT[3 * DMODEL * DMODEL];
__device__ __half g_wprojT[DMODEL * DMODEL];
__device__ __half g_wff1T[DFF * DMODEL];
__device__ __half g_wff2T[DMODEL * DFF];

// ---------------------------------------------------------------------------
// PTX helpers
// ---------------------------------------------------------------------------
__device__ __forceinline__ void mma_tf32(float c[4], const uint32_t a[4], const uint32_t b[2]) {
    asm volatile(
        "mma.sync.aligned.m16n8k8.row.col.f32.tf32.tf32.f32 "
        "{%0,%1,%2,%3}, {%4,%5,%6,%7}, {%8,%9}, {%0,%1,%2,%3};"
        : "+f"(c[0]), "+f"(c[1]), "+f"(c[2]), "+f"(c[3])
        : "r"(a[0]), "r"(a[1]), "r"(a[2]), "r"(a[3]), "r"(b[0]), "r"(b[1]));
}

__device__ __forceinline__ void mma_f16(float c[4], const uint32_t a[4], const uint32_t b[2]) {
    asm volatile(
        "mma.sync.aligned.m16n8k16.row.col.f32.f16.f16.f32 "
        "{%0,%1,%2,%3}, {%4,%5,%6,%7}, {%8,%9}, {%0,%1,%2,%3};"
        : "+f"(c[0]), "+f"(c[1]), "+f"(c[2]), "+f"(c[3])
        : "r"(a[0]), "r"(a[1]), "r"(a[2]), "r"(a[3]), "r"(b[0]), "r"(b[1]));
}

__device__ __forceinline__ void cp16(uint32_t smem_addr, const void* gmem) {
    asm volatile("cp.async.cg.shared.global [%0], [%1], 16;" :: "r"(smem_addr), "l"(gmem));
}
__device__ __forceinline__ void cp_commit() { asm volatile("cp.async.commit_group;"); }
template <int N>
__device__ __forceinline__ void cp_wait() { asm volatile("cp.async.wait_group %0;" :: "n"(N)); }
__device__ __forceinline__ uint32_t smem_u32(const void* p) {
    return (uint32_t)__cvta_generic_to_shared(p);
}

// ---------------------------------------------------------------------------
// LayerNorm: one warp per row (D=512), 8 warps per block. Output = half.
// ---------------------------------------------------------------------------
__global__ void ln_kernel_h(const float* __restrict__ x,
                            const float* __restrict__ g,
                            const float* __restrict__ b,
                            __half* __restrict__ out, int rows)
{
    int row  = blockIdx.x * 8 + threadIdx.y;
    int lane = threadIdx.x;
    if (row >= rows) return;

    const float4* xr = (const float4*)(x + (size_t)row * DMODEL);
    float4 v[4];
    float s = 0.f, s2 = 0.f;
    #pragma unroll
    for (int i = 0; i < 4; i++) {
        v[i] = xr[lane + i * 32];
        s  += v[i].x + v[i].y + v[i].z + v[i].w;
        s2 += v[i].x*v[i].x + v[i].y*v[i].y + v[i].z*v[i].z + v[i].w*v[i].w;
    }
    #pragma unroll
    for (int o = 16; o > 0; o >>= 1) {
        s  += __shfl_xor_sync(0xffffffffu, s,  o);
        s2 += __shfl_xor_sync(0xffffffffu, s2, o);
    }
    float mu  = s * (1.f / DMODEL);
    float var = s2 * (1.f / DMODEL) - mu * mu;
    float inv = rsqrtf(var + 1e-5f);

    __half2* orow = (__half2*)(out + (size_t)row * DMODEL);
    const float4* g4 = (const float4*)g;
    const float4* b4 = (const float4*)b;
    #pragma unroll
    for (int i = 0; i < 4; i++) {
        float4 gg = g4[lane + i * 32];
        float4 bb = b4[lane + i * 32];
        float r0 = (v[i].x - mu) * inv * gg.x + bb.x;
        float r1 = (v[i].y - mu) * inv * gg.y + bb.y;
        float r2 = (v[i].z - mu) * inv * gg.z + bb.z;
        float r3 = (v[i].w - mu) * inv * gg.w + bb.w;
        orow[(lane + i * 32) * 2 + 0] = __floats2half2_rn(r0, r1);
        orow[(lane + i * 32) * 2 + 1] = __floats2half2_rn(r2, r3);
    }
}

// ---------------------------------------------------------------------------
// Weight transpose + fp16 convert: BT[n][k] = (half)B[k][n]
// ---------------------------------------------------------------------------
__global__ void transpose_h_kernel(const float* __restrict__ B, __half* __restrict__ BT,
                                   int K, int N)
{
    __shared__ float t[32][33];
    int x  = blockIdx.x * 32 + threadIdx.x;   // n
    int y0 = blockIdx.y * 32;                 // k
    #pragma unroll
    for (int i = 0; i < 4; i++) {
        int y = y0 + threadIdx.y + i * 8;
        t[threadIdx.y + i * 8][threadIdx.x] = B[(size_t)y * N + x];
    }
    __syncthreads();
    int xo  = blockIdx.y * 32 + threadIdx.x;  // k
    int yo0 = blockIdx.x * 32;                // n
    #pragma unroll
    for (int i = 0; i < 4; i++) {
        int yo = yo0 + threadIdx.y + i * 8;
        BT[(size_t)yo * K + xo] = __float2half_rn(t[threadIdx.x][threadIdx.y + i * 8]);
    }
}

// ---------------------------------------------------------------------------
// fp16 tensor-core GEMM (m16n8k16), cp.async double buffer, 1 sync / k-tile.
// Block 128x128x32, 128 threads = 4 warps (2m x 2n), warp tile 64x64.
// A[M,K] half, BT[N,K] half.
// EPI: 0 = none (float out), 1 = exact GELU (half out), 2 = +residual (float out)
// ---------------------------------------------------------------------------
#define HS_STR 40                    // halves per row (32 + 8 pad) -> conflict-free frags
#define HT_ELEMS (128 * HS_STR)      // 5120 halves per tile
#define HSTAGE_BYTES (2 * HT_ELEMS * 2)   // A + B tile = 20480 B
#define GEMMH_SMEM (2 * HSTAGE_BYTES)     // 40960 B

__device__ __forceinline__ void load_stage_h(
    uint32_t dstA, uint32_t dstB,
    const __half* Ab, const __half* BTb, int k0, int K, int tid)
{
    #pragma unroll
    for (int t = 0; t < 4; t++) {
        int idx = tid + t * 128;
        int r = idx >> 2, q = idx & 3;
        cp16(dstA + r * (HS_STR*2) + q * 16, Ab  + (size_t)r * K + k0 + q * 8);
        cp16(dstB + r * (HS_STR*2) + q * 16, BTb + (size_t)r * K + k0 + q * 8);
    }
}

template <int EPI>
__global__ void __launch_bounds__(128, 2)
gemm_h(const __half* __restrict__ A, const __half* __restrict__ BT,
       const float* __restrict__ res, void* __restrict__ Cv,
       int M, int N, int K)
{
    extern __shared__ __half smh[];
    __half* As[2] = { smh,                 smh + 2 * HT_ELEMS };
    __half* Bs[2] = { smh + HT_ELEMS,      smh + 3 * HT_ELEMS };
    const uint32_t aAddr[2] = { smem_u32(As[0]), smem_u32(As[1]) };
    const uint32_t bAddr[2] = { smem_u32(Bs[0]), smem_u32(Bs[1]) };

    const int tid  = threadIdx.x;
    const int lane = tid & 31;
    const int wid  = tid >> 5;
    const int wm   = wid >> 1;     // 0..1
    const int wn   = wid & 1;      // 0..1
    const int g    = lane >> 2;    // 0..7
    const int tig  = lane & 3;     // 0..3

    const int bx = blockIdx.x;
    const int by = blockIdx.y;

    const __half* Ab  = A  + (size_t)(by * 128) * K;
    const __half* BTb = BT + (size_t)(bx * 128) * K;

    float acc[4][8][4];
    #pragma unroll
    for (int mf = 0; mf < 4; mf++)
        #pragma unroll
        for (int nf = 0; nf < 8; nf++)
            #pragma unroll
            for (int r = 0; r < 4; r++) acc[mf][nf][r] = 0.f;

    const int nt = K >> 5;
    load_stage_h(aAddr[0], bAddr[0], Ab, BTb, 0, K, tid);
    cp_commit();

    for (int kt = 0; kt < nt; kt++) {
        const int cur = kt & 1;
        const __half* Asc = As[cur];
        const __half* Bsc = Bs[cur];

        cp_wait<0>();
        __syncthreads();          // stage kt visible; compute kt-1 done

        if (kt + 1 < nt) {
            const int nxt = 1 - cur;
            load_stage_h(aAddr[nxt], bAddr[nxt], Ab, BTb, (kt + 1) * 32, K, tid);
            cp_commit();
        }

        #pragma unroll
        for (int ks = 0; ks < 2; ks++) {      // two k16 steps per 32-chunk
            const int kb = ks * 16;
            uint32_t af[4][4], bf[8][2];
            #pragma unroll
            for (int mf = 0; mf < 4; mf++) {
                int r = wm * 64 + mf * 16 + g;
                const __half* p0 = Asc + r * HS_STR + kb;
                const __half* p1 = Asc + (r + 8) * HS_STR + kb;
                af[mf][0] = *(const uint32_t*)(p0 + 2 * tig);
                af[mf][1] = *(const uint32_t*)(p1 + 2 * tig);
                af[mf][2] = *(const uint32_t*)(p0 + 2 * tig + 8);
                af[mf][3] = *(const uint32_t*)(p1 + 2 * tig + 8);
            }
            #pragma unroll
            for (int nf = 0; nf < 8; nf++) {
                int n = wn * 64 + nf * 8 + g;
                const __half* pb = Bsc + n * HS_STR + kb;
                bf[nf][0] = *(const uint32_t*)(pb + 2 * tig);
                bf[nf][1] = *(const uint32_t*)(pb + 2 * tig + 8);
            }
            #pragma unroll
            for (int mf = 0; mf < 4; mf++)
                #pragma unroll
                for (int nf = 0; nf < 8; nf++)
                    mma_f16(acc[mf][nf], af[mf], bf[nf]);
        }
    }

    // epilogue
    #pragma unroll
    for (int mf = 0; mf < 4; mf++) {
        #pragma unroll
        for (int i2 = 0; i2 < 2; i2++) {
            int row = by * 128 + wm * 64 + mf * 16 + g + i2 * 8;
            #pragma unroll
            for (int nf = 0; nf < 8; nf++) {
                int col = bx * 128 + wn * 64 + nf * 8 + tig * 2;
                float v0 = acc[mf][nf][i2 * 2 + 0];
                float v1 = acc[mf][nf][i2 * 2 + 1];
                size_t off = (size_t)row * N + col;
                if (EPI == 1) {
                    v0 = 0.5f * v0 * (1.f + erff(v0 * 0.70710678118654752f));
                    v1 = 0.5f * v1 * (1.f + erff(v1 * 0.70710678118654752f));
                    *(__half2*)((__half*)Cv + off) = __floats2half2_rn(v0, v1);
                } else if (EPI == 2) {
                    float2 r = *(const float2*)(res + off);
                    *(float2*)((float*)Cv + off) = make_float2(v0 + r.x, v1 + r.y);
                } else {
                    *(float2*)((float*)Cv + off) = make_float2(v0, v1);
                }
            }
        }
    }
}

// ---------------------------------------------------------------------------
// Tensor-core flash attention, tf32 MMA, causal. Output converted to half.
// 256 threads = 8 warps, each warp owns 16 q-rows. BQ=128, BK=64.
// ---------------------------------------------------------------------------
#define BQA 128
#define BKA 64
#define QS_STR 132
#define KS_STR 132
#define VS_STR 136
#define PS_STR 68
#define ATTN_SMEM ((BQA*QS_STR + BKA*KS_STR + BKA*VS_STR + BQA*PS_STR) * 4)

__global__ void __launch_bounds__(256, 1)
attn_tc(const float* __restrict__ qkv, __half* __restrict__ out)
{
    extern __shared__ float sma[];
    float* Qs = sma;
    float* Ks = Qs + BQA * QS_STR;
    float* Vs = Ks + BKA * KS_STR;
    float* Ps = Vs + BKA * VS_STR;

    const int qblk = (SEQ / BQA - 1) - blockIdx.x;
    const int h  = blockIdx.y;
    const int b  = blockIdx.z;
    const int tid  = threadIdx.x;
    const int lane = tid & 31;
    const int wid  = tid >> 5;
    const int g    = lane >> 2;
    const int tig  = lane & 3;
    const int m0w  = wid * 16;

    const size_t rstride = 3 * DMODEL;
    const float scale = 0.08838834764831845f;

    {
        const float* qbase = qkv + ((size_t)b * SEQ + qblk * BQA) * rstride + h * HDIM;
        #pragma unroll
        for (int t = 0; t < 16; t++) {
            int idx = tid + t * 256;
            int row = idx >> 5, d4 = idx & 31;
            *(float4*)(&Qs[row * QS_STR + d4 * 4]) =
                *(const float4*)(qbase + (size_t)row * rstride + d4 * 4);
        }
    }

    float o[16][4];
    #pragma unroll
    for (int nf = 0; nf < 16; nf++)
        #pragma unroll
        for (int r = 0; r < 4; r++) o[nf][r] = 0.f;
    float m0 = -1e30f, m1 = -1e30f, l0 = 0.f, l1 = 0.f;

    const int ntiles = 2 * qblk + 2;
    for (int kt = 0; kt < ntiles; kt++) {
        const float* kbase = qkv + ((size_t)b * SEQ + kt * BKA) * rstride + h * HDIM + DMODEL;
        const float* vbase = kbase + DMODEL;
        __syncthreads();
        #pragma unroll
        for (int t = 0; t < 8; t++) {
            int idx = tid + t * 256;
            int row = idx >> 5, d4 = idx & 31;
            *(float4*)(&Ks[row * KS_STR + d4 * 4]) =
                *(const float4*)(kbase + (size_t)row * rstride + d4 * 4);
            *(float4*)(&Vs[row * VS_STR + d4 * 4]) =
                *(const float4*)(vbase + (size_t)row * rstride + d4 * 4);
        }
        __syncthreads();

        float s[8][4];
        #pragma unroll
        for (int nf = 0; nf < 8; nf++)
            #pragma unroll
            for (int r = 0; r < 4; r++) s[nf][r] = 0.f;

        #pragma unroll
        for (int kk = 0; kk < 16; kk++) {
            uint32_t a[4];
            const float* q0 = &Qs[(m0w + g)     * QS_STR + kk * 8];
            const float* q1 = &Qs[(m0w + 8 + g) * QS_STR + kk * 8];
            a[0] = __float_as_uint(q0[tig]);
            a[1] = __float_as_uint(q1[tig]);
            a[2] = __float_as_uint(q0[tig + 4]);
            a[3] = __float_as_uint(q1[tig + 4]);
            #pragma unroll
            for (int nf = 0; nf < 8; nf++) {
                uint32_t bb[2];
                const float* kr = &Ks[(nf * 8 + g) * KS_STR + kk * 8];
                bb[0] = __float_as_uint(kr[tig]);
                bb[1] = __float_as_uint(kr[tig + 4]);
                mma_tf32(s[nf], a, bb);
            }
        }

        if (kt >= 2 * qblk) {
            int qrow0 = qblk * BQA + m0w + g;
            int col0  = kt * BKA;
            #pragma unroll
            for (int nf = 0; nf < 8; nf++) {
                int c0 = col0 + nf * 8 + tig * 2;
                if (c0     > qrow0)     s[nf][0] = -1e30f;
                if (c0 + 1 > qrow0)     s[nf][1] = -1e30f;
                if (c0     > qrow0 + 8) s[nf][2] = -1e30f;
                if (c0 + 1 > qrow0 + 8) s[nf][3] = -1e30f;
            }
        }

        float rm0 = -1e30f, rm1 = -1e30f;
        #pragma unroll
        for (int nf = 0; nf < 8; nf++) {
            rm0 = fmaxf(rm0, fmaxf(s[nf][0], s[nf][1]));
            rm1 = fmaxf(rm1, fmaxf(s[nf][2], s[nf][3]));
        }
        rm0 = fmaxf(rm0, __shfl_xor_sync(0xffffffffu, rm0, 1));
        rm0 = fmaxf(rm0, __shfl_xor_sync(0xffffffffu, rm0, 2));
        rm1 = fmaxf(rm1, __shfl_xor_sync(0xffffffffu, rm1, 1));
        rm1 = fmaxf(rm1, __shfl_xor_sync(0xffffffffu, rm1, 2));
        float mn0 = fmaxf(m0, rm0);
        float mn1 = fmaxf(m1, rm1);

        float rs0 = 0.f, rs1 = 0.f;
        #pragma unroll
        for (int nf = 0; nf < 8; nf++) {
            float p00 = __expf((s[nf][0] - mn0) * scale);
            float p01 = __expf((s[nf][1] - mn0) * scale);
            float p10 = __expf((s[nf][2] - mn1) * scale);
            float p11 = __expf((s[nf][3] - mn1) * scale);
            rs0 += p00 + p01;
            rs1 += p10 + p11;
            *(float2*)(&Ps[(m0w + g)     * PS_STR + nf * 8 + tig * 2]) = make_float2(p00, p01);
            *(float2*)(&Ps[(m0w + 8 + g) * PS_STR + nf * 8 + tig * 2]) = make_float2(p10, p11);
        }
        rs0 += __shfl_xor_sync(0xffffffffu, rs0, 1);
        rs0 += __shfl_xor_sync(0xffffffffu, rs0, 2);
        rs1 += __shfl_xor_sync(0xffffffffu, rs1, 1);
        rs1 += __shfl_xor_sync(0xffffffffu, rs1, 2);

        float corr0 = __expf((m0 - mn0) * scale);
        float corr1 = __expf((m1 - mn1) * scale);
        l0 = l0 * corr0 + rs0;
        l1 = l1 * corr1 + rs1;
        m0 = mn0; m1 = mn1;
        #pragma unroll
        for (int nf = 0; nf < 16; nf++) {
            o[nf][0] *= corr0; o[nf][1] *= corr0;
            o[nf][2] *= corr1; o[nf][3] *= corr1;
        }
        __syncwarp();

        #pragma unroll
        for (int kk = 0; kk < 8; kk++) {
            uint32_t a[4];
            const float* p0 = &Ps[(m0w + g)     * PS_STR + kk * 8];
            const float* p1 = &Ps[(m0w + 8 + g) * PS_STR + kk * 8];
            a[0] = __float_as_uint(p0[tig]);
            a[1] = __float_as_uint(p1[tig]);
            a[2] = __float_as_uint(p0[tig + 4]);
            a[3] = __float_as_uint(p1[tig + 4]);
            #pragma unroll
            for (int nf = 0; nf < 16; nf++) {
                uint32_t bb[2];
                const float* vr = &Vs[(kk * 8 + tig) * VS_STR + nf * 8 + g];
                bb[0] = __float_as_uint(vr[0]);
                bb[1] = __float_as_uint(Vs[(kk * 8 + tig + 4) * VS_STR + nf * 8 + g]);
                mma_tf32(o[nf], a, bb);
            }
        }
    }

    float inv0 = 1.f / l0, inv1 = 1.f / l1;
    int row0 = qblk * BQA + m0w + g;
    __half* ob0 = out + ((size_t)b * SEQ + row0)     * DMODEL + h * HDIM;
    __half* ob1 = out + ((size_t)b * SEQ + row0 + 8) * DMODEL + h * HDIM;
    #pragma unroll
    for (int nf = 0; nf < 16; nf++) {
        *(__half2*)(ob0 + nf * 8 + tig * 2) = __floats2half2_rn(o[nf][0] * inv0, o[nf][1] * inv0);
        *(__half2*)(ob1 + nf * 8 + tig * 2) = __floats2half2_rn(o[nf][2] * inv1, o[nf][3] * inv1);
    }
}

// ---------------------------------------------------------------------------
// Launch
// ---------------------------------------------------------------------------
extern "C" void kernel_launch(void* const* d_in, const int* in_sizes, int n_in,
                              void* d_out, int out_size)
{
    const float* x      = (const float*)d_in[0];
    const float* ln1_g  = (const float*)d_in[1];
    const float* ln1_b  = (const float*)d_in[2];
    const float* w_qkv  = (const float*)d_in[3];
    const float* w_proj = (const float*)d_in[4];
    const float* ln2_g  = (const float*)d_in[5];
    const float* ln2_b  = (const float*)d_in[6];
    const float* w_ff1  = (const float*)d_in[7];
    const float* w_ff2  = (const float*)d_in[8];
    float* out = (float*)d_out;

    float *qkv, *x1;
    __half *ln1h, *attnh, *ln2h, *ff1h, *wqkvT, *wprojT, *wff1T, *wff2T;
    cudaGetSymbolAddress((void**)&qkv,   g_qkv);
    cudaGetSymbolAddress((void**)&x1,    g_x1);
    cudaGetSymbolAddress((void**)&ln1h,  g_ln1h);
    cudaGetSymbolAddress((void**)&attnh, g_attnh);
    cudaGetSymbolAddress((void**)&ln2h,  g_ln2h);
    cudaGetSymbolAddress((void**)&ff1h,  g_ff1h);
    cudaGetSymbolAddress((void**)&wqkvT, g_wqkvT);
    cudaGetSymbolAddress((void**)&wprojT, g_wprojT);
    cudaGetSymbolAddress((void**)&wff1T, g_wff1T);
    cudaGetSymbolAddress((void**)&wff2T, g_wff2T);

    cudaFuncSetAttribute(gemm_h<0>, cudaFuncAttributeMaxDynamicSharedMemorySize, GEMMH_SMEM);
    cudaFuncSetAttribute(gemm_h<1>, cudaFuncAttributeMaxDynamicSharedMemorySize, GEMMH_SMEM);
    cudaFuncSetAttribute(gemm_h<2>, cudaFuncAttributeMaxDynamicSharedMemorySize, GEMMH_SMEM);
    cudaFuncSetAttribute(attn_tc,   cudaFuncAttributeMaxDynamicSharedMemorySize, ATTN_SMEM);

    dim3 lnBlk(32, 8);
    dim3 tb(32, 8);

    // 0. weight transposes+convert [K,N] -> half [N,K]
    transpose_h_kernel<<<dim3((3*DMODEL)/32, DMODEL/32), tb>>>(w_qkv,  wqkvT,  DMODEL, 3*DMODEL);
    transpose_h_kernel<<<dim3(DMODEL/32, DMODEL/32), tb>>>(w_proj, wprojT, DMODEL, DMODEL);
    transpose_h_kernel<<<dim3(DFF/32, DMODEL/32), tb>>>(w_ff1,  wff1T,  DMODEL, DFF);
    transpose_h_kernel<<<dim3(DMODEL/32, DFF/32), tb>>>(w_ff2,  wff2T,  DFF, DMODEL);

    // 1. ln1 = LN(x) -> half
    ln_kernel_h<<<MROWS / 8, lnBlk>>>(x, ln1_g, ln1_b, ln1h, MROWS);
    // 2. qkv = ln1 @ w_qkv -> fp32
    gemm_h<0><<<dim3(1536/128, MROWS/128), 128, GEMMH_SMEM>>>(ln1h, wqkvT, nullptr, qkv,
                                                              MROWS, 3*DMODEL, DMODEL);
    // 3. attn = causal_flash(qkv) -> half
    attn_tc<<<dim3(SEQ/BQA, NHEADS, BATCH), 256, ATTN_SMEM>>>(qkv, attnh);
    // 4. x1 = x + attn @ w_proj -> fp32
    gemm_h<2><<<dim3(512/128, MROWS/128), 128, GEMMH_SMEM>>>(attnh, wprojT, x, x1,
                                                             MROWS, DMODEL, DMODEL);
    // 5. ln2 = LN(x1) -> half
    ln_kernel_h<<<MROWS / 8, lnBlk>>>(x1, ln2_g, ln2_b, ln2h, MROWS);
    // 6. ff1 = gelu(ln2 @ w_ff1) -> half
    gemm_h<1><<<dim3(DFF/128, MROWS/128), 128, GEMMH_SMEM>>>(ln2h, wff1T, nullptr, ff1h,
                                                             MROWS, DFF, DMODEL);
    // 7. out = x1 + ff1 @ w_ff2 -> fp32
    gemm_h<2><<<dim3(512/128, MROWS/128), 128, GEMMH_SMEM>>>(ff1h, wff2T, x1, out,
                                                             MROWS, DMODEL, DFF);
}

// round 8
// speedup vs baseline: 32.6606x; 1.1410x over previous
#include <cuda_runtime.h>
#include <cuda_fp16.h>
#include <math.h>
#include <stdint.h>

// Problem constants
#define BATCH 4
#define SEQ   2048
#define DMODEL 512
#define NHEADS 4
#define HDIM  128
#define DFF   2048
#define MROWS (BATCH*SEQ)   // 8192

// ---------------------------------------------------------------------------
// Static scratch (no allocation allowed)
// ---------------------------------------------------------------------------
__device__ float  g_x1  [MROWS * DMODEL];       // fp32 residual
__device__ __half g_qkvh [MROWS * 3 * DMODEL];  // half (attention input)
__device__ __half g_ln1h [MROWS * DMODEL];
__device__ __half g_attnh[MROWS * DMODEL];
__device__ __half g_ln2h [MROWS * DMODEL];
__device__ __half g_ff1h [MROWS * DFF];
// transposed half weights [N,K]
__device__ __half g_wqkvT[3 * DMODEL * DMODEL];
__device__ __half g_wprojT[DMODEL * DMODEL];
__device__ __half g_wff1T[DFF * DMODEL];
__device__ __half g_wff2T[DMODEL * DFF];

// ---------------------------------------------------------------------------
// PTX helpers
// ---------------------------------------------------------------------------
__device__ __forceinline__ void mma_f16(float c[4], const uint32_t a[4], const uint32_t b[2]) {
    asm volatile(
        "mma.sync.aligned.m16n8k16.row.col.f32.f16.f16.f32 "
        "{%0,%1,%2,%3}, {%4,%5,%6,%7}, {%8,%9}, {%0,%1,%2,%3};"
        : "+f"(c[0]), "+f"(c[1]), "+f"(c[2]), "+f"(c[3])
        : "r"(a[0]), "r"(a[1]), "r"(a[2]), "r"(a[3]), "r"(b[0]), "r"(b[1]));
}

__device__ __forceinline__ void ldsm_x2_trans(uint32_t& r0, uint32_t& r1, uint32_t addr) {
    asm volatile("ldmatrix.sync.aligned.m8n8.x2.trans.shared.b16 {%0,%1}, [%2];"
                 : "=r"(r0), "=r"(r1) : "r"(addr));
}

__device__ __forceinline__ void cp16(uint32_t smem_addr, const void* gmem) {
    asm volatile("cp.async.cg.shared.global [%0], [%1], 16;" :: "r"(smem_addr), "l"(gmem));
}
__device__ __forceinline__ void cp_commit() { asm volatile("cp.async.commit_group;"); }
template <int N>
__device__ __forceinline__ void cp_wait() { asm volatile("cp.async.wait_group %0;" :: "n"(N)); }
__device__ __forceinline__ uint32_t smem_u32(const void* p) {
    return (uint32_t)__cvta_generic_to_shared(p);
}

// ---------------------------------------------------------------------------
// LayerNorm: one warp per row (D=512), 8 warps per block. Output = half.
// ---------------------------------------------------------------------------
__global__ void ln_kernel_h(const float* __restrict__ x,
                            const float* __restrict__ g,
                            const float* __restrict__ b,
                            __half* __restrict__ out, int rows)
{
    int row  = blockIdx.x * 8 + threadIdx.y;
    int lane = threadIdx.x;
    if (row >= rows) return;

    const float4* xr = (const float4*)(x + (size_t)row * DMODEL);
    float4 v[4];
    float s = 0.f, s2 = 0.f;
    #pragma unroll
    for (int i = 0; i < 4; i++) {
        v[i] = xr[lane + i * 32];
        s  += v[i].x + v[i].y + v[i].z + v[i].w;
        s2 += v[i].x*v[i].x + v[i].y*v[i].y + v[i].z*v[i].z + v[i].w*v[i].w;
    }
    #pragma unroll
    for (int o = 16; o > 0; o >>= 1) {
        s  += __shfl_xor_sync(0xffffffffu, s,  o);
        s2 += __shfl_xor_sync(0xffffffffu, s2, o);
    }
    float mu  = s * (1.f / DMODEL);
    float var = s2 * (1.f / DMODEL) - mu * mu;
    float inv = rsqrtf(var + 1e-5f);

    __half2* orow = (__half2*)(out + (size_t)row * DMODEL);
    const float4* g4 = (const float4*)g;
    const float4* b4 = (const float4*)b;
    #pragma unroll
    for (int i = 0; i < 4; i++) {
        float4 gg = g4[lane + i * 32];
        float4 bb = b4[lane + i * 32];
        float r0 = (v[i].x - mu) * inv * gg.x + bb.x;
        float r1 = (v[i].y - mu) * inv * gg.y + bb.y;
        float r2 = (v[i].z - mu) * inv * gg.z + bb.z;
        float r3 = (v[i].w - mu) * inv * gg.w + bb.w;
        orow[(lane + i * 32) * 2 + 0] = __floats2half2_rn(r0, r1);
        orow[(lane + i * 32) * 2 + 1] = __floats2half2_rn(r2, r3);
    }
}

// ---------------------------------------------------------------------------
// Weight transpose + fp16 convert: BT[n][k] = (half)B[k][n]
// ---------------------------------------------------------------------------
__global__ void transpose_h_kernel(const float* __restrict__ B, __half* __restrict__ BT,
                                   int K, int N)
{
    __shared__ float t[32][33];
    int x  = blockIdx.x * 32 + threadIdx.x;   // n
    int y0 = blockIdx.y * 32;                 // k
    #pragma unroll
    for (int i = 0; i < 4; i++) {
        int y = y0 + threadIdx.y + i * 8;
        t[threadIdx.y + i * 8][threadIdx.x] = B[(size_t)y * N + x];
    }
    __syncthreads();
    int xo  = blockIdx.y * 32 + threadIdx.x;  // k
    int yo0 = blockIdx.x * 32;                // n
    #pragma unroll
    for (int i = 0; i < 4; i++) {
        int yo = yo0 + threadIdx.y + i * 8;
        BT[(size_t)yo * K + xo] = __float2half_rn(t[threadIdx.x][threadIdx.y + i * 8]);
    }
}

// ---------------------------------------------------------------------------
// fp16 tensor-core GEMM (m16n8k16), cp.async double buffer, 1 sync / k-tile.
// Block 128x128x32, 128 threads = 4 warps (2m x 2n), warp tile 64x64.
// EPI: 0 = float out, 1 = GELU half out, 2 = +residual float out, 3 = half out
// ---------------------------------------------------------------------------
#define HS_STR 40
#define HT_ELEMS (128 * HS_STR)
#define HSTAGE_BYTES (2 * HT_ELEMS * 2)
#define GEMMH_SMEM (2 * HSTAGE_BYTES)     // 40960 B

__device__ __forceinline__ void load_stage_h(
    uint32_t dstA, uint32_t dstB,
    const __half* Ab, const __half* BTb, int k0, int K, int tid)
{
    #pragma unroll
    for (int t = 0; t < 4; t++) {
        int idx = tid + t * 128;
        int r = idx >> 2, q = idx & 3;
        cp16(dstA + r * (HS_STR*2) + q * 16, Ab  + (size_t)r * K + k0 + q * 8);
        cp16(dstB + r * (HS_STR*2) + q * 16, BTb + (size_t)r * K + k0 + q * 8);
    }
}

template <int EPI>
__global__ void __launch_bounds__(128, 2)
gemm_h(const __half* __restrict__ A, const __half* __restrict__ BT,
       const float* __restrict__ res, void* __restrict__ Cv,
       int M, int N, int K)
{
    extern __shared__ __half smh[];
    __half* As[2] = { smh,                 smh + 2 * HT_ELEMS };
    __half* Bs[2] = { smh + HT_ELEMS,      smh + 3 * HT_ELEMS };
    const uint32_t aAddr[2] = { smem_u32(As[0]), smem_u32(As[1]) };
    const uint32_t bAddr[2] = { smem_u32(Bs[0]), smem_u32(Bs[1]) };

    const int tid  = threadIdx.x;
    const int lane = tid & 31;
    const int wid  = tid >> 5;
    const int wm   = wid >> 1;
    const int wn   = wid & 1;
    const int g    = lane >> 2;
    const int tig  = lane & 3;

    const int bx = blockIdx.x;
    const int by = blockIdx.y;

    const __half* Ab  = A  + (size_t)(by * 128) * K;
    const __half* BTb = BT + (size_t)(bx * 128) * K;

    float acc[4][8][4];
    #pragma unroll
    for (int mf = 0; mf < 4; mf++)
        #pragma unroll
        for (int nf = 0; nf < 8; nf++)
            #pragma unroll
            for (int r = 0; r < 4; r++) acc[mf][nf][r] = 0.f;

    const int nt = K >> 5;
    load_stage_h(aAddr[0], bAddr[0], Ab, BTb, 0, K, tid);
    cp_commit();

    for (int kt = 0; kt < nt; kt++) {
        const int cur = kt & 1;
        const __half* Asc = As[cur];
        const __half* Bsc = Bs[cur];

        cp_wait<0>();
        __syncthreads();

        if (kt + 1 < nt) {
            const int nxt = 1 - cur;
            load_stage_h(aAddr[nxt], bAddr[nxt], Ab, BTb, (kt + 1) * 32, K, tid);
            cp_commit();
        }

        #pragma unroll
        for (int ks = 0; ks < 2; ks++) {
            const int kb = ks * 16;
            uint32_t af[4][4], bf[8][2];
            #pragma unroll
            for (int mf = 0; mf < 4; mf++) {
                int r = wm * 64 + mf * 16 + g;
                const __half* p0 = Asc + r * HS_STR + kb;
                const __half* p1 = Asc + (r + 8) * HS_STR + kb;
                af[mf][0] = *(const uint32_t*)(p0 + 2 * tig);
                af[mf][1] = *(const uint32_t*)(p1 + 2 * tig);
                af[mf][2] = *(const uint32_t*)(p0 + 2 * tig + 8);
                af[mf][3] = *(const uint32_t*)(p1 + 2 * tig + 8);
            }
            #pragma unroll
            for (int nf = 0; nf < 8; nf++) {
                int n = wn * 64 + nf * 8 + g;
                const __half* pb = Bsc + n * HS_STR + kb;
                bf[nf][0] = *(const uint32_t*)(pb + 2 * tig);
                bf[nf][1] = *(const uint32_t*)(pb + 2 * tig + 8);
            }
            #pragma unroll
            for (int mf = 0; mf < 4; mf++)
                #pragma unroll
                for (int nf = 0; nf < 8; nf++)
                    mma_f16(acc[mf][nf], af[mf], bf[nf]);
        }
    }

    // epilogue
    #pragma unroll
    for (int mf = 0; mf < 4; mf++) {
        #pragma unroll
        for (int i2 = 0; i2 < 2; i2++) {
            int row = by * 128 + wm * 64 + mf * 16 + g + i2 * 8;
            #pragma unroll
            for (int nf = 0; nf < 8; nf++) {
                int col = bx * 128 + wn * 64 + nf * 8 + tig * 2;
                float v0 = acc[mf][nf][i2 * 2 + 0];
                float v1 = acc[mf][nf][i2 * 2 + 1];
                size_t off = (size_t)row * N + col;
                if (EPI == 1) {
                    v0 = 0.5f * v0 * (1.f + erff(v0 * 0.70710678118654752f));
                    v1 = 0.5f * v1 * (1.f + erff(v1 * 0.70710678118654752f));
                    *(__half2*)((__half*)Cv + off) = __floats2half2_rn(v0, v1);
                } else if (EPI == 2) {
                    float2 r = *(const float2*)(res + off);
                    *(float2*)((float*)Cv + off) = make_float2(v0 + r.x, v1 + r.y);
                } else if (EPI == 3) {
                    *(__half2*)((__half*)Cv + off) = __floats2half2_rn(v0, v1);
                } else {
                    *(float2*)((float*)Cv + off) = make_float2(v0, v1);
                }
            }
        }
    }
}

// ---------------------------------------------------------------------------
// fp16 tensor-core flash attention (m16n8k16), causal.
// 256 threads = 8 warps, each warp owns 16 q-rows. BQ=128, BK=64.
// QK: direct pair loads from row-major Ks. PV: ldmatrix.x2.trans on Vs.
// Softmax in fp32 with running (unscaled) max; scale folded into exp.
// ---------------------------------------------------------------------------
#define BQA 128
#define BKA 64
#define QSTR 136   // halves
#define KSTR 136
#define VSTR 136
#define PSTR 72
#define ATTN_SMEM ((BQA*QSTR + BKA*KSTR + BKA*VSTR + BQA*PSTR) * 2)   // 88064 B

__global__ void __launch_bounds__(256, 2)
attn_h(const __half* __restrict__ qkv, __half* __restrict__ out)
{
    extern __shared__ __align__(16) __half smah[];
    __half* Qs = smah;                     // [128][136] (q, d)
    __half* Ks = Qs + BQA * QSTR;          // [64][136]  (j, d)
    __half* Vs = Ks + BKA * KSTR;          // [64][136]  (j, d)
    __half* Ps = Vs + BKA * VSTR;          // [128][72]  (q, j)

    const int qblk = (SEQ / BQA - 1) - blockIdx.x;
    const int h  = blockIdx.y;
    const int b  = blockIdx.z;
    const int tid  = threadIdx.x;
    const int lane = tid & 31;
    const int wid  = tid >> 5;
    const int g    = lane >> 2;
    const int tig  = lane & 3;
    const int m0w  = wid * 16;

    const size_t rstride = 3 * DMODEL;   // halves
    const float scale = 0.08838834764831845f;

    // ---- load Q tile [128][128] halves ----
    {
        const __half* qbase = qkv + ((size_t)b * SEQ + qblk * BQA) * rstride + h * HDIM;
        #pragma unroll
        for (int t = 0; t < 8; t++) {
            int idx = tid + t * 256;       // 0..2047
            int row = idx >> 4, q8 = idx & 15;
            *(float4*)(&Qs[row * QSTR + q8 * 8]) =
                *(const float4*)(qbase + (size_t)row * rstride + q8 * 8);
        }
    }

    float o[16][4];
    #pragma unroll
    for (int nf = 0; nf < 16; nf++)
        #pragma unroll
        for (int r = 0; r < 4; r++) o[nf][r] = 0.f;
    float m0 = -1e30f, m1 = -1e30f, l0 = 0.f, l1 = 0.f;

    // per-lane ldmatrix row base (lanes 0-15 used)
    const int lm_row = lane & 15;

    const int ntiles = 2 * qblk + 2;
    for (int kt = 0; kt < ntiles; kt++) {
        const __half* kbase = qkv + ((size_t)b * SEQ + kt * BKA) * rstride + h * HDIM + DMODEL;
        const __half* vbase = kbase + DMODEL;
        __syncthreads();
        #pragma unroll
        for (int t = 0; t < 4; t++) {
            int idx = tid + t * 256;       // 0..1023
            int row = idx >> 4, q8 = idx & 15;
            *(float4*)(&Ks[row * KSTR + q8 * 8]) =
                *(const float4*)(kbase + (size_t)row * rstride + q8 * 8);
            *(float4*)(&Vs[row * VSTR + q8 * 8]) =
                *(const float4*)(vbase + (size_t)row * rstride + q8 * 8);
        }
        __syncthreads();

        // ---- S = Q K^T : rows [m0w,m0w+16), cols [0,64), fp32 accum ----
        float s[8][4];
        #pragma unroll
        for (int nf = 0; nf < 8; nf++)
            #pragma unroll
            for (int r = 0; r < 4; r++) s[nf][r] = 0.f;

        #pragma unroll
        for (int kb8 = 0; kb8 < 8; kb8++) {
            const int kb = kb8 * 16;
            uint32_t a[4];
            const __half* q0 = &Qs[(m0w + g)     * QSTR + kb];
            const __half* q1 = &Qs[(m0w + 8 + g) * QSTR + kb];
            a[0] = *(const uint32_t*)(q0 + 2 * tig);
            a[1] = *(const uint32_t*)(q1 + 2 * tig);
            a[2] = *(const uint32_t*)(q0 + 2 * tig + 8);
            a[3] = *(const uint32_t*)(q1 + 2 * tig + 8);
            #pragma unroll
            for (int nf = 0; nf < 8; nf++) {
                uint32_t bb[2];
                const __half* kr = &Ks[(nf * 8 + g) * KSTR + kb];
                bb[0] = *(const uint32_t*)(kr + 2 * tig);
                bb[1] = *(const uint32_t*)(kr + 2 * tig + 8);
                mma_f16(s[nf], a, bb);
            }
        }

        // ---- causal mask (last two tiles only) ----
        if (kt >= 2 * qblk) {
            int qrow0 = qblk * BQA + m0w + g;
            int col0  = kt * BKA;
            #pragma unroll
            for (int nf = 0; nf < 8; nf++) {
                int c0 = col0 + nf * 8 + tig * 2;
                if (c0     > qrow0)     s[nf][0] = -1e30f;
                if (c0 + 1 > qrow0)     s[nf][1] = -1e30f;
                if (c0     > qrow0 + 8) s[nf][2] = -1e30f;
                if (c0 + 1 > qrow0 + 8) s[nf][3] = -1e30f;
            }
        }

        // ---- online softmax ----
        float rm0 = -1e30f, rm1 = -1e30f;
        #pragma unroll
        for (int nf = 0; nf < 8; nf++) {
            rm0 = fmaxf(rm0, fmaxf(s[nf][0], s[nf][1]));
            rm1 = fmaxf(rm1, fmaxf(s[nf][2], s[nf][3]));
        }
        rm0 = fmaxf(rm0, __shfl_xor_sync(0xffffffffu, rm0, 1));
        rm0 = fmaxf(rm0, __shfl_xor_sync(0xffffffffu, rm0, 2));
        rm1 = fmaxf(rm1, __shfl_xor_sync(0xffffffffu, rm1, 1));
        rm1 = fmaxf(rm1, __shfl_xor_sync(0xffffffffu, rm1, 2));
        float mn0 = fmaxf(m0, rm0);
        float mn1 = fmaxf(m1, rm1);

        float rs0 = 0.f, rs1 = 0.f;
        #pragma unroll
        for (int nf = 0; nf < 8; nf++) {
            float p00 = __expf((s[nf][0] - mn0) * scale);
            float p01 = __expf((s[nf][1] - mn0) * scale);
            float p10 = __expf((s[nf][2] - mn1) * scale);
            float p11 = __expf((s[nf][3] - mn1) * scale);
            rs0 += p00 + p01;
            rs1 += p10 + p11;
            *(__half2*)(&Ps[(m0w + g)     * PSTR + nf * 8 + tig * 2]) = __floats2half2_rn(p00, p01);
            *(__half2*)(&Ps[(m0w + 8 + g) * PSTR + nf * 8 + tig * 2]) = __floats2half2_rn(p10, p11);
        }
        rs0 += __shfl_xor_sync(0xffffffffu, rs0, 1);
        rs0 += __shfl_xor_sync(0xffffffffu, rs0, 2);
        rs1 += __shfl_xor_sync(0xffffffffu, rs1, 1);
        rs1 += __shfl_xor_sync(0xffffffffu, rs1, 2);

        float corr0 = __expf((m0 - mn0) * scale);
        float corr1 = __expf((m1 - mn1) * scale);
        l0 = l0 * corr0 + rs0;
        l1 = l1 * corr1 + rs1;
        m0 = mn0; m1 = mn1;
        #pragma unroll
        for (int nf = 0; nf < 16; nf++) {
            o[nf][0] *= corr0; o[nf][1] *= corr0;
            o[nf][2] *= corr1; o[nf][3] *= corr1;
        }
        __syncwarp();   // Ps write -> read within warp

        // ---- O += P V : A from Ps, B via ldmatrix.x2.trans on Vs ----
        #pragma unroll
        for (int kc = 0; kc < 4; kc++) {
            const int kb = kc * 16;
            uint32_t a[4];
            const __half* p0 = &Ps[(m0w + g)     * PSTR + kb];
            const __half* p1 = &Ps[(m0w + 8 + g) * PSTR + kb];
            a[0] = *(const uint32_t*)(p0 + 2 * tig);
            a[1] = *(const uint32_t*)(p1 + 2 * tig);
            a[2] = *(const uint32_t*)(p0 + 2 * tig + 8);
            a[3] = *(const uint32_t*)(p1 + 2 * tig + 8);
            const uint32_t vrow = smem_u32(&Vs[(kb + lm_row) * VSTR]);
            #pragma unroll
            for (int nf = 0; nf < 16; nf++) {
                uint32_t b0, b1;
                ldsm_x2_trans(b0, b1, vrow + nf * 16);
                uint32_t bb[2] = { b0, b1 };
                mma_f16(o[nf], a, bb);
            }
        }
    }

    // ---- write O (half, divide by l) ----
    float inv0 = 1.f / l0, inv1 = 1.f / l1;
    int row0 = qblk * BQA + m0w + g;
    __half* ob0 = out + ((size_t)b * SEQ + row0)     * DMODEL + h * HDIM;
    __half* ob1 = out + ((size_t)b * SEQ + row0 + 8) * DMODEL + h * HDIM;
    #pragma unroll
    for (int nf = 0; nf < 16; nf++) {
        *(__half2*)(ob0 + nf * 8 + tig * 2) = __floats2half2_rn(o[nf][0] * inv0, o[nf][1] * inv0);
        *(__half2*)(ob1 + nf * 8 + tig * 2) = __floats2half2_rn(o[nf][2] * inv1, o[nf][3] * inv1);
    }
}

// ---------------------------------------------------------------------------
// Launch
// ---------------------------------------------------------------------------
extern "C" void kernel_launch(void* const* d_in, const int* in_sizes, int n_in,
                              void* d_out, int out_size)
{
    const float* x      = (const float*)d_in[0];
    const float* ln1_g  = (const float*)d_in[1];
    const float* ln1_b  = (const float*)d_in[2];
    const float* w_qkv  = (const float*)d_in[3];
    const float* w_proj = (const float*)d_in[4];
    const float* ln2_g  = (const float*)d_in[5];
    const float* ln2_b  = (const float*)d_in[6];
    const float* w_ff1  = (const float*)d_in[7];
    const float* w_ff2  = (const float*)d_in[8];
    float* out = (float*)d_out;

    float *x1;
    __half *qkvh, *ln1h, *attnh, *ln2h, *ff1h, *wqkvT, *wprojT, *wff1T, *wff2T;
    cudaGetSymbolAddress((void**)&x1,    g_x1);
    cudaGetSymbolAddress((void**)&qkvh,  g_qkvh);
    cudaGetSymbolAddress((void**)&ln1h,  g_ln1h);
    cudaGetSymbolAddress((void**)&attnh, g_attnh);
    cudaGetSymbolAddress((void**)&ln2h,  g_ln2h);
    cudaGetSymbolAddress((void**)&ff1h,  g_ff1h);
    cudaGetSymbolAddress((void**)&wqkvT, g_wqkvT);
    cudaGetSymbolAddress((void**)&wprojT, g_wprojT);
    cudaGetSymbolAddress((void**)&wff1T, g_wff1T);
    cudaGetSymbolAddress((void**)&wff2T, g_wff2T);

    cudaFuncSetAttribute(gemm_h<1>, cudaFuncAttributeMaxDynamicSharedMemorySize, GEMMH_SMEM);
    cudaFuncSetAttribute(gemm_h<2>, cudaFuncAttributeMaxDynamicSharedMemorySize, GEMMH_SMEM);
    cudaFuncSetAttribute(gemm_h<3>, cudaFuncAttributeMaxDynamicSharedMemorySize, GEMMH_SMEM);
    cudaFuncSetAttribute(attn_h,    cudaFuncAttributeMaxDynamicSharedMemorySize, ATTN_SMEM);

    dim3 lnBlk(32, 8);
    dim3 tb(32, 8);

    // 0. weight transposes+convert [K,N] -> half [N,K]
    transpose_h_kernel<<<dim3((3*DMODEL)/32, DMODEL/32), tb>>>(w_qkv,  wqkvT,  DMODEL, 3*DMODEL);
    transpose_h_kernel<<<dim3(DMODEL/32, DMODEL/32), tb>>>(w_proj, wprojT, DMODEL, DMODEL);
    transpose_h_kernel<<<dim3(DFF/32, DMODEL/32), tb>>>(w_ff1,  wff1T,  DMODEL, DFF);
    transpose_h_kernel<<<dim3(DMODEL/32, DFF/32), tb>>>(w_ff2,  wff2T,  DFF, DMODEL);

    // 1. ln1 = LN(x) -> half
    ln_kernel_h<<<MROWS / 8, lnBlk>>>(x, ln1_g, ln1_b, ln1h, MROWS);
    // 2. qkv = ln1 @ w_qkv -> half
    gemm_h<3><<<dim3(1536/128, MROWS/128), 128, GEMMH_SMEM>>>(ln1h, wqkvT, nullptr, qkvh,
                                                              MROWS, 3*DMODEL, DMODEL);
    // 3. attn = causal_flash(qkv) -> half
    attn_h<<<dim3(SEQ/BQA, NHEADS, BATCH), 256, ATTN_SMEM>>>(qkvh, attnh);
    // 4. x1 = x + attn @ w_proj -> fp32
    gemm_h<2><<<dim3(512/128, MROWS/128), 128, GEMMH_SMEM>>>(attnh, wprojT, x, x1,
                                                             MROWS, DMODEL, DMODEL);
    // 5. ln2 = LN(x1) -> half
    ln_kernel_h<<<MROWS / 8, lnBlk>>>(x1, ln2_g, ln2_b, ln2h, MROWS);
    // 6. ff1 = gelu(ln2 @ w_ff1) -> half
    gemm_h<1><<<dim3(DFF/128, MROWS/128), 128, GEMMH_SMEM>>>(ln2h, wff1T, nullptr, ff1h,
                                                             MROWS, DFF, DMODEL);
    // 7. out = x1 + ff1 @ w_ff2 -> fp32
    gemm_h<2><<<dim3(512/128, MROWS/128), 128, GEMMH_SMEM>>>(ff1h, wff2T, x1, out,
                                                             MROWS, DMODEL, DFF);
}

// round 9
// speedup vs baseline: 35.6623x; 1.0919x over previous
#include <cuda_runtime.h>
#include <cuda_fp16.h>
#include <math.h>
#include <stdint.h>

// Problem constants
#define BATCH 4
#define SEQ   2048
#define DMODEL 512
#define NHEADS 4
#define HDIM  128
#define DFF   2048
#define MROWS (BATCH*SEQ)   // 8192

// ---------------------------------------------------------------------------
// Static scratch (no allocation allowed)
// ---------------------------------------------------------------------------
__device__ float  g_x1  [MROWS * DMODEL];       // fp32 residual
__device__ __half g_qkvh [MROWS * 3 * DMODEL];  // half (attention input)
__device__ __half g_ln1h [MROWS * DMODEL];
__device__ __half g_attnh[MROWS * DMODEL];
__device__ __half g_ln2h [MROWS * DMODEL];
__device__ __half g_ff1h [MROWS * DFF];
// transposed half weights [N,K]
__device__ __half g_wqkvT[3 * DMODEL * DMODEL];
__device__ __half g_wprojT[DMODEL * DMODEL];
__device__ __half g_wff1T[DFF * DMODEL];
__device__ __half g_wff2T[DMODEL * DFF];

// ---------------------------------------------------------------------------
// PTX helpers
// ---------------------------------------------------------------------------
__device__ __forceinline__ void mma_f16(float c[4], const uint32_t a[4], const uint32_t b[2]) {
    asm volatile(
        "mma.sync.aligned.m16n8k16.row.col.f32.f16.f16.f32 "
        "{%0,%1,%2,%3}, {%4,%5,%6,%7}, {%8,%9}, {%0,%1,%2,%3};"
        : "+f"(c[0]), "+f"(c[1]), "+f"(c[2]), "+f"(c[3])
        : "r"(a[0]), "r"(a[1]), "r"(a[2]), "r"(a[3]), "r"(b[0]), "r"(b[1]));
}

__device__ __forceinline__ void ldsm_x4(uint32_t& r0, uint32_t& r1, uint32_t& r2, uint32_t& r3,
                                        uint32_t addr) {
    asm volatile("ldmatrix.sync.aligned.m8n8.x4.shared.b16 {%0,%1,%2,%3}, [%4];"
                 : "=r"(r0), "=r"(r1), "=r"(r2), "=r"(r3) : "r"(addr));
}
__device__ __forceinline__ void ldsm_x4_trans(uint32_t& r0, uint32_t& r1, uint32_t& r2, uint32_t& r3,
                                              uint32_t addr) {
    asm volatile("ldmatrix.sync.aligned.m8n8.x4.trans.shared.b16 {%0,%1,%2,%3}, [%4];"
                 : "=r"(r0), "=r"(r1), "=r"(r2), "=r"(r3) : "r"(addr));
}

__device__ __forceinline__ void cp16(uint32_t smem_addr, const void* gmem) {
    asm volatile("cp.async.cg.shared.global [%0], [%1], 16;" :: "r"(smem_addr), "l"(gmem));
}
__device__ __forceinline__ void cp_commit() { asm volatile("cp.async.commit_group;"); }
template <int N>
__device__ __forceinline__ void cp_wait() { asm volatile("cp.async.wait_group %0;" :: "n"(N)); }
__device__ __forceinline__ uint32_t smem_u32(const void* p) {
    return (uint32_t)__cvta_generic_to_shared(p);
}

// ---------------------------------------------------------------------------
// LayerNorm: one warp per row (D=512), 8 warps per block. Output = half.
// ---------------------------------------------------------------------------
__global__ void ln_kernel_h(const float* __restrict__ x,
                            const float* __restrict__ g,
                            const float* __restrict__ b,
                            __half* __restrict__ out, int rows)
{
    int row  = blockIdx.x * 8 + threadIdx.y;
    int lane = threadIdx.x;
    if (row >= rows) return;

    const float4* xr = (const float4*)(x + (size_t)row * DMODEL);
    float4 v[4];
    float s = 0.f, s2 = 0.f;
    #pragma unroll
    for (int i = 0; i < 4; i++) {
        v[i] = xr[lane + i * 32];
        s  += v[i].x + v[i].y + v[i].z + v[i].w;
        s2 += v[i].x*v[i].x + v[i].y*v[i].y + v[i].z*v[i].z + v[i].w*v[i].w;
    }
    #pragma unroll
    for (int o = 16; o > 0; o >>= 1) {
        s  += __shfl_xor_sync(0xffffffffu, s,  o);
        s2 += __shfl_xor_sync(0xffffffffu, s2, o);
    }
    float mu  = s * (1.f / DMODEL);
    float var = s2 * (1.f / DMODEL) - mu * mu;
    float inv = rsqrtf(var + 1e-5f);

    __half2* orow = (__half2*)(out + (size_t)row * DMODEL);
    const float4* g4 = (const float4*)g;
    const float4* b4 = (const float4*)b;
    #pragma unroll
    for (int i = 0; i < 4; i++) {
        float4 gg = g4[lane + i * 32];
        float4 bb = b4[lane + i * 32];
        float r0 = (v[i].x - mu) * inv * gg.x + bb.x;
        float r1 = (v[i].y - mu) * inv * gg.y + bb.y;
        float r2 = (v[i].z - mu) * inv * gg.z + bb.z;
        float r3 = (v[i].w - mu) * inv * gg.w + bb.w;
        orow[(lane + i * 32) * 2 + 0] = __floats2half2_rn(r0, r1);
        orow[(lane + i * 32) * 2 + 1] = __floats2half2_rn(r2, r3);
    }
}

// ---------------------------------------------------------------------------
// Weight transpose + fp16 convert: BT[n][k] = (half)B[k][n]
// ---------------------------------------------------------------------------
__global__ void transpose_h_kernel(const float* __restrict__ B, __half* __restrict__ BT,
                                   int K, int N)
{
    __shared__ float t[32][33];
    int x  = blockIdx.x * 32 + threadIdx.x;   // n
    int y0 = blockIdx.y * 32;                 // k
    #pragma unroll
    for (int i = 0; i < 4; i++) {
        int y = y0 + threadIdx.y + i * 8;
        t[threadIdx.y + i * 8][threadIdx.x] = B[(size_t)y * N + x];
    }
    __syncthreads();
    int xo  = blockIdx.y * 32 + threadIdx.x;  // k
    int yo0 = blockIdx.x * 32;                // n
    #pragma unroll
    for (int i = 0; i < 4; i++) {
        int yo = yo0 + threadIdx.y + i * 8;
        BT[(size_t)yo * K + xo] = __float2half_rn(t[threadIdx.x][threadIdx.y + i * 8]);
    }
}

// ---------------------------------------------------------------------------
// fp16 tensor-core GEMM (m16n8k16), 3-stage cp.async pipeline, ldmatrix frags.
// Block 128x128x32, 128 threads = 4 warps (2m x 2n), warp tile 64x64.
// EPI: 0 = float out, 1 = GELU half out, 2 = +residual float out, 3 = half out
// ---------------------------------------------------------------------------
#define HS_STR 40
#define HT_ELEMS (128 * HS_STR)
#define HSTAGE_ELEMS (2 * HT_ELEMS)
#define GEMMH_SMEM (3 * HSTAGE_ELEMS * 2)   // 61440 B

__device__ __forceinline__ void load_stage_h(
    uint32_t dstA, uint32_t dstB,
    const __half* Ab, const __half* BTb, int k0, int K, int tid)
{
    #pragma unroll
    for (int t = 0; t < 4; t++) {
        int idx = tid + t * 128;
        int r = idx >> 2, q = idx & 3;
        cp16(dstA + r * (HS_STR*2) + q * 16, Ab  + (size_t)r * K + k0 + q * 8);
        cp16(dstB + r * (HS_STR*2) + q * 16, BTb + (size_t)r * K + k0 + q * 8);
    }
}

template <int EPI>
__global__ void __launch_bounds__(128, 2)
gemm_h(const __half* __restrict__ A, const __half* __restrict__ BT,
       const float* __restrict__ res, void* __restrict__ Cv,
       int M, int N, int K)
{
    extern __shared__ __half smh[];
    const uint32_t smb = smem_u32(smh);
    // stage s: A tile at s*HSTAGE, B tile at s*HSTAGE + HT_ELEMS (in halves)
    uint32_t aAddr[3], bAddr[3];
    #pragma unroll
    for (int s = 0; s < 3; s++) {
        aAddr[s] = smb + s * HSTAGE_ELEMS * 2;
        bAddr[s] = aAddr[s] + HT_ELEMS * 2;
    }

    const int tid  = threadIdx.x;
    const int lane = tid & 31;
    const int wid  = tid >> 5;
    const int wm   = wid >> 1;
    const int wn   = wid & 1;

    const int bx = blockIdx.x;
    const int by = blockIdx.y;

    const __half* Ab  = A  + (size_t)(by * 128) * K;
    const __half* BTb = BT + (size_t)(bx * 128) * K;

    float acc[4][8][4];
    #pragma unroll
    for (int mf = 0; mf < 4; mf++)
        #pragma unroll
        for (int nf = 0; nf < 8; nf++)
            #pragma unroll
            for (int r = 0; r < 4; r++) acc[mf][nf][r] = 0.f;

    // ldmatrix lane addressing components (in half-elements)
    const int a_row = (lane & 15);                 // + m0
    const int a_col = (lane >> 4) << 3;            // 0 or 8
    const int b_row = (lane & 7) + ((lane >> 4) << 3);  // + n0
    const int b_col = (lane & 8) ? 8 : 0;

    const int nt = K >> 5;
    load_stage_h(aAddr[0], bAddr[0], Ab, BTb, 0, K, tid);
    cp_commit();
    if (nt > 1) {
        load_stage_h(aAddr[1], bAddr[1], Ab, BTb, 32, K, tid);
        cp_commit();
    }

    for (int kt = 0; kt < nt; kt++) {
        const int cur = kt % 3;
        if (kt + 1 < nt) cp_wait<1>(); else cp_wait<0>();
        __syncthreads();     // stage kt visible; compute kt-1 done everywhere

        if (kt + 2 < nt) {
            const int nxt = (kt + 2) % 3;
            load_stage_h(aAddr[nxt], bAddr[nxt], Ab, BTb, (kt + 2) * 32, K, tid);
            cp_commit();
        }

        const uint32_t Asc = aAddr[cur];
        const uint32_t Bsc = bAddr[cur];

        #pragma unroll
        for (int ks = 0; ks < 2; ks++) {
            const int kb = ks * 16;
            uint32_t af[4][4], bf[8][2];
            #pragma unroll
            for (int mf = 0; mf < 4; mf++) {
                int r = wm * 64 + mf * 16 + a_row;
                ldsm_x4(af[mf][0], af[mf][1], af[mf][2], af[mf][3],
                        Asc + (r * HS_STR + kb + a_col) * 2);
            }
            #pragma unroll
            for (int p = 0; p < 4; p++) {
                int n = wn * 64 + p * 16 + b_row;
                ldsm_x4(bf[2*p][0], bf[2*p][1], bf[2*p+1][0], bf[2*p+1][1],
                        Bsc + (n * HS_STR + kb + b_col) * 2);
            }
            #pragma unroll
            for (int mf = 0; mf < 4; mf++)
                #pragma unroll
                for (int nf = 0; nf < 8; nf++)
                    mma_f16(acc[mf][nf], af[mf], bf[nf]);
        }
    }

    // epilogue
    const int g   = lane >> 2;
    const int tig = lane & 3;
    #pragma unroll
    for (int mf = 0; mf < 4; mf++) {
        #pragma unroll
        for (int i2 = 0; i2 < 2; i2++) {
            int row = by * 128 + wm * 64 + mf * 16 + g + i2 * 8;
            #pragma unroll
            for (int nf = 0; nf < 8; nf++) {
                int col = bx * 128 + wn * 64 + nf * 8 + tig * 2;
                float v0 = acc[mf][nf][i2 * 2 + 0];
                float v1 = acc[mf][nf][i2 * 2 + 1];
                size_t off = (size_t)row * N + col;
                if (EPI == 1) {
                    v0 = 0.5f * v0 * (1.f + erff(v0 * 0.70710678118654752f));
                    v1 = 0.5f * v1 * (1.f + erff(v1 * 0.70710678118654752f));
                    *(__half2*)((__half*)Cv + off) = __floats2half2_rn(v0, v1);
                } else if (EPI == 2) {
                    float2 r = *(const float2*)(res + off);
                    *(float2*)((float*)Cv + off) = make_float2(v0 + r.x, v1 + r.y);
                } else if (EPI == 3) {
                    *(__half2*)((__half*)Cv + off) = __floats2half2_rn(v0, v1);
                } else {
                    *(float2*)((float*)Cv + off) = make_float2(v0, v1);
                }
            }
        }
    }
}

// ---------------------------------------------------------------------------
// fp16 tensor-core flash attention (m16n8k16), causal, ldmatrix everywhere.
// 256 threads = 8 warps, each warp owns 16 q-rows. BQ=128, BK=64.
// ---------------------------------------------------------------------------
#define BQA 128
#define BKA 64
#define QSTR 136   // halves
#define KSTR 136
#define VSTR 136
#define PSTR 72
#define ATTN_SMEM ((BQA*QSTR + BKA*KSTR + BKA*VSTR + BQA*PSTR) * 2)   // 88064 B

__global__ void __launch_bounds__(256, 2)
attn_h(const __half* __restrict__ qkv, __half* __restrict__ out)
{
    extern __shared__ __align__(16) __half smah[];
    __half* Qs = smah;                     // [128][136] (q, d)
    __half* Ks = Qs + BQA * QSTR;          // [64][136]  (j, d)
    __half* Vs = Ks + BKA * KSTR;          // [64][136]  (j, d)
    __half* Ps = Vs + BKA * VSTR;          // [128][72]  (q, j)

    const int qblk = (SEQ / BQA - 1) - blockIdx.x;
    const int h  = blockIdx.y;
    const int b  = blockIdx.z;
    const int tid  = threadIdx.x;
    const int lane = tid & 31;
    const int wid  = tid >> 5;
    const int g    = lane >> 2;
    const int tig  = lane & 3;
    const int m0w  = wid * 16;

    const size_t rstride = 3 * DMODEL;   // halves
    const float scale = 0.08838834764831845f;

    // ldmatrix lane addressing
    const int a_row = (lane & 15);
    const int a_col = (lane >> 4) << 3;
    const int b_row = (lane & 7) + ((lane >> 4) << 3);
    const int b_col = (lane & 8) ? 8 : 0;

    // ---- load Q tile [128][128] halves ----
    {
        const __half* qbase = qkv + ((size_t)b * SEQ + qblk * BQA) * rstride + h * HDIM;
        #pragma unroll
        for (int t = 0; t < 8; t++) {
            int idx = tid + t * 256;
            int row = idx >> 4, q8 = idx & 15;
            *(float4*)(&Qs[row * QSTR + q8 * 8]) =
                *(const float4*)(qbase + (size_t)row * rstride + q8 * 8);
        }
    }

    float o[16][4];
    #pragma unroll
    for (int nf = 0; nf < 16; nf++)
        #pragma unroll
        for (int r = 0; r < 4; r++) o[nf][r] = 0.f;
    float m0 = -1e30f, m1 = -1e30f, l0 = 0.f, l1 = 0.f;

    const int ntiles = 2 * qblk + 2;
    for (int kt = 0; kt < ntiles; kt++) {
        const __half* kbase = qkv + ((size_t)b * SEQ + kt * BKA) * rstride + h * HDIM + DMODEL;
        const __half* vbase = kbase + DMODEL;
        __syncthreads();
        #pragma unroll
        for (int t = 0; t < 4; t++) {
            int idx = tid + t * 256;
            int row = idx >> 4, q8 = idx & 15;
            *(float4*)(&Ks[row * KSTR + q8 * 8]) =
                *(const float4*)(kbase + (size_t)row * rstride + q8 * 8);
            *(float4*)(&Vs[row * VSTR + q8 * 8]) =
                *(const float4*)(vbase + (size_t)row * rstride + q8 * 8);
        }
        __syncthreads();

        // ---- S = Q K^T : rows [m0w,m0w+16), cols [0,64) ----
        float s[8][4];
        #pragma unroll
        for (int nf = 0; nf < 8; nf++)
            #pragma unroll
            for (int r = 0; r < 4; r++) s[nf][r] = 0.f;

        #pragma unroll
        for (int kb8 = 0; kb8 < 8; kb8++) {
            const int kb = kb8 * 16;
            uint32_t a[4];
            ldsm_x4(a[0], a[1], a[2], a[3],
                    smem_u32(&Qs[(m0w + a_row) * QSTR + kb + a_col]));
            uint32_t bf[8][2];
            #pragma unroll
            for (int p = 0; p < 4; p++) {
                int n = p * 16 + b_row;
                ldsm_x4(bf[2*p][0], bf[2*p][1], bf[2*p+1][0], bf[2*p+1][1],
                        smem_u32(&Ks[n * KSTR + kb + b_col]));
            }
            #pragma unroll
            for (int nf = 0; nf < 8; nf++)
                mma_f16(s[nf], a, bf[nf]);
        }

        // ---- causal mask (last two tiles only) ----
        if (kt >= 2 * qblk) {
            int qrow0 = qblk * BQA + m0w + g;
            int col0  = kt * BKA;
            #pragma unroll
            for (int nf = 0; nf < 8; nf++) {
                int c0 = col0 + nf * 8 + tig * 2;
                if (c0     > qrow0)     s[nf][0] = -1e30f;
                if (c0 + 1 > qrow0)     s[nf][1] = -1e30f;
                if (c0     > qrow0 + 8) s[nf][2] = -1e30f;
                if (c0 + 1 > qrow0 + 8) s[nf][3] = -1e30f;
            }
        }

        // ---- online softmax ----
        float rm0 = -1e30f, rm1 = -1e30f;
        #pragma unroll
        for (int nf = 0; nf < 8; nf++) {
            rm0 = fmaxf(rm0, fmaxf(s[nf][0], s[nf][1]));
            rm1 = fmaxf(rm1, fmaxf(s[nf][2], s[nf][3]));
        }
        rm0 = fmaxf(rm0, __shfl_xor_sync(0xffffffffu, rm0, 1));
        rm0 = fmaxf(rm0, __shfl_xor_sync(0xffffffffu, rm0, 2));
        rm1 = fmaxf(rm1, __shfl_xor_sync(0xffffffffu, rm1, 1));
        rm1 = fmaxf(rm1, __shfl_xor_sync(0xffffffffu, rm1, 2));
        float mn0 = fmaxf(m0, rm0);
        float mn1 = fmaxf(m1, rm1);

        float rs0 = 0.f, rs1 = 0.f;
        #pragma unroll
        for (int nf = 0; nf < 8; nf++) {
            float p00 = __expf((s[nf][0] - mn0) * scale);
            float p01 = __expf((s[nf][1] - mn0) * scale);
            float p10 = __expf((s[nf][2] - mn1) * scale);
            float p11 = __expf((s[nf][3] - mn1) * scale);
            rs0 += p00 + p01;
            rs1 += p10 + p11;
            *(__half2*)(&Ps[(m0w + g)     * PSTR + nf * 8 + tig * 2]) = __floats2half2_rn(p00, p01);
            *(__half2*)(&Ps[(m0w + 8 + g) * PSTR + nf * 8 + tig * 2]) = __floats2half2_rn(p10, p11);
        }
        rs0 += __shfl_xor_sync(0xffffffffu, rs0, 1);
        rs0 += __shfl_xor_sync(0xffffffffu, rs0, 2);
        rs1 += __shfl_xor_sync(0xffffffffu, rs1, 1);
        rs1 += __shfl_xor_sync(0xffffffffu, rs1, 2);

        float corr0 = __expf((m0 - mn0) * scale);
        float corr1 = __expf((m1 - mn1) * scale);
        l0 = l0 * corr0 + rs0;
        l1 = l1 * corr1 + rs1;
        m0 = mn0; m1 = mn1;
        #pragma unroll
        for (int nf = 0; nf < 16; nf++) {
            o[nf][0] *= corr0; o[nf][1] *= corr0;
            o[nf][2] *= corr1; o[nf][3] *= corr1;
        }
        __syncwarp();   // Ps write -> read within warp

        // ---- O += P V : A from Ps (ldmatrix.x4), B from Vs (ldmatrix.x4.trans) ----
        #pragma unroll
        for (int kc = 0; kc < 4; kc++) {
            const int kb = kc * 16;
            uint32_t a[4];
            ldsm_x4(a[0], a[1], a[2], a[3],
                    smem_u32(&Ps[(m0w + a_row) * PSTR + kb + a_col]));
            #pragma unroll
            for (int np = 0; np < 8; np++) {
                uint32_t b0, b1, b2, b3;
                ldsm_x4_trans(b0, b1, b2, b3,
                              smem_u32(&Vs[(kb + a_row) * VSTR + np * 16 + a_col]));
                uint32_t bb0[2] = { b0, b1 };
                uint32_t bb1[2] = { b2, b3 };
                mma_f16(o[2*np],   a, bb0);
                mma_f16(o[2*np+1], a, bb1);
            }
        }
    }

    // ---- write O (half, divide by l) ----
    float inv0 = 1.f / l0, inv1 = 1.f / l1;
    int row0 = qblk * BQA + m0w + g;
    __half* ob0 = out + ((size_t)b * SEQ + row0)     * DMODEL + h * HDIM;
    __half* ob1 = out + ((size_t)b * SEQ + row0 + 8) * DMODEL + h * HDIM;
    #pragma unroll
    for (int nf = 0; nf < 16; nf++) {
        *(__half2*)(ob0 + nf * 8 + tig * 2) = __floats2half2_rn(o[nf][0] * inv0, o[nf][1] * inv0);
        *(__half2*)(ob1 + nf * 8 + tig * 2) = __floats2half2_rn(o[nf][2] * inv1, o[nf][3] * inv1);
    }
}

// ---------------------------------------------------------------------------
// Launch
// ---------------------------------------------------------------------------
extern "C" void kernel_launch(void* const* d_in, const int* in_sizes, int n_in,
                              void* d_out, int out_size)
{
    const float* x      = (const float*)d_in[0];
    const float* ln1_g  = (const float*)d_in[1];
    const float* ln1_b  = (const float*)d_in[2];
    const float* w_qkv  = (const float*)d_in[3];
    const float* w_proj = (const float*)d_in[4];
    const float* ln2_g  = (const float*)d_in[5];
    const float* ln2_b  = (const float*)d_in[6];
    const float* w_ff1  = (const float*)d_in[7];
    const float* w_ff2  = (const float*)d_in[8];
    float* out = (float*)d_out;

    float *x1;
    __half *qkvh, *ln1h, *attnh, *ln2h, *ff1h, *wqkvT, *wprojT, *wff1T, *wff2T;
    cudaGetSymbolAddress((void**)&x1,    g_x1);
    cudaGetSymbolAddress((void**)&qkvh,  g_qkvh);
    cudaGetSymbolAddress((void**)&ln1h,  g_ln1h);
    cudaGetSymbolAddress((void**)&attnh, g_attnh);
    cudaGetSymbolAddress((void**)&ln2h,  g_ln2h);
    cudaGetSymbolAddress((void**)&ff1h,  g_ff1h);
    cudaGetSymbolAddress((void**)&wqkvT, g_wqkvT);
    cudaGetSymbolAddress((void**)&wprojT, g_wprojT);
    cudaGetSymbolAddress((void**)&wff1T, g_wff1T);
    cudaGetSymbolAddress((void**)&wff2T, g_wff2T);

    cudaFuncSetAttribute(gemm_h<1>, cudaFuncAttributeMaxDynamicSharedMemorySize, GEMMH_SMEM);
    cudaFuncSetAttribute(gemm_h<2>, cudaFuncAttributeMaxDynamicSharedMemorySize, GEMMH_SMEM);
    cudaFuncSetAttribute(gemm_h<3>, cudaFuncAttributeMaxDynamicSharedMemorySize, GEMMH_SMEM);
    cudaFuncSetAttribute(attn_h,    cudaFuncAttributeMaxDynamicSharedMemorySize, ATTN_SMEM);

    dim3 lnBlk(32, 8);
    dim3 tb(32, 8);

    // 0. weight transposes+convert [K,N] -> half [N,K]
    transpose_h_kernel<<<dim3((3*DMODEL)/32, DMODEL/32), tb>>>(w_qkv,  wqkvT,  DMODEL, 3*DMODEL);
    transpose_h_kernel<<<dim3(DMODEL/32, DMODEL/32), tb>>>(w_proj, wprojT, DMODEL, DMODEL);
    transpose_h_kernel<<<dim3(DFF/32, DMODEL/32), tb>>>(w_ff1,  wff1T,  DMODEL, DFF);
    transpose_h_kernel<<<dim3(DMODEL/32, DFF/32), tb>>>(w_ff2,  wff2T,  DFF, DMODEL);

    // 1. ln1 = LN(x) -> half
    ln_kernel_h<<<MROWS / 8, lnBlk>>>(x, ln1_g, ln1_b, ln1h, MROWS);
    // 2. qkv = ln1 @ w_qkv -> half
    gemm_h<3><<<dim3(1536/128, MROWS/128), 128, GEMMH_SMEM>>>(ln1h, wqkvT, nullptr, qkvh,
                                                              MROWS, 3*DMODEL, DMODEL);
    // 3. attn = causal_flash(qkv) -> half
    attn_h<<<dim3(SEQ/BQA, NHEADS, BATCH), 256, ATTN_SMEM>>>(qkvh, attnh);
    // 4. x1 = x + attn @ w_proj -> fp32
    gemm_h<2><<<dim3(512/128, MROWS/128), 128, GEMMH_SMEM>>>(attnh, wprojT, x, x1,
                                                             MROWS, DMODEL, DMODEL);
    // 5. ln2 = LN(x1) -> half
    ln_kernel_h<<<MROWS / 8, lnBlk>>>(x1, ln2_g, ln2_b, ln2h, MROWS);
    // 6. ff1 = gelu(ln2 @ w_ff1) -> half
    gemm_h<1><<<dim3(DFF/128, MROWS/128), 128, GEMMH_SMEM>>>(ln2h, wff1T, nullptr, ff1h,
                                                             MROWS, DFF, DMODEL);
    // 7. out = x1 + ff1 @ w_ff2 -> fp32
    gemm_h<2><<<dim3(512/128, MROWS/128), 128, GEMMH_SMEM>>>(ff1h, wff2T, x1, out,
                                                             MROWS, DMODEL, DFF);
}

// round 10
// speedup vs baseline: 36.0786x; 1.0117x over previous
#include <cuda_runtime.h>
#include <cuda_fp16.h>
#include <math.h>
#include <stdint.h>

// Problem constants
#define BATCH 4
#define SEQ   2048
#define DMODEL 512
#define NHEADS 4
#define HDIM  128
#define DFF   2048
#define MROWS (BATCH*SEQ)   // 8192

// ---------------------------------------------------------------------------
// Static scratch (no allocation allowed)
// ---------------------------------------------------------------------------
__device__ float  g_x1  [MROWS * DMODEL];       // fp32 residual
__device__ __half g_qkvh [MROWS * 3 * DMODEL];  // half (attention input)
__device__ __half g_ln1h [MROWS * DMODEL];
__device__ __half g_attnh[MROWS * DMODEL];
__device__ __half g_ln2h [MROWS * DMODEL];
__device__ __half g_ff1h [MROWS * DFF];
// transposed half weights [N,K]
__device__ __half g_wqkvT[3 * DMODEL * DMODEL];
__device__ __half g_wprojT[DMODEL * DMODEL];
__device__ __half g_wff1T[DFF * DMODEL];
__device__ __half g_wff2T[DMODEL * DFF];

// ---------------------------------------------------------------------------
// PTX helpers
// ---------------------------------------------------------------------------
__device__ __forceinline__ void mma_f16(float c[4], const uint32_t a[4], const uint32_t b[2]) {
    asm volatile(
        "mma.sync.aligned.m16n8k16.row.col.f32.f16.f16.f32 "
        "{%0,%1,%2,%3}, {%4,%5,%6,%7}, {%8,%9}, {%0,%1,%2,%3};"
        : "+f"(c[0]), "+f"(c[1]), "+f"(c[2]), "+f"(c[3])
        : "r"(a[0]), "r"(a[1]), "r"(a[2]), "r"(a[3]), "r"(b[0]), "r"(b[1]));
}

__device__ __forceinline__ void ldsm_x4(uint32_t& r0, uint32_t& r1, uint32_t& r2, uint32_t& r3,
                                        uint32_t addr) {
    asm volatile("ldmatrix.sync.aligned.m8n8.x4.shared.b16 {%0,%1,%2,%3}, [%4];"
                 : "=r"(r0), "=r"(r1), "=r"(r2), "=r"(r3) : "r"(addr));
}
__device__ __forceinline__ void ldsm_x4_trans(uint32_t& r0, uint32_t& r1, uint32_t& r2, uint32_t& r3,
                                              uint32_t addr) {
    asm volatile("ldmatrix.sync.aligned.m8n8.x4.trans.shared.b16 {%0,%1,%2,%3}, [%4];"
                 : "=r"(r0), "=r"(r1), "=r"(r2), "=r"(r3) : "r"(addr));
}

__device__ __forceinline__ void cp16(uint32_t smem_addr, const void* gmem) {
    asm volatile("cp.async.cg.shared.global [%0], [%1], 16;" :: "r"(smem_addr), "l"(gmem));
}
__device__ __forceinline__ void cp_commit() { asm volatile("cp.async.commit_group;"); }
template <int N>
__device__ __forceinline__ void cp_wait() { asm volatile("cp.async.wait_group %0;" :: "n"(N)); }
__device__ __forceinline__ uint32_t smem_u32(const void* p) {
    return (uint32_t)__cvta_generic_to_shared(p);
}

// ---------------------------------------------------------------------------
// LayerNorm: one warp per row (D=512), 8 warps per block. Output = half.
// ---------------------------------------------------------------------------
__global__ void ln_kernel_h(const float* __restrict__ x,
                            const float* __restrict__ g,
                            const float* __restrict__ b,
                            __half* __restrict__ out, int rows)
{
    int row  = blockIdx.x * 8 + threadIdx.y;
    int lane = threadIdx.x;
    if (row >= rows) return;

    const float4* xr = (const float4*)(x + (size_t)row * DMODEL);
    float4 v[4];
    float s = 0.f, s2 = 0.f;
    #pragma unroll
    for (int i = 0; i < 4; i++) {
        v[i] = xr[lane + i * 32];
        s  += v[i].x + v[i].y + v[i].z + v[i].w;
        s2 += v[i].x*v[i].x + v[i].y*v[i].y + v[i].z*v[i].z + v[i].w*v[i].w;
    }
    #pragma unroll
    for (int o = 16; o > 0; o >>= 1) {
        s  += __shfl_xor_sync(0xffffffffu, s,  o);
        s2 += __shfl_xor_sync(0xffffffffu, s2, o);
    }
    float mu  = s * (1.f / DMODEL);
    float var = s2 * (1.f / DMODEL) - mu * mu;
    float inv = rsqrtf(var + 1e-5f);

    __half2* orow = (__half2*)(out + (size_t)row * DMODEL);
    const float4* g4 = (const float4*)g;
    const float4* b4 = (const float4*)b;
    #pragma unroll
    for (int i = 0; i < 4; i++) {
        float4 gg = g4[lane + i * 32];
        float4 bb = b4[lane + i * 32];
        float r0 = (v[i].x - mu) * inv * gg.x + bb.x;
        float r1 = (v[i].y - mu) * inv * gg.y + bb.y;
        float r2 = (v[i].z - mu) * inv * gg.z + bb.z;
        float r3 = (v[i].w - mu) * inv * gg.w + bb.w;
        orow[(lane + i * 32) * 2 + 0] = __floats2half2_rn(r0, r1);
        orow[(lane + i * 32) * 2 + 1] = __floats2half2_rn(r2, r3);
    }
}

// ---------------------------------------------------------------------------
// Fused weight transposes + fp16 convert: BT[n][k] = (half)B[k][n] for all 4.
// Linearized 32x32 tiles: qkv 48x16, proj 16x16, ff1 64x16, ff2 16x64.
// ---------------------------------------------------------------------------
__global__ void transpose_all(const float* __restrict__ w_qkv, const float* __restrict__ w_proj,
                              const float* __restrict__ w_ff1, const float* __restrict__ w_ff2,
                              __half* __restrict__ qkvT, __half* __restrict__ projT,
                              __half* __restrict__ ff1T, __half* __restrict__ ff2T)
{
    __shared__ float t[32][33];
    int bid = blockIdx.x;
    const float* B; __half* BT; int K, N, bx, by;
    if (bid < 768)        { B = w_qkv;  BT = qkvT;  K = DMODEL; N = 3*DMODEL; bid -= 0;    bx = bid % 48; by = bid / 48; }
    else if (bid < 1024)  { B = w_proj; BT = projT; K = DMODEL; N = DMODEL;   bid -= 768;  bx = bid % 16; by = bid / 16; }
    else if (bid < 2048)  { B = w_ff1;  BT = ff1T;  K = DMODEL; N = DFF;      bid -= 1024; bx = bid % 64; by = bid / 64; }
    else                  { B = w_ff2;  BT = ff2T;  K = DFF;    N = DMODEL;   bid -= 2048; bx = bid % 16; by = bid / 16; }

    int x  = bx * 32 + threadIdx.x;   // n
    int y0 = by * 32;                 // k
    #pragma unroll
    for (int i = 0; i < 4; i++) {
        int y = y0 + threadIdx.y + i * 8;
        t[threadIdx.y + i * 8][threadIdx.x] = B[(size_t)y * N + x];
    }
    __syncthreads();
    int xo  = by * 32 + threadIdx.x;  // k
    int yo0 = bx * 32;                // n
    #pragma unroll
    for (int i = 0; i < 4; i++) {
        int yo = yo0 + threadIdx.y + i * 8;
        BT[(size_t)yo * K + xo] = __float2half_rn(t[threadIdx.x][threadIdx.y + i * 8]);
    }
}

// ---------------------------------------------------------------------------
// fp16 tensor-core GEMM (m16n8k16), 3-stage cp.async pipeline, ldmatrix frags.
// Block 128x128x32, 256 threads = 8 warps (4m x 2n), warp tile 32x64.
// EPI: 0 = float out, 1 = GELU half out, 2 = +residual float out, 3 = half out
// ---------------------------------------------------------------------------
#define HS_STR 40
#define HT_ELEMS (128 * HS_STR)
#define HSTAGE_ELEMS (2 * HT_ELEMS)
#define GEMMH_SMEM (3 * HSTAGE_ELEMS * 2)   // 61440 B

__device__ __forceinline__ void load_stage_h(
    uint32_t dstA, uint32_t dstB,
    const __half* Ab, const __half* BTb, int k0, int K, int tid)
{
    #pragma unroll
    for (int t = 0; t < 2; t++) {
        int idx = tid + t * 256;
        int r = idx >> 2, q = idx & 3;
        cp16(dstA + r * (HS_STR*2) + q * 16, Ab  + (size_t)r * K + k0 + q * 8);
        cp16(dstB + r * (HS_STR*2) + q * 16, BTb + (size_t)r * K + k0 + q * 8);
    }
}

template <int EPI>
__global__ void __launch_bounds__(256, 2)
gemm_h(const __half* __restrict__ A, const __half* __restrict__ BT,
       const float* __restrict__ res, void* __restrict__ Cv,
       int M, int N, int K)
{
    extern __shared__ __half smh[];
    const uint32_t smb = smem_u32(smh);
    uint32_t aAddr[3], bAddr[3];
    #pragma unroll
    for (int s = 0; s < 3; s++) {
        aAddr[s] = smb + s * HSTAGE_ELEMS * 2;
        bAddr[s] = aAddr[s] + HT_ELEMS * 2;
    }

    const int tid  = threadIdx.x;
    const int lane = tid & 31;
    const int wid  = tid >> 5;
    const int wm   = wid >> 1;     // 0..3 (m, x32)
    const int wn   = wid & 1;      // 0..1 (n, x64)

    const int bx = blockIdx.x;
    const int by = blockIdx.y;

    const __half* Ab  = A  + (size_t)(by * 128) * K;
    const __half* BTb = BT + (size_t)(bx * 128) * K;

    float acc[2][8][4];
    #pragma unroll
    for (int mf = 0; mf < 2; mf++)
        #pragma unroll
        for (int nf = 0; nf < 8; nf++)
            #pragma unroll
            for (int r = 0; r < 4; r++) acc[mf][nf][r] = 0.f;

    // ldmatrix lane addressing components (half-elements)
    const int a_row = (lane & 15);
    const int a_col = (lane >> 4) << 3;
    const int b_row = (lane & 7) + ((lane >> 4) << 3);
    const int b_col = (lane & 8) ? 8 : 0;

    const int nt = K >> 5;
    load_stage_h(aAddr[0], bAddr[0], Ab, BTb, 0, K, tid);
    cp_commit();
    if (nt > 1) {
        load_stage_h(aAddr[1], bAddr[1], Ab, BTb, 32, K, tid);
        cp_commit();
    }

    for (int kt = 0; kt < nt; kt++) {
        const int cur = kt % 3;
        if (kt + 1 < nt) cp_wait<1>(); else cp_wait<0>();
        __syncthreads();

        if (kt + 2 < nt) {
            const int nxt = (kt + 2) % 3;
            load_stage_h(aAddr[nxt], bAddr[nxt], Ab, BTb, (kt + 2) * 32, K, tid);
            cp_commit();
        }

        const uint32_t Asc = aAddr[cur];
        const uint32_t Bsc = bAddr[cur];

        #pragma unroll
        for (int ks = 0; ks < 2; ks++) {
            const int kb = ks * 16;
            uint32_t af[2][4], bf[8][2];
            #pragma unroll
            for (int mf = 0; mf < 2; mf++) {
                int r = wm * 32 + mf * 16 + a_row;
                ldsm_x4(af[mf][0], af[mf][1], af[mf][2], af[mf][3],
                        Asc + (r * HS_STR + kb + a_col) * 2);
            }
            #pragma unroll
            for (int p = 0; p < 4; p++) {
                int n = wn * 64 + p * 16 + b_row;
                ldsm_x4(bf[2*p][0], bf[2*p][1], bf[2*p+1][0], bf[2*p+1][1],
                        Bsc + (n * HS_STR + kb + b_col) * 2);
            }
            #pragma unroll
            for (int mf = 0; mf < 2; mf++)
                #pragma unroll
                for (int nf = 0; nf < 8; nf++)
                    mma_f16(acc[mf][nf], af[mf], bf[nf]);
        }
    }

    // epilogue
    const int g   = lane >> 2;
    const int tig = lane & 3;
    #pragma unroll
    for (int mf = 0; mf < 2; mf++) {
        #pragma unroll
        for (int i2 = 0; i2 < 2; i2++) {
            int row = by * 128 + wm * 32 + mf * 16 + g + i2 * 8;
            #pragma unroll
            for (int nf = 0; nf < 8; nf++) {
                int col = bx * 128 + wn * 64 + nf * 8 + tig * 2;
                float v0 = acc[mf][nf][i2 * 2 + 0];
                float v1 = acc[mf][nf][i2 * 2 + 1];
                size_t off = (size_t)row * N + col;
                if (EPI == 1) {
                    v0 = 0.5f * v0 * (1.f + erff(v0 * 0.70710678118654752f));
                    v1 = 0.5f * v1 * (1.f + erff(v1 * 0.70710678118654752f));
                    *(__half2*)((__half*)Cv + off) = __floats2half2_rn(v0, v1);
                } else if (EPI == 2) {
                    float2 r = *(const float2*)(res + off);
                    *(float2*)((float*)Cv + off) = make_float2(v0 + r.x, v1 + r.y);
                } else if (EPI == 3) {
                    *(__half2*)((__half*)Cv + off) = __floats2half2_rn(v0, v1);
                } else {
                    *(float2*)((float*)Cv + off) = make_float2(v0, v1);
                }
            }
        }
    }
}

// ---------------------------------------------------------------------------
// fp16 tensor-core flash attention (m16n8k16), causal, ldmatrix everywhere.
// 256 threads = 8 warps, each warp owns 16 q-rows. BQ=128, BK=64.
// K/V tile loads via cp.async.
// ---------------------------------------------------------------------------
#define BQA 128
#define BKA 64
#define QSTR 136   // halves
#define KSTR 136
#define VSTR 136
#define PSTR 72
#define ATTN_SMEM ((BQA*QSTR + BKA*KSTR + BKA*VSTR + BQA*PSTR) * 2)   // 88064 B

__global__ void __launch_bounds__(256, 2)
attn_h(const __half* __restrict__ qkv, __half* __restrict__ out)
{
    extern __shared__ __align__(16) __half smah[];
    __half* Qs = smah;                     // [128][136] (q, d)
    __half* Ks = Qs + BQA * QSTR;          // [64][136]  (j, d)
    __half* Vs = Ks + BKA * KSTR;          // [64][136]  (j, d)
    __half* Ps = Vs + BKA * VSTR;          // [128][72]  (q, j)
    const uint32_t ksAddr = smem_u32(Ks);
    const uint32_t vsAddr = smem_u32(Vs);

    const int qblk = (SEQ / BQA - 1) - blockIdx.x;
    const int h  = blockIdx.y;
    const int b  = blockIdx.z;
    const int tid  = threadIdx.x;
    const int lane = tid & 31;
    const int wid  = tid >> 5;
    const int g    = lane >> 2;
    const int tig  = lane & 3;
    const int m0w  = wid * 16;

    const size_t rstride = 3 * DMODEL;   // halves
    const float scale = 0.08838834764831845f;

    // ldmatrix lane addressing
    const int a_row = (lane & 15);
    const int a_col = (lane >> 4) << 3;
    const int b_row = (lane & 7) + ((lane >> 4) << 3);
    const int b_col = (lane & 8) ? 8 : 0;

    // ---- load Q tile [128][128] halves ----
    {
        const __half* qbase = qkv + ((size_t)b * SEQ + qblk * BQA) * rstride + h * HDIM;
        #pragma unroll
        for (int t = 0; t < 8; t++) {
            int idx = tid + t * 256;
            int row = idx >> 4, q8 = idx & 15;
            *(float4*)(&Qs[row * QSTR + q8 * 8]) =
                *(const float4*)(qbase + (size_t)row * rstride + q8 * 8);
        }
    }

    float o[16][4];
    #pragma unroll
    for (int nf = 0; nf < 16; nf++)
        #pragma unroll
        for (int r = 0; r < 4; r++) o[nf][r] = 0.f;
    float m0 = -1e30f, m1 = -1e30f, l0 = 0.f, l1 = 0.f;

    const int ntiles = 2 * qblk + 2;
    for (int kt = 0; kt < ntiles; kt++) {
        const __half* kbase = qkv + ((size_t)b * SEQ + kt * BKA) * rstride + h * HDIM + DMODEL;
        const __half* vbase = kbase + DMODEL;
        __syncthreads();
        #pragma unroll
        for (int t = 0; t < 4; t++) {
            int idx = tid + t * 256;
            int row = idx >> 4, q8 = idx & 15;
            cp16(ksAddr + (row * KSTR + q8 * 8) * 2, kbase + (size_t)row * rstride + q8 * 8);
            cp16(vsAddr + (row * VSTR + q8 * 8) * 2, vbase + (size_t)row * rstride + q8 * 8);
        }
        cp_commit();
        cp_wait<0>();
        __syncthreads();

        // ---- S = Q K^T ----
        float s[8][4];
        #pragma unroll
        for (int nf = 0; nf < 8; nf++)
            #pragma unroll
            for (int r = 0; r < 4; r++) s[nf][r] = 0.f;

        #pragma unroll
        for (int kb8 = 0; kb8 < 8; kb8++) {
            const int kb = kb8 * 16;
            uint32_t a[4];
            ldsm_x4(a[0], a[1], a[2], a[3],
                    smem_u32(&Qs[(m0w + a_row) * QSTR + kb + a_col]));
            uint32_t bf[8][2];
            #pragma unroll
            for (int p = 0; p < 4; p++) {
                int n = p * 16 + b_row;
                ldsm_x4(bf[2*p][0], bf[2*p][1], bf[2*p+1][0], bf[2*p+1][1],
                        smem_u32(&Ks[n * KSTR + kb + b_col]));
            }
            #pragma unroll
            for (int nf = 0; nf < 8; nf++)
                mma_f16(s[nf], a, bf[nf]);
        }

        // ---- causal mask (last two tiles only) ----
        if (kt >= 2 * qblk) {
            int qrow0 = qblk * BQA + m0w + g;
            int col0  = kt * BKA;
            #pragma unroll
            for (int nf = 0; nf < 8; nf++) {
                int c0 = col0 + nf * 8 + tig * 2;
                if (c0     > qrow0)     s[nf][0] = -1e30f;
                if (c0 + 1 > qrow0)     s[nf][1] = -1e30f;
                if (c0     > qrow0 + 8) s[nf][2] = -1e30f;
                if (c0 + 1 > qrow0 + 8) s[nf][3] = -1e30f;
            }
        }

        // ---- online softmax ----
        float rm0 = -1e30f, rm1 = -1e30f;
        #pragma unroll
        for (int nf = 0; nf < 8; nf++) {
            rm0 = fmaxf(rm0, fmaxf(s[nf][0], s[nf][1]));
            rm1 = fmaxf(rm1, fmaxf(s[nf][2], s[nf][3]));
        }
        rm0 = fmaxf(rm0, __shfl_xor_sync(0xffffffffu, rm0, 1));
        rm0 = fmaxf(rm0, __shfl_xor_sync(0xffffffffu, rm0, 2));
        rm1 = fmaxf(rm1, __shfl_xor_sync(0xffffffffu, rm1, 1));
        rm1 = fmaxf(rm1, __shfl_xor_sync(0xffffffffu, rm1, 2));
        float mn0 = fmaxf(m0, rm0);
        float mn1 = fmaxf(m1, rm1);

        float rs0 = 0.f, rs1 = 0.f;
        #pragma unroll
        for (int nf = 0; nf < 8; nf++) {
            float p00 = __expf((s[nf][0] - mn0) * scale);
            float p01 = __expf((s[nf][1] - mn0) * scale);
            float p10 = __expf((s[nf][2] - mn1) * scale);
            float p11 = __expf((s[nf][3] - mn1) * scale);
            rs0 += p00 + p01;
            rs1 += p10 + p11;
            *(__half2*)(&Ps[(m0w + g)     * PSTR + nf * 8 + tig * 2]) = __floats2half2_rn(p00, p01);
            *(__half2*)(&Ps[(m0w + 8 + g) * PSTR + nf * 8 + tig * 2]) = __floats2half2_rn(p10, p11);
        }
        rs0 += __shfl_xor_sync(0xffffffffu, rs0, 1);
        rs0 += __shfl_xor_sync(0xffffffffu, rs0, 2);
        rs1 += __shfl_xor_sync(0xffffffffu, rs1, 1);
        rs1 += __shfl_xor_sync(0xffffffffu, rs1, 2);

        float corr0 = __expf((m0 - mn0) * scale);
        float corr1 = __expf((m1 - mn1) * scale);
        l0 = l0 * corr0 + rs0;
        l1 = l1 * corr1 + rs1;
        m0 = mn0; m1 = mn1;
        #pragma unroll
        for (int nf = 0; nf < 16; nf++) {
            o[nf][0] *= corr0; o[nf][1] *= corr0;
            o[nf][2] *= corr1; o[nf][3] *= corr1;
        }
        __syncwarp();

        // ---- O += P V ----
        #pragma unroll
        for (int kc = 0; kc < 4; kc++) {
            const int kb = kc * 16;
            uint32_t a[4];
            ldsm_x4(a[0], a[1], a[2], a[3],
                    smem_u32(&Ps[(m0w + a_row) * PSTR + kb + a_col]));
            #pragma unroll
            for (int np = 0; np < 8; np++) {
                uint32_t b0, b1, b2, b3;
                ldsm_x4_trans(b0, b1, b2, b3,
                              smem_u32(&Vs[(kb + a_row) * VSTR + np * 16 + a_col]));
                uint32_t bb0[2] = { b0, b1 };
                uint32_t bb1[2] = { b2, b3 };
                mma_f16(o[2*np],   a, bb0);
                mma_f16(o[2*np+1], a, bb1);
            }
        }
    }

    // ---- write O (half, divide by l) ----
    float inv0 = 1.f / l0, inv1 = 1.f / l1;
    int row0 = qblk * BQA + m0w + g;
    __half* ob0 = out + ((size_t)b * SEQ + row0)     * DMODEL + h * HDIM;
    __half* ob1 = out + ((size_t)b * SEQ + row0 + 8) * DMODEL + h * HDIM;
    #pragma unroll
    for (int nf = 0; nf < 16; nf++) {
        *(__half2*)(ob0 + nf * 8 + tig * 2) = __floats2half2_rn(o[nf][0] * inv0, o[nf][1] * inv0);
        *(__half2*)(ob1 + nf * 8 + tig * 2) = __floats2half2_rn(o[nf][2] * inv1, o[nf][3] * inv1);
    }
}

// ---------------------------------------------------------------------------
// Launch
// ---------------------------------------------------------------------------
extern "C" void kernel_launch(void* const* d_in, const int* in_sizes, int n_in,
                              void* d_out, int out_size)
{
    const float* x      = (const float*)d_in[0];
    const float* ln1_g  = (const float*)d_in[1];
    const float* ln1_b  = (const float*)d_in[2];
    const float* w_qkv  = (const float*)d_in[3];
    const float* w_proj = (const float*)d_in[4];
    const float* ln2_g  = (const float*)d_in[5];
    const float* ln2_b  = (const float*)d_in[6];
    const float* w_ff1  = (const float*)d_in[7];
    const float* w_ff2  = (const float*)d_in[8];
    float* out = (float*)d_out;

    float *x1;
    __half *qkvh, *ln1h, *attnh, *ln2h, *ff1h, *wqkvT, *wprojT, *wff1T, *wff2T;
    cudaGetSymbolAddress((void**)&x1,    g_x1);
    cudaGetSymbolAddress((void**)&qkvh,  g_qkvh);
    cudaGetSymbolAddress((void**)&ln1h,  g_ln1h);
    cudaGetSymbolAddress((void**)&attnh, g_attnh);
    cudaGetSymbolAddress((void**)&ln2h,  g_ln2h);
    cudaGetSymbolAddress((void**)&ff1h,  g_ff1h);
    cudaGetSymbolAddress((void**)&wqkvT, g_wqkvT);
    cudaGetSymbolAddress((void**)&wprojT, g_wprojT);
    cudaGetSymbolAddress((void**)&wff1T, g_wff1T);
    cudaGetSymbolAddress((void**)&wff2T, g_wff2T);

    cudaFuncSetAttribute(gemm_h<1>, cudaFuncAttributeMaxDynamicSharedMemorySize, GEMMH_SMEM);
    cudaFuncSetAttribute(gemm_h<2>, cudaFuncAttributeMaxDynamicSharedMemorySize, GEMMH_SMEM);
    cudaFuncSetAttribute(gemm_h<3>, cudaFuncAttributeMaxDynamicSharedMemorySize, GEMMH_SMEM);
    cudaFuncSetAttribute(attn_h,    cudaFuncAttributeMaxDynamicSharedMemorySize, ATTN_SMEM);

    dim3 lnBlk(32, 8);
    dim3 tb(32, 8);

    // 0. fused weight transposes+convert [K,N] -> half [N,K]
    transpose_all<<<3072, tb>>>(w_qkv, w_proj, w_ff1, w_ff2, wqkvT, wprojT, wff1T, wff2T);

    // 1. ln1 = LN(x) -> half
    ln_kernel_h<<<MROWS / 8, lnBlk>>>(x, ln1_g, ln1_b, ln1h, MROWS);
    // 2. qkv = ln1 @ w_qkv -> half
    gemm_h<3><<<dim3(1536/128, MROWS/128), 256, GEMMH_SMEM>>>(ln1h, wqkvT, nullptr, qkvh,
                                                              MROWS, 3*DMODEL, DMODEL);
    // 3. attn = causal_flash(qkv) -> half
    attn_h<<<dim3(SEQ/BQA, NHEADS, BATCH), 256, ATTN_SMEM>>>(qkvh, attnh);
    // 4. x1 = x + attn @ w_proj -> fp32
    gemm_h<2><<<dim3(512/128, MROWS/128), 256, GEMMH_SMEM>>>(attnh, wprojT, x, x1,
                                                             MROWS, DMODEL, DMODEL);
    // 5. ln2 = LN(x1) -> half
    ln_kernel_h<<<MROWS / 8, lnBlk>>>(x1, ln2_g, ln2_b, ln2h, MROWS);
    // 6. ff1 = gelu(ln2 @ w_ff1) -> half
    gemm_h<1><<<dim3(DFF/128, MROWS/128), 256, GEMMH_SMEM>>>(ln2h, wff1T, nullptr, ff1h,
                                                             MROWS, DFF, DMODEL);
    // 7. out = x1 + ff1 @ w_ff2 -> fp32
    gemm_h<2><<<dim3(512/128, MROWS/128), 256, GEMMH_SMEM>>>(ff1h, wff2T, x1, out,
                                                             MROWS, DMODEL, DFF);
}

// round 11
// speedup vs baseline: 37.4207x; 1.0372x over previous
#include <cuda_runtime.h>
#include <cuda_fp16.h>
#include <math.h>
#include <stdint.h>

// Problem constants
#define BATCH 4
#define SEQ   2048
#define DMODEL 512
#define NHEADS 4
#define HDIM  128
#define DFF   2048
#define MROWS (BATCH*SEQ)   // 8192

// ---------------------------------------------------------------------------
// Static scratch (no allocation allowed)
// ---------------------------------------------------------------------------
__device__ float  g_x1  [MROWS * DMODEL];       // fp32 residual
__device__ __half g_qkvh [MROWS * 3 * DMODEL];  // half (attention input)
__device__ __half g_ln1h [MROWS * DMODEL];
__device__ __half g_attnh[MROWS * DMODEL];
__device__ __half g_ln2h [MROWS * DMODEL];
__device__ __half g_ff1h [MROWS * DFF];
// transposed half weights [N,K]
__device__ __half g_wqkvT[3 * DMODEL * DMODEL];
__device__ __half g_wprojT[DMODEL * DMODEL];
__device__ __half g_wff1T[DFF * DMODEL];
__device__ __half g_wff2T[DMODEL * DFF];

// ---------------------------------------------------------------------------
// PTX helpers
// ---------------------------------------------------------------------------
__device__ __forceinline__ void mma_f16(float c[4], const uint32_t a[4], const uint32_t b[2]) {
    asm volatile(
        "mma.sync.aligned.m16n8k16.row.col.f32.f16.f16.f32 "
        "{%0,%1,%2,%3}, {%4,%5,%6,%7}, {%8,%9}, {%0,%1,%2,%3};"
        : "+f"(c[0]), "+f"(c[1]), "+f"(c[2]), "+f"(c[3])
        : "r"(a[0]), "r"(a[1]), "r"(a[2]), "r"(a[3]), "r"(b[0]), "r"(b[1]));
}

__device__ __forceinline__ void ldsm_x4(uint32_t& r0, uint32_t& r1, uint32_t& r2, uint32_t& r3,
                                        uint32_t addr) {
    asm volatile("ldmatrix.sync.aligned.m8n8.x4.shared.b16 {%0,%1,%2,%3}, [%4];"
                 : "=r"(r0), "=r"(r1), "=r"(r2), "=r"(r3) : "r"(addr));
}
__device__ __forceinline__ void ldsm_x4_trans(uint32_t& r0, uint32_t& r1, uint32_t& r2, uint32_t& r3,
                                              uint32_t addr) {
    asm volatile("ldmatrix.sync.aligned.m8n8.x4.trans.shared.b16 {%0,%1,%2,%3}, [%4];"
                 : "=r"(r0), "=r"(r1), "=r"(r2), "=r"(r3) : "r"(addr));
}

__device__ __forceinline__ void cp16(uint32_t smem_addr, const void* gmem) {
    asm volatile("cp.async.cg.shared.global [%0], [%1], 16;" :: "r"(smem_addr), "l"(gmem));
}
__device__ __forceinline__ void cp_commit() { asm volatile("cp.async.commit_group;"); }
template <int N>
__device__ __forceinline__ void cp_wait() { asm volatile("cp.async.wait_group %0;" :: "n"(N)); }
__device__ __forceinline__ uint32_t smem_u32(const void* p) {
    return (uint32_t)__cvta_generic_to_shared(p);
}

// ---------------------------------------------------------------------------
// LayerNorm: one warp per row (D=512), 8 warps per block. Output = half.
// ---------------------------------------------------------------------------
__global__ void ln_kernel_h(const float* __restrict__ x,
                            const float* __restrict__ g,
                            const float* __restrict__ b,
                            __half* __restrict__ out, int rows)
{
    int row  = blockIdx.x * 8 + threadIdx.y;
    int lane = threadIdx.x;
    if (row >= rows) return;

    const float4* xr = (const float4*)(x + (size_t)row * DMODEL);
    float4 v[4];
    float s = 0.f, s2 = 0.f;
    #pragma unroll
    for (int i = 0; i < 4; i++) {
        v[i] = xr[lane + i * 32];
        s  += v[i].x + v[i].y + v[i].z + v[i].w;
        s2 += v[i].x*v[i].x + v[i].y*v[i].y + v[i].z*v[i].z + v[i].w*v[i].w;
    }
    #pragma unroll
    for (int o = 16; o > 0; o >>= 1) {
        s  += __shfl_xor_sync(0xffffffffu, s,  o);
        s2 += __shfl_xor_sync(0xffffffffu, s2, o);
    }
    float mu  = s * (1.f / DMODEL);
    float var = s2 * (1.f / DMODEL) - mu * mu;
    float inv = rsqrtf(var + 1e-5f);

    __half2* orow = (__half2*)(out + (size_t)row * DMODEL);
    const float4* g4 = (const float4*)g;
    const float4* b4 = (const float4*)b;
    #pragma unroll
    for (int i = 0; i < 4; i++) {
        float4 gg = g4[lane + i * 32];
        float4 bb = b4[lane + i * 32];
        float r0 = (v[i].x - mu) * inv * gg.x + bb.x;
        float r1 = (v[i].y - mu) * inv * gg.y + bb.y;
        float r2 = (v[i].z - mu) * inv * gg.z + bb.z;
        float r3 = (v[i].w - mu) * inv * gg.w + bb.w;
        orow[(lane + i * 32) * 2 + 0] = __floats2half2_rn(r0, r1);
        orow[(lane + i * 32) * 2 + 1] = __floats2half2_rn(r2, r3);
    }
}

// ---------------------------------------------------------------------------
// Fused weight transposes + fp16 convert: BT[n][k] = (half)B[k][n] for all 4.
// ---------------------------------------------------------------------------
__global__ void transpose_all(const float* __restrict__ w_qkv, const float* __restrict__ w_proj,
                              const float* __restrict__ w_ff1, const float* __restrict__ w_ff2,
                              __half* __restrict__ qkvT, __half* __restrict__ projT,
                              __half* __restrict__ ff1T, __half* __restrict__ ff2T)
{
    __shared__ float t[32][33];
    int bid = blockIdx.x;
    const float* B; __half* BT; int K, N, bx, by;
    if (bid < 768)        { B = w_qkv;  BT = qkvT;  K = DMODEL; N = 3*DMODEL; bid -= 0;    bx = bid % 48; by = bid / 48; }
    else if (bid < 1024)  { B = w_proj; BT = projT; K = DMODEL; N = DMODEL;   bid -= 768;  bx = bid % 16; by = bid / 16; }
    else if (bid < 2048)  { B = w_ff1;  BT = ff1T;  K = DMODEL; N = DFF;      bid -= 1024; bx = bid % 64; by = bid / 64; }
    else                  { B = w_ff2;  BT = ff2T;  K = DFF;    N = DMODEL;   bid -= 2048; bx = bid % 16; by = bid / 16; }

    int x  = bx * 32 + threadIdx.x;   // n
    int y0 = by * 32;                 // k
    #pragma unroll
    for (int i = 0; i < 4; i++) {
        int y = y0 + threadIdx.y + i * 8;
        t[threadIdx.y + i * 8][threadIdx.x] = B[(size_t)y * N + x];
    }
    __syncthreads();
    int xo  = by * 32 + threadIdx.x;  // k
    int yo0 = bx * 32;                // n
    #pragma unroll
    for (int i = 0; i < 4; i++) {
        int yo = yo0 + threadIdx.y + i * 8;
        BT[(size_t)yo * K + xo] = __float2half_rn(t[threadIdx.x][threadIdx.y + i * 8]);
    }
}

// ---------------------------------------------------------------------------
// fp16 tensor-core GEMM (m16n8k16), 3-stage cp.async pipeline, ldmatrix frags.
// Block 128x128x32, 256 threads = 8 warps (4m x 2n), warp tile 32x64.
// EPI: 0 = float out, 1 = GELU half out, 2 = +residual float out, 3 = half out
// ---------------------------------------------------------------------------
#define HS_STR 40
#define HT_ELEMS (128 * HS_STR)
#define HSTAGE_ELEMS (2 * HT_ELEMS)
#define GEMMH_SMEM (3 * HSTAGE_ELEMS * 2)   // 61440 B

__device__ __forceinline__ void load_stage_h(
    uint32_t dstA, uint32_t dstB,
    const __half* Ab, const __half* BTb, int k0, int K, int tid)
{
    #pragma unroll
    for (int t = 0; t < 2; t++) {
        int idx = tid + t * 256;
        int r = idx >> 2, q = idx & 3;
        cp16(dstA + r * (HS_STR*2) + q * 16, Ab  + (size_t)r * K + k0 + q * 8);
        cp16(dstB + r * (HS_STR*2) + q * 16, BTb + (size_t)r * K + k0 + q * 8);
    }
}

template <int EPI>
__global__ void __launch_bounds__(256, 2)
gemm_h(const __half* __restrict__ A, const __half* __restrict__ BT,
       const float* __restrict__ res, void* __restrict__ Cv,
       int M, int N, int K)
{
    extern __shared__ __half smh[];
    const uint32_t smb = smem_u32(smh);
    uint32_t aAddr[3], bAddr[3];
    #pragma unroll
    for (int s = 0; s < 3; s++) {
        aAddr[s] = smb + s * HSTAGE_ELEMS * 2;
        bAddr[s] = aAddr[s] + HT_ELEMS * 2;
    }

    const int tid  = threadIdx.x;
    const int lane = tid & 31;
    const int wid  = tid >> 5;
    const int wm   = wid >> 1;
    const int wn   = wid & 1;

    const int bx = blockIdx.x;
    const int by = blockIdx.y;

    const __half* Ab  = A  + (size_t)(by * 128) * K;
    const __half* BTb = BT + (size_t)(bx * 128) * K;

    float acc[2][8][4];
    #pragma unroll
    for (int mf = 0; mf < 2; mf++)
        #pragma unroll
        for (int nf = 0; nf < 8; nf++)
            #pragma unroll
            for (int r = 0; r < 4; r++) acc[mf][nf][r] = 0.f;

    const int a_row = (lane & 15);
    const int a_col = (lane >> 4) << 3;
    const int b_row = (lane & 7) + ((lane >> 4) << 3);
    const int b_col = (lane & 8) ? 8 : 0;

    const int nt = K >> 5;
    load_stage_h(aAddr[0], bAddr[0], Ab, BTb, 0, K, tid);
    cp_commit();
    if (nt > 1) {
        load_stage_h(aAddr[1], bAddr[1], Ab, BTb, 32, K, tid);
        cp_commit();
    }

    for (int kt = 0; kt < nt; kt++) {
        const int cur = kt % 3;
        if (kt + 1 < nt) cp_wait<1>(); else cp_wait<0>();
        __syncthreads();

        if (kt + 2 < nt) {
            const int nxt = (kt + 2) % 3;
            load_stage_h(aAddr[nxt], bAddr[nxt], Ab, BTb, (kt + 2) * 32, K, tid);
            cp_commit();
        }

        const uint32_t Asc = aAddr[cur];
        const uint32_t Bsc = bAddr[cur];

        #pragma unroll
        for (int ks = 0; ks < 2; ks++) {
            const int kb = ks * 16;
            uint32_t af[2][4], bf[8][2];
            #pragma unroll
            for (int mf = 0; mf < 2; mf++) {
                int r = wm * 32 + mf * 16 + a_row;
                ldsm_x4(af[mf][0], af[mf][1], af[mf][2], af[mf][3],
                        Asc + (r * HS_STR + kb + a_col) * 2);
            }
            #pragma unroll
            for (int p = 0; p < 4; p++) {
                int n = wn * 64 + p * 16 + b_row;
                ldsm_x4(bf[2*p][0], bf[2*p][1], bf[2*p+1][0], bf[2*p+1][1],
                        Bsc + (n * HS_STR + kb + b_col) * 2);
            }
            #pragma unroll
            for (int mf = 0; mf < 2; mf++)
                #pragma unroll
                for (int nf = 0; nf < 8; nf++)
                    mma_f16(acc[mf][nf], af[mf], bf[nf]);
        }
    }

    // epilogue
    const int g   = lane >> 2;
    const int tig = lane & 3;
    #pragma unroll
    for (int mf = 0; mf < 2; mf++) {
        #pragma unroll
        for (int i2 = 0; i2 < 2; i2++) {
            int row = by * 128 + wm * 32 + mf * 16 + g + i2 * 8;
            #pragma unroll
            for (int nf = 0; nf < 8; nf++) {
                int col = bx * 128 + wn * 64 + nf * 8 + tig * 2;
                float v0 = acc[mf][nf][i2 * 2 + 0];
                float v1 = acc[mf][nf][i2 * 2 + 1];
                size_t off = (size_t)row * N + col;
                if (EPI == 1) {
                    v0 = 0.5f * v0 * (1.f + erff(v0 * 0.70710678118654752f));
                    v1 = 0.5f * v1 * (1.f + erff(v1 * 0.70710678118654752f));
                    *(__half2*)((__half*)Cv + off) = __floats2half2_rn(v0, v1);
                } else if (EPI == 2) {
                    float2 r = *(const float2*)(res + off);
                    *(float2*)((float*)Cv + off) = make_float2(v0 + r.x, v1 + r.y);
                } else if (EPI == 3) {
                    *(__half2*)((__half*)Cv + off) = __floats2half2_rn(v0, v1);
                } else {
                    *(float2*)((float*)Cv + off) = make_float2(v0, v1);
                }
            }
        }
    }
}

// ---------------------------------------------------------------------------
// fp16 flash attention v3: register-resident P (no smem roundtrip),
// 2-stage cp.async K/V pipeline. 256 threads = 8 warps x 16 q-rows.
// BQ=128, BK=64. Smem: Q[128][136] + 2 x (K+V)[64][136]  = 104448 B.
// ---------------------------------------------------------------------------
#define BQA 128
#define BKA 64
#define QSTR 136   // halves
#define KSTR 136
#define VSTR 136
#define KV_STAGE_ELEMS (BKA * KSTR + BKA * VSTR)     // 17408 halves
#define ATTN_SMEM ((BQA*QSTR + 2*KV_STAGE_ELEMS) * 2)  // 104448 B

__global__ void __launch_bounds__(256, 2)
attn_h(const __half* __restrict__ qkv, __half* __restrict__ out)
{
    extern __shared__ __align__(16) __half smah[];
    __half* Qs = smah;                               // [128][136]
    // stage s: K at base, V at base + BKA*KSTR
    uint32_t kAddr[2], vAddr[2];
    {
        uint32_t kv0 = smem_u32(Qs + BQA * QSTR);
        kAddr[0] = kv0;
        vAddr[0] = kv0 + BKA * KSTR * 2;
        kAddr[1] = kv0 + KV_STAGE_ELEMS * 2;
        vAddr[1] = kAddr[1] + BKA * KSTR * 2;
    }
    __half* KsBase = Qs + BQA * QSTR;

    const int qblk = (SEQ / BQA - 1) - blockIdx.x;
    const int h  = blockIdx.y;
    const int b  = blockIdx.z;
    const int tid  = threadIdx.x;
    const int lane = tid & 31;
    const int wid  = tid >> 5;
    const int g    = lane >> 2;
    const int tig  = lane & 3;
    const int m0w  = wid * 16;

    const size_t rstride = 3 * DMODEL;   // halves
    const float scale = 0.08838834764831845f;

    const int a_row = (lane & 15);
    const int a_col = (lane >> 4) << 3;
    const int b_row = (lane & 7) + ((lane >> 4) << 3);
    const int b_col = (lane & 8) ? 8 : 0;

    const __half* kvbase = qkv + (size_t)b * SEQ * rstride + h * HDIM + DMODEL;

    // ---- load Q tile [128][128] halves ----
    {
        const __half* qbase = qkv + ((size_t)b * SEQ + qblk * BQA) * rstride + h * HDIM;
        #pragma unroll
        for (int t = 0; t < 8; t++) {
            int idx = tid + t * 256;
            int row = idx >> 4, q8 = idx & 15;
            *(float4*)(&Qs[row * QSTR + q8 * 8]) =
                *(const float4*)(qbase + (size_t)row * rstride + q8 * 8);
        }
    }

    float o[16][4];
    #pragma unroll
    for (int nf = 0; nf < 16; nf++)
        #pragma unroll
        for (int r = 0; r < 4; r++) o[nf][r] = 0.f;
    float m0 = -1e30f, m1 = -1e30f, l0 = 0.f, l1 = 0.f;

    const int ntiles = 2 * qblk + 2;

    // prologue: issue K/V loads for tile 0
    {
        const __half* kb0 = kvbase;
        #pragma unroll
        for (int t = 0; t < 4; t++) {
            int idx = tid + t * 256;
            int row = idx >> 4, q8 = idx & 15;
            cp16(kAddr[0] + (row * KSTR + q8 * 8) * 2, kb0 + (size_t)row * rstride + q8 * 8);
            cp16(vAddr[0] + (row * VSTR + q8 * 8) * 2, kb0 + DMODEL + (size_t)row * rstride + q8 * 8);
        }
        cp_commit();
    }

    for (int kt = 0; kt < ntiles; kt++) {
        const int cur = kt & 1;
        __syncthreads();   // compute kt-1 done in all warps (buffer nxt reusable)

        if (kt + 1 < ntiles) {
            const int nxt = 1 - cur;
            const __half* kbn = kvbase + (size_t)(kt + 1) * BKA * rstride;
            #pragma unroll
            for (int t = 0; t < 4; t++) {
                int idx = tid + t * 256;
                int row = idx >> 4, q8 = idx & 15;
                cp16(kAddr[nxt] + (row * KSTR + q8 * 8) * 2, kbn + (size_t)row * rstride + q8 * 8);
                cp16(vAddr[nxt] + (row * VSTR + q8 * 8) * 2, kbn + DMODEL + (size_t)row * rstride + q8 * 8);
            }
            cp_commit();
            cp_wait<1>();
        } else {
            cp_wait<0>();
        }
        __syncthreads();   // stage kt visible

        const __half* Ks = KsBase + cur * KV_STAGE_ELEMS;
        const __half* Vs = Ks + BKA * KSTR;

        // ---- S = Q K^T ----
        float s[8][4];
        #pragma unroll
        for (int nf = 0; nf < 8; nf++)
            #pragma unroll
            for (int r = 0; r < 4; r++) s[nf][r] = 0.f;

        #pragma unroll
        for (int kb8 = 0; kb8 < 8; kb8++) {
            const int kb = kb8 * 16;
            uint32_t a[4];
            ldsm_x4(a[0], a[1], a[2], a[3],
                    smem_u32(&Qs[(m0w + a_row) * QSTR + kb + a_col]));
            uint32_t bf[8][2];
            #pragma unroll
            for (int p = 0; p < 4; p++) {
                int n = p * 16 + b_row;
                ldsm_x4(bf[2*p][0], bf[2*p][1], bf[2*p+1][0], bf[2*p+1][1],
                        smem_u32(&Ks[n * KSTR + kb + b_col]));
            }
            #pragma unroll
            for (int nf = 0; nf < 8; nf++)
                mma_f16(s[nf], a, bf[nf]);
        }

        // ---- causal mask (last two tiles only) ----
        if (kt >= 2 * qblk) {
            int qrow0 = qblk * BQA + m0w + g;
            int col0  = kt * BKA;
            #pragma unroll
            for (int nf = 0; nf < 8; nf++) {
                int c0 = col0 + nf * 8 + tig * 2;
                if (c0     > qrow0)     s[nf][0] = -1e30f;
                if (c0 + 1 > qrow0)     s[nf][1] = -1e30f;
                if (c0     > qrow0 + 8) s[nf][2] = -1e30f;
                if (c0 + 1 > qrow0 + 8) s[nf][3] = -1e30f;
            }
        }

        // ---- online softmax; P packed to half2 in registers ----
        float rm0 = -1e30f, rm1 = -1e30f;
        #pragma unroll
        for (int nf = 0; nf < 8; nf++) {
            rm0 = fmaxf(rm0, fmaxf(s[nf][0], s[nf][1]));
            rm1 = fmaxf(rm1, fmaxf(s[nf][2], s[nf][3]));
        }
        rm0 = fmaxf(rm0, __shfl_xor_sync(0xffffffffu, rm0, 1));
        rm0 = fmaxf(rm0, __shfl_xor_sync(0xffffffffu, rm0, 2));
        rm1 = fmaxf(rm1, __shfl_xor_sync(0xffffffffu, rm1, 1));
        rm1 = fmaxf(rm1, __shfl_xor_sync(0xffffffffu, rm1, 2));
        float mn0 = fmaxf(m0, rm0);
        float mn1 = fmaxf(m1, rm1);

        uint32_t ph[8][2];
        float rs0 = 0.f, rs1 = 0.f;
        #pragma unroll
        for (int nf = 0; nf < 8; nf++) {
            float p00 = __expf((s[nf][0] - mn0) * scale);
            float p01 = __expf((s[nf][1] - mn0) * scale);
            float p10 = __expf((s[nf][2] - mn1) * scale);
            float p11 = __expf((s[nf][3] - mn1) * scale);
            rs0 += p00 + p01;
            rs1 += p10 + p11;
            __half2 h0 = __floats2half2_rn(p00, p01);
            __half2 h1 = __floats2half2_rn(p10, p11);
            ph[nf][0] = *(uint32_t*)&h0;
            ph[nf][1] = *(uint32_t*)&h1;
        }
        rs0 += __shfl_xor_sync(0xffffffffu, rs0, 1);
        rs0 += __shfl_xor_sync(0xffffffffu, rs0, 2);
        rs1 += __shfl_xor_sync(0xffffffffu, rs1, 1);
        rs1 += __shfl_xor_sync(0xffffffffu, rs1, 2);

        float corr0 = __expf((m0 - mn0) * scale);
        float corr1 = __expf((m1 - mn1) * scale);
        l0 = l0 * corr0 + rs0;
        l1 = l1 * corr1 + rs1;
        m0 = mn0; m1 = mn1;
        #pragma unroll
        for (int nf = 0; nf < 16; nf++) {
            o[nf][0] *= corr0; o[nf][1] *= corr0;
            o[nf][2] *= corr1; o[nf][3] *= corr1;
        }

        // ---- O += P V : A directly from registers, B via ldmatrix.x4.trans ----
        #pragma unroll
        for (int kc = 0; kc < 4; kc++) {
            const int kb = kc * 16;
            uint32_t a[4] = { ph[2*kc][0], ph[2*kc][1], ph[2*kc+1][0], ph[2*kc+1][1] };
            #pragma unroll
            for (int np = 0; np < 8; np++) {
                uint32_t b0, b1, b2, b3;
                ldsm_x4_trans(b0, b1, b2, b3,
                              smem_u32(&Vs[(kb + a_row) * VSTR + np * 16 + a_col]));
                uint32_t bb0[2] = { b0, b1 };
                uint32_t bb1[2] = { b2, b3 };
                mma_f16(o[2*np],   a, bb0);
                mma_f16(o[2*np+1], a, bb1);
            }
        }
    }

    // ---- write O (half, divide by l) ----
    float inv0 = 1.f / l0, inv1 = 1.f / l1;
    int row0 = qblk * BQA + m0w + g;
    __half* ob0 = out + ((size_t)b * SEQ + row0)     * DMODEL + h * HDIM;
    __half* ob1 = out + ((size_t)b * SEQ + row0 + 8) * DMODEL + h * HDIM;
    #pragma unroll
    for (int nf = 0; nf < 16; nf++) {
        *(__half2*)(ob0 + nf * 8 + tig * 2) = __floats2half2_rn(o[nf][0] * inv0, o[nf][1] * inv0);
        *(__half2*)(ob1 + nf * 8 + tig * 2) = __floats2half2_rn(o[nf][2] * inv1, o[nf][3] * inv1);
    }
}

// ---------------------------------------------------------------------------
// Launch
// ---------------------------------------------------------------------------
extern "C" void kernel_launch(void* const* d_in, const int* in_sizes, int n_in,
                              void* d_out, int out_size)
{
    const float* x      = (const float*)d_in[0];
    const float* ln1_g  = (const float*)d_in[1];
    const float* ln1_b  = (const float*)d_in[2];
    const float* w_qkv  = (const float*)d_in[3];
    const float* w_proj = (const float*)d_in[4];
    const float* ln2_g  = (const float*)d_in[5];
    const float* ln2_b  = (const float*)d_in[6];
    const float* w_ff1  = (const float*)d_in[7];
    const float* w_ff2  = (const float*)d_in[8];
    float* out = (float*)d_out;

    float *x1;
    __half *qkvh, *ln1h, *attnh, *ln2h, *ff1h, *wqkvT, *wprojT, *wff1T, *wff2T;
    cudaGetSymbolAddress((void**)&x1,    g_x1);
    cudaGetSymbolAddress((void**)&qkvh,  g_qkvh);
    cudaGetSymbolAddress((void**)&ln1h,  g_ln1h);
    cudaGetSymbolAddress((void**)&attnh, g_attnh);
    cudaGetSymbolAddress((void**)&ln2h,  g_ln2h);
    cudaGetSymbolAddress((void**)&ff1h,  g_ff1h);
    cudaGetSymbolAddress((void**)&wqkvT, g_wqkvT);
    cudaGetSymbolAddress((void**)&wprojT, g_wprojT);
    cudaGetSymbolAddress((void**)&wff1T, g_wff1T);
    cudaGetSymbolAddress((void**)&wff2T, g_wff2T);

    cudaFuncSetAttribute(gemm_h<1>, cudaFuncAttributeMaxDynamicSharedMemorySize, GEMMH_SMEM);
    cudaFuncSetAttribute(gemm_h<2>, cudaFuncAttributeMaxDynamicSharedMemorySize, GEMMH_SMEM);
    cudaFuncSetAttribute(gemm_h<3>, cudaFuncAttributeMaxDynamicSharedMemorySize, GEMMH_SMEM);
    cudaFuncSetAttribute(attn_h,    cudaFuncAttributeMaxDynamicSharedMemorySize, ATTN_SMEM);

    dim3 lnBlk(32, 8);
    dim3 tb(32, 8);

    // 0. fused weight transposes+convert [K,N] -> half [N,K]
    transpose_all<<<3072, tb>>>(w_qkv, w_proj, w_ff1, w_ff2, wqkvT, wprojT, wff1T, wff2T);

    // 1. ln1 = LN(x) -> half
    ln_kernel_h<<<MROWS / 8, lnBlk>>>(x, ln1_g, ln1_b, ln1h, MROWS);
    // 2. qkv = ln1 @ w_qkv -> half
    gemm_h<3><<<dim3(1536/128, MROWS/128), 256, GEMMH_SMEM>>>(ln1h, wqkvT, nullptr, qkvh,
                                                              MROWS, 3*DMODEL, DMODEL);
    // 3. attn = causal_flash(qkv) -> half
    attn_h<<<dim3(SEQ/BQA, NHEADS, BATCH), 256, ATTN_SMEM>>>(qkvh, attnh);
    // 4. x1 = x + attn @ w_proj -> fp32
    gemm_h<2><<<dim3(512/128, MROWS/128), 256, GEMMH_SMEM>>>(attnh, wprojT, x, x1,
                                                             MROWS, DMODEL, DMODEL);
    // 5. ln2 = LN(x1) -> half
    ln_kernel_h<<<MROWS / 8, lnBlk>>>(x1, ln2_g, ln2_b, ln2h, MROWS);
    // 6. ff1 = gelu(ln2 @ w_ff1) -> half
    gemm_h<1><<<dim3(DFF/128, MROWS/128), 256, GEMMH_SMEM>>>(ln2h, wff1T, nullptr, ff1h,
                                                             MROWS, DFF, DMODEL);
    // 7. out = x1 + ff1 @ w_ff2 -> fp32
    gemm_h<2><<<dim3(512/128, MROWS/128), 256, GEMMH_SMEM>>>(ff1h, wff2T, x1, out,
                                                             MROWS, DMODEL, DFF);
}